// round 1
// baseline (speedup 1.0000x reference)
#include <cuda_runtime.h>
#include <math.h>

// Problem constants
#define B_  16
#define S_  1024
#define D_  64
#define H_  4
#define DEP 16
#define DFF 256
#define L_  2
#define BS  (B_ * S_)
#define KT  128   // keys per attention smem tile

// ------------------------- device scratch (no allocs allowed) ----------------
__device__ float g_x   [BS * D_];
__device__ float g_q   [BS * D_];
__device__ float g_k   [BS * D_];
__device__ float g_v   [BS * D_];
__device__ float g_ctx [BS * D_];
__device__ float g_tmp [BS * D_];
__device__ float g_out1[BS * D_];
__device__ float g_h   [BS * DFF];
__device__ float g_keep[BS];
__device__ float g_nanf[BS];

// ------------------------- helpers ------------------------------------------
__device__ __forceinline__ float wred_sum(float x) {
    #pragma unroll
    for (int o = 16; o > 0; o >>= 1) x += __shfl_xor_sync(0xffffffffu, x, o);
    return x;
}

// ------------------------- prep: nan flags + keep ----------------------------
__global__ void prep_kernel(const float* __restrict__ in,
                            float* __restrict__ keepv, float* __restrict__ nanf) {
    int b = blockIdx.x;
    int s = threadIdx.x;            // 1024 threads
    float v = in[b * S_ + s];
    bool nan = (v != v);
    unsigned bal = __ballot_sync(0xffffffffu, nan);
    __shared__ int warp_all[32];
    __shared__ int allnan_s;
    if ((s & 31) == 0) warp_all[s >> 5] = (bal == 0xffffffffu);
    __syncthreads();
    if (s == 0) {
        int a = 1;
        #pragma unroll
        for (int i = 0; i < 32; ++i) a &= warp_all[i];
        allnan_s = a;
    }
    __syncthreads();
    float kp = (nan || allnan_s) ? 0.f : 1.f;
    keepv[b * S_ + s] = kp;
    nanf [b * S_ + s] = nan ? 1.f : 0.f;
}

// ------------------------- build x -------------------------------------------
__global__ void build_x_kernel(const float* __restrict__ in,
                               const float* __restrict__ emb,
                               const float* __restrict__ keepv,
                               float* __restrict__ x) {
    int idx = blockIdx.x * 256 + threadIdx.x;   // < BS*64
    int d   = idx & 63;
    int row = idx >> 6;
    int s   = row & (S_ - 1);
    float kp = keepv[row];
    float val;
    const float SQF = 7.93725393319377f * 8.0f;  // sqrt(63)*sqrt(64)
    if (d < 63) {
        val = emb[s * 63 + d] * SQF;
    } else {
        float v = in[row];
        val = (v != v) ? 0.f : v;
    }
    x[idx] = val * kp;
}

// ------------------------- generic tiled GEMM: C = A@W (+bias)(relu) ---------
// A: (M,K) row-major, W: (K,N) row-major, C: (M,N). M%64==0, N%64==0, K%64==0.
__global__ void gemm_kernel(const float* __restrict__ A, const float* __restrict__ W,
                            const float* __restrict__ bias, float* __restrict__ C,
                            int M, int N, int K, int relu) {
    __shared__ float As[64][65];
    __shared__ float Ws[64][64];
    int tid = threadIdx.x;
    int tx = tid & 15, ty = tid >> 4;
    int m0 = blockIdx.x * 64;
    int n0 = blockIdx.y * 64;

    float acc[4][4];
    #pragma unroll
    for (int i = 0; i < 4; ++i)
        #pragma unroll
        for (int j = 0; j < 4; ++j) acc[i][j] = 0.f;

    for (int k0 = 0; k0 < K; k0 += 64) {
        for (int i = tid; i < 64 * 64; i += 256) {
            int r = i >> 6, c = i & 63;
            As[r][c] = A[(size_t)(m0 + r) * K + (k0 + c)];
            Ws[r][c] = W[(size_t)(k0 + r) * N + (n0 + c)];
        }
        __syncthreads();
        #pragma unroll 16
        for (int k = 0; k < 64; ++k) {
            float4 w = *(const float4*)&Ws[k][tx * 4];
            float a0 = As[ty * 4 + 0][k];
            float a1 = As[ty * 4 + 1][k];
            float a2 = As[ty * 4 + 2][k];
            float a3 = As[ty * 4 + 3][k];
            acc[0][0] += a0 * w.x; acc[0][1] += a0 * w.y; acc[0][2] += a0 * w.z; acc[0][3] += a0 * w.w;
            acc[1][0] += a1 * w.x; acc[1][1] += a1 * w.y; acc[1][2] += a1 * w.z; acc[1][3] += a1 * w.w;
            acc[2][0] += a2 * w.x; acc[2][1] += a2 * w.y; acc[2][2] += a2 * w.z; acc[2][3] += a2 * w.w;
            acc[3][0] += a3 * w.x; acc[3][1] += a3 * w.y; acc[3][2] += a3 * w.z; acc[3][3] += a3 * w.w;
        }
        __syncthreads();
    }

    float4 bv = make_float4(0.f, 0.f, 0.f, 0.f);
    if (bias) bv = *(const float4*)&bias[n0 + tx * 4];
    #pragma unroll
    for (int i = 0; i < 4; ++i) {
        int r = m0 + ty * 4 + i;
        float4 o;
        o.x = acc[i][0] + bv.x;
        o.y = acc[i][1] + bv.y;
        o.z = acc[i][2] + bv.z;
        o.w = acc[i][3] + bv.w;
        if (relu) {
            o.x = fmaxf(o.x, 0.f); o.y = fmaxf(o.y, 0.f);
            o.z = fmaxf(o.z, 0.f); o.w = fmaxf(o.w, 0.f);
        }
        *(float4*)&C[(size_t)r * N + n0 + tx * 4] = o;
    }
}

// ------------------------- fused masked flash attention ----------------------
// q,k,v,ctx laid out (B,S,D) with head h occupying columns [h*16, h*16+16).
__global__ void attn_kernel(const float* __restrict__ q, const float* __restrict__ k,
                            const float* __restrict__ v, const float* __restrict__ nanf,
                            float* __restrict__ ctx) {
    __shared__ float Kt[KT][16];
    __shared__ float Vt[KT][16];
    __shared__ float nj[KT];

    int tid = threadIdx.x;
    int bh = blockIdx.y;
    int b = bh >> 2, h = bh & 3;
    int qi = blockIdx.x * 256 + tid;
    size_t rowq = (size_t)(b * S_ + qi);

    const float SC = 0.25f * 1.4426950408889634f; // 1/sqrt(16) * log2(e)
    const float* qp = q + rowq * D_ + h * DEP;
    float4 q0 = *((const float4*)qp + 0);
    float4 q1 = *((const float4*)qp + 1);
    float4 q2 = *((const float4*)qp + 2);
    float4 q3 = *((const float4*)qp + 3);
    q0.x *= SC; q0.y *= SC; q0.z *= SC; q0.w *= SC;
    q1.x *= SC; q1.y *= SC; q1.z *= SC; q1.w *= SC;
    q2.x *= SC; q2.y *= SC; q2.z *= SC; q2.w *= SC;
    q3.x *= SC; q3.y *= SC; q3.z *= SC; q3.w *= SC;

    float nan_i = nanf[rowq];
    float m = -1e30f, Z = 0.f;
    float4 a0 = make_float4(0.f,0.f,0.f,0.f);
    float4 a1 = a0, a2 = a0, a3 = a0;

    for (int t = 0; t < S_ / KT; ++t) {
        const float* kb = k + ((size_t)(b * S_ + t * KT)) * D_ + h * DEP;
        const float* vb = v + ((size_t)(b * S_ + t * KT)) * D_ + h * DEP;
        __syncthreads();
        for (int i = tid; i < KT * 4; i += 256) {
            int j = i >> 2, d4 = i & 3;
            ((float4*)Kt[j])[d4] = ((const float4*)(kb + (size_t)j * D_))[d4];
            ((float4*)Vt[j])[d4] = ((const float4*)(vb + (size_t)j * D_))[d4];
        }
        if (tid < KT) nj[tid] = nanf[(size_t)(b * S_) + t * KT + tid];
        __syncthreads();

        for (int j = 0; j < KT; ++j) {
            float4 k0 = ((float4*)Kt[j])[0];
            float4 k1 = ((float4*)Kt[j])[1];
            float4 k2 = ((float4*)Kt[j])[2];
            float4 k3 = ((float4*)Kt[j])[3];
            float l = q0.x*k0.x + q0.y*k0.y + q0.z*k0.z + q0.w*k0.w
                    + q1.x*k1.x + q1.y*k1.y + q1.z*k1.z + q1.w*k1.w
                    + q2.x*k2.x + q2.y*k2.y + q2.z*k2.z + q2.w*k2.w
                    + q3.x*k3.x + q3.y*k3.y + q3.z*k3.z + q3.w*k3.w;
            bool msk = (nan_i != 0.f) || (nj[j] != 0.f);
            if (!msk) {
                float4 v0 = ((float4*)Vt[j])[0];
                float4 v1 = ((float4*)Vt[j])[1];
                float4 v2 = ((float4*)Vt[j])[2];
                float4 v3 = ((float4*)Vt[j])[3];
                if (l > m) {
                    float corr = exp2f(m - l);
                    m = l;
                    Z = Z * corr + 1.f;
                    a0.x = a0.x*corr + v0.x; a0.y = a0.y*corr + v0.y; a0.z = a0.z*corr + v0.z; a0.w = a0.w*corr + v0.w;
                    a1.x = a1.x*corr + v1.x; a1.y = a1.y*corr + v1.y; a1.z = a1.z*corr + v1.z; a1.w = a1.w*corr + v1.w;
                    a2.x = a2.x*corr + v2.x; a2.y = a2.y*corr + v2.y; a2.z = a2.z*corr + v2.z; a2.w = a2.w*corr + v2.w;
                    a3.x = a3.x*corr + v3.x; a3.y = a3.y*corr + v3.y; a3.z = a3.z*corr + v3.z; a3.w = a3.w*corr + v3.w;
                } else {
                    float p = exp2f(l - m);
                    Z += p;
                    a0.x += p*v0.x; a0.y += p*v0.y; a0.z += p*v0.z; a0.w += p*v0.w;
                    a1.x += p*v1.x; a1.y += p*v1.y; a1.z += p*v1.z; a1.w += p*v1.w;
                    a2.x += p*v2.x; a2.y += p*v2.y; a2.z += p*v2.z; a2.w += p*v2.w;
                    a3.x += p*v3.x; a3.y += p*v3.y; a3.z += p*v3.z; a3.w += p*v3.w;
                }
            }
        }
    }

    float rz = (Z > 0.f) ? (1.f / Z) : 0.f;
    float* op = ctx + rowq * D_ + h * DEP;
    float4 o;
    o.x=a0.x*rz; o.y=a0.y*rz; o.z=a0.z*rz; o.w=a0.w*rz; ((float4*)op)[0]=o;
    o.x=a1.x*rz; o.y=a1.y*rz; o.z=a1.z*rz; o.w=a1.w*rz; ((float4*)op)[1]=o;
    o.x=a2.x*rz; o.y=a2.y*rz; o.z=a2.z*rz; o.w=a2.w*rz; ((float4*)op)[2]=o;
    o.x=a3.x*rz; o.y=a3.y*rz; o.z=a3.z*rz; o.w=a3.w*rz; ((float4*)op)[3]=o;
}

// ------------------------- add + layernorm + keep -----------------------------
__global__ void add_ln_kernel(const float* __restrict__ a, const float* __restrict__ t,
                              const float* __restrict__ g, const float* __restrict__ be,
                              const float* __restrict__ keep, float* __restrict__ out) {
    int warp = threadIdx.x >> 5;
    int lane = threadIdx.x & 31;
    int row = blockIdx.x * 8 + warp;
    size_t base = (size_t)row * 64;
    float s0 = a[base + lane]      + t[base + lane];
    float s1 = a[base + lane + 32] + t[base + lane + 32];
    float mean = wred_sum(s0 + s1) * (1.f / 64.f);
    float d0 = s0 - mean, d1 = s1 - mean;
    float var = wred_sum(d0 * d0 + d1 * d1) * (1.f / 64.f);
    float inv = rsqrtf(var + 1e-6f);
    float kp = keep[row];
    out[base + lane]      = (d0 * inv * g[lane]      + be[lane])      * kp;
    out[base + lane + 32] = (d1 * inv * g[lane + 32] + be[lane + 32]) * kp;
}

// ------------------------- final: phi = h2@w3 + b3, per-batch sum + out_bias --
__global__ void final_kernel(const float* __restrict__ h2, const float* __restrict__ w3,
                             const float* __restrict__ b3, const float* __restrict__ ob,
                             float* __restrict__ y) {
    int b = blockIdx.x;
    int tid = threadIdx.x;  // 256
    __shared__ float w3s[64];
    __shared__ float red[256];
    if (tid < 64) w3s[tid] = w3[tid];
    __syncthreads();
    float local = 0.f;
    for (int s = tid; s < S_; s += 256) {
        const float* r = h2 + ((size_t)(b * S_ + s)) * 64;
        float acc = 0.f;
        #pragma unroll
        for (int d4 = 0; d4 < 16; ++d4) {
            float4 rv = ((const float4*)r)[d4];
            acc += rv.x * w3s[d4*4+0] + rv.y * w3s[d4*4+1]
                 + rv.z * w3s[d4*4+2] + rv.w * w3s[d4*4+3];
        }
        local += acc + b3[0];
    }
    red[tid] = local;
    __syncthreads();
    for (int st = 128; st > 0; st >>= 1) {
        if (tid < st) red[tid] += red[tid + st];
        __syncthreads();
    }
    if (tid == 0) y[b] = red[0] + ob[0];
}

// ------------------------- launcher ------------------------------------------
extern "C" void kernel_launch(void* const* d_in, const int* in_sizes, int n_in,
                              void* d_out, int out_size) {
    const float* input  = (const float*)d_in[0];
    const float* emb    = (const float*)d_in[1];
    const float* wq     = (const float*)d_in[2];
    const float* wq_b   = (const float*)d_in[3];
    const float* wk     = (const float*)d_in[4];
    const float* wk_b   = (const float*)d_in[5];
    const float* wv     = (const float*)d_in[6];
    const float* wv_b   = (const float*)d_in[7];
    const float* wo     = (const float*)d_in[8];
    const float* ffn_w1 = (const float*)d_in[9];
    const float* ffn_w2 = (const float*)d_in[10];
    const float* ln1_g  = (const float*)d_in[11];
    const float* ln1_b  = (const float*)d_in[12];
    const float* ln2_g  = (const float*)d_in[13];
    const float* ln2_b  = (const float*)d_in[14];
    const float* c_w1   = (const float*)d_in[15];
    const float* c_b1   = (const float*)d_in[16];
    const float* c_w2   = (const float*)d_in[17];
    const float* c_b2   = (const float*)d_in[18];
    const float* c_w3   = (const float*)d_in[19];
    const float* c_b3   = (const float*)d_in[20];
    const float* ob     = (const float*)d_in[21];
    float* y = (float*)d_out;

    float *x, *q, *k, *v, *ctx, *tmp, *out1, *h, *keep, *nanf;
    cudaGetSymbolAddress((void**)&x,    g_x);
    cudaGetSymbolAddress((void**)&q,    g_q);
    cudaGetSymbolAddress((void**)&k,    g_k);
    cudaGetSymbolAddress((void**)&v,    g_v);
    cudaGetSymbolAddress((void**)&ctx,  g_ctx);
    cudaGetSymbolAddress((void**)&tmp,  g_tmp);
    cudaGetSymbolAddress((void**)&out1, g_out1);
    cudaGetSymbolAddress((void**)&h,    g_h);
    cudaGetSymbolAddress((void**)&keep, g_keep);
    cudaGetSymbolAddress((void**)&nanf, g_nanf);

    prep_kernel<<<B_, S_>>>(input, keep, nanf);
    build_x_kernel<<<(BS * D_) / 256, 256>>>(input, emb, keep, x);

    for (int l = 0; l < L_; ++l) {
        const float* wq_l  = wq  + l * D_ * D_;
        const float* wk_l  = wk  + l * D_ * D_;
        const float* wv_l  = wv  + l * D_ * D_;
        const float* wo_l  = wo  + l * D_ * D_;
        const float* wqb_l = wq_b + l * D_;
        const float* wkb_l = wk_b + l * D_;
        const float* wvb_l = wv_b + l * D_;
        const float* w1_l  = ffn_w1 + l * D_ * DFF;
        const float* w2_l  = ffn_w2 + l * DFF * D_;
        const float* g1 = ln1_g + l * D_, *b1 = ln1_b + l * D_;
        const float* g2 = ln2_g + l * D_, *b2 = ln2_b + l * D_;

        gemm_kernel<<<dim3(BS / 64, 1), 256>>>(x, wq_l, wqb_l, q, BS, D_, D_, 0);
        gemm_kernel<<<dim3(BS / 64, 1), 256>>>(x, wk_l, wkb_l, k, BS, D_, D_, 0);
        gemm_kernel<<<dim3(BS / 64, 1), 256>>>(x, wv_l, wvb_l, v, BS, D_, D_, 0);
        attn_kernel<<<dim3(S_ / 256, B_ * H_), 256>>>(q, k, v, nanf, ctx);
        gemm_kernel<<<dim3(BS / 64, 1), 256>>>(ctx, wo_l, nullptr, tmp, BS, D_, D_, 0);
        add_ln_kernel<<<BS / 8, 256>>>(x, tmp, g1, b1, keep, out1);
        gemm_kernel<<<dim3(BS / 64, DFF / 64), 256>>>(out1, w1_l, nullptr, h, BS, DFF, D_, 1);
        gemm_kernel<<<dim3(BS / 64, 1), 256>>>(h, w2_l, nullptr, tmp, BS, D_, DFF, 0);
        add_ln_kernel<<<BS / 8, 256>>>(out1, tmp, g2, b2, keep, x);
    }

    gemm_kernel<<<dim3(BS / 64, 1), 256>>>(x, c_w1, c_b1, q, BS, D_, D_, 1);
    gemm_kernel<<<dim3(BS / 64, 1), 256>>>(q, c_w2, c_b2, k, BS, D_, D_, 1);
    final_kernel<<<B_, 256>>>(k, c_w3, c_b3, ob, y);
}

// round 2
// speedup vs baseline: 1.2121x; 1.2121x over previous
#include <cuda_runtime.h>

#define B_  16
#define S_  1024
#define D_  64
#define H_  4
#define DFF 256
#define L_  2
#define BS  (B_ * S_)
#define KT  128

typedef unsigned long long u64;

// ------------------------- device scratch ------------------------------------
__device__ float g_x   [BS * D_];
__device__ float g_q   [BS * D_];
__device__ float g_k   [BS * D_];
__device__ float g_v   [BS * D_];
__device__ float g_ctx [BS * D_];
__device__ float g_out1[BS * D_];
__device__ float g_h   [BS * DFF];
__device__ float g_keep[BS];
__device__ float g_nanf[BS];
__device__ float g_part[BS / 64];

// ------------------------- f32x2 helpers --------------------------------------
__device__ __forceinline__ u64 fma2(u64 a, u64 b, u64 c) {
    u64 d; asm("fma.rn.f32x2 %0, %1, %2, %3;" : "=l"(d) : "l"(a), "l"(b), "l"(c)); return d;
}
__device__ __forceinline__ u64 mul2(u64 a, u64 b) {
    u64 d; asm("mul.rn.f32x2 %0, %1, %2;" : "=l"(d) : "l"(a), "l"(b)); return d;
}
__device__ __forceinline__ u64 pack2(float x, float y) {
    u64 d; asm("mov.b64 %0, {%1, %2};" : "=l"(d) : "f"(x), "f"(y)); return d;
}
__device__ __forceinline__ float2 unpack2(u64 a) {
    float lo, hi; asm("mov.b64 {%0, %1}, %2;" : "=f"(lo), "=f"(hi) : "l"(a));
    return make_float2(lo, hi);
}
__device__ __forceinline__ float ex2f(float x) {
    float r; asm("ex2.approx.f32 %0, %1;" : "=f"(r) : "f"(x)); return r;
}

// ------------------------- prep: nan flags + keep ----------------------------
__global__ void prep_kernel(const float* __restrict__ in,
                            float* __restrict__ keepv, float* __restrict__ nanf) {
    int b = blockIdx.x;
    int s = threadIdx.x;            // 1024 threads
    float v = in[b * S_ + s];
    bool nan = (v != v);
    unsigned bal = __ballot_sync(0xffffffffu, nan);
    __shared__ int warp_all[32];
    __shared__ int allnan_s;
    if ((s & 31) == 0) warp_all[s >> 5] = (bal == 0xffffffffu);
    __syncthreads();
    if (s == 0) {
        int a = 1;
        #pragma unroll
        for (int i = 0; i < 32; ++i) a &= warp_all[i];
        allnan_s = a;
    }
    __syncthreads();
    float kp = (nan || allnan_s) ? 0.f : 1.f;
    keepv[b * S_ + s] = kp;
    nanf [b * S_ + s] = nan ? 1.f : 0.f;
}

// ------------------------- build x -------------------------------------------
__global__ void build_x_kernel(const float* __restrict__ in,
                               const float* __restrict__ emb,
                               const float* __restrict__ keepv,
                               float* __restrict__ x) {
    int idx = blockIdx.x * 256 + threadIdx.x;
    int d   = idx & 63;
    int row = idx >> 6;
    int s   = row & (S_ - 1);
    float kp = keepv[row];
    float val;
    const float SQF = 7.93725393319377f * 8.0f;  // sqrt(63)*sqrt(64)
    if (d < 63) {
        val = emb[s * 63 + d] * SQF;
    } else {
        float v = in[row];
        val = (v != v) ? 0.f : v;
    }
    x[idx] = val * kp;
}

// ------------------------- fused QKV GEMM -------------------------------------
__global__ void __launch_bounds__(256) qkv_kernel(
    const float* __restrict__ x,
    const float* __restrict__ wq, const float* __restrict__ wk, const float* __restrict__ wv,
    const float* __restrict__ bq, const float* __restrict__ bk, const float* __restrict__ bv_,
    float* __restrict__ q, float* __restrict__ k, float* __restrict__ v) {
    __shared__ float As[64][65];
    __shared__ __align__(16) float Ws[64][64];
    int tid = threadIdx.x;
    int tx = tid & 15, ty = tid >> 4;
    int m0 = blockIdx.x * 64;

    for (int i = tid; i < 64 * 64; i += 256) {
        int r = i >> 6, c = i & 63;
        As[r][c] = x[(size_t)(m0 + r) * 64 + c];
    }

    u64 acc[3][4][2];
    #pragma unroll
    for (int w = 0; w < 3; ++w)
        #pragma unroll
        for (int i = 0; i < 4; ++i) { acc[w][i][0] = 0ull; acc[w][i][1] = 0ull; }

    const float* wptr[3] = {wq, wk, wv};
    for (int w = 0; w < 3; ++w) {
        __syncthreads();
        const float* W = wptr[w];
        for (int i = tid; i < 64 * 64; i += 256) Ws[i >> 6][i & 63] = W[i];
        __syncthreads();
        #pragma unroll 8
        for (int kk = 0; kk < 64; ++kk) {
            ulonglong2 w2 = *(const ulonglong2*)&Ws[kk][tx * 4];
            #pragma unroll
            for (int i = 0; i < 4; ++i) {
                float a = As[ty * 4 + i][kk];
                u64 ap = pack2(a, a);
                acc[w][i][0] = fma2(ap, w2.x, acc[w][i][0]);
                acc[w][i][1] = fma2(ap, w2.y, acc[w][i][1]);
            }
        }
    }

    const float* bptr[3] = {bq, bk, bv_};
    float* optr[3] = {q, k, v};
    #pragma unroll
    for (int w = 0; w < 3; ++w) {
        float4 bv4 = *(const float4*)&bptr[w][tx * 4];
        #pragma unroll
        for (int i = 0; i < 4; ++i) {
            float2 p0 = unpack2(acc[w][i][0]);
            float2 p1 = unpack2(acc[w][i][1]);
            float4 o = make_float4(p0.x + bv4.x, p0.y + bv4.y, p1.x + bv4.z, p1.y + bv4.w);
            *(float4*)&optr[w][(size_t)(m0 + ty * 4 + i) * 64 + tx * 4] = o;
        }
    }
}

// ------------------------- attention (branch-free, f32x2) ---------------------
__global__ void __launch_bounds__(128) attn_kernel(
    const float* __restrict__ q, const float* __restrict__ k,
    const float* __restrict__ v, const float* __restrict__ nanf,
    float* __restrict__ ctx) {
    __shared__ __align__(16) float Kt[KT][16];
    __shared__ __align__(16) float Vt[KT][16];
    __shared__ float kf[KT];

    int tid = threadIdx.x;
    int bh = blockIdx.y;
    int b = bh >> 2, h = bh & 3;
    int q0i = blockIdx.x * 256 + tid;
    size_t r0 = (size_t)b * S_ + q0i;
    size_t r1 = r0 + 128;

    const float SC = 0.25f * 1.4426950408889634f;  // 1/sqrt(16) * log2(e)
    u64 qa[8], qb[8];
    {
        const float4* p = (const float4*)(q + r0 * 64 + h * 16);
        #pragma unroll
        for (int t = 0; t < 4; ++t) {
            float4 f = p[t];
            qa[2 * t]     = pack2(f.x * SC, f.y * SC);
            qa[2 * t + 1] = pack2(f.z * SC, f.w * SC);
        }
        p = (const float4*)(q + r1 * 64 + h * 16);
        #pragma unroll
        for (int t = 0; t < 4; ++t) {
            float4 f = p[t];
            qb[2 * t]     = pack2(f.x * SC, f.y * SC);
            qb[2 * t + 1] = pack2(f.z * SC, f.w * SC);
        }
    }
    float nq0 = nanf[r0], nq1 = nanf[r1];

    u64 a0[8], a1[8];
    #pragma unroll
    for (int i = 0; i < 8; ++i) { a0[i] = 0ull; a1[i] = 0ull; }
    float Z0 = 0.f, Z1 = 0.f;

    for (int t = 0; t < S_ / KT; ++t) {
        __syncthreads();
        size_t base = (size_t)b * S_ + t * KT;
        #pragma unroll
        for (int i = tid; i < KT * 4; i += 128) {
            int j = i >> 2, d4 = i & 3;
            ((float4*)Kt[j])[d4] = ((const float4*)(k + (base + j) * 64 + h * 16))[d4];
            ((float4*)Vt[j])[d4] = ((const float4*)(v + (base + j) * 64 + h * 16))[d4];
        }
        kf[tid] = 1.f - nanf[base + tid];   // blockDim == KT
        __syncthreads();

        #pragma unroll 2
        for (int j = 0; j < KT; ++j) {
            const ulonglong2* kp = (const ulonglong2*)Kt[j];
            ulonglong2 kA = kp[0], kB = kp[1], kC = kp[2], kD = kp[3];
            u64 c0 = mul2(qa[0], kA.x); c0 = fma2(qa[1], kA.y, c0);
            c0 = fma2(qa[2], kB.x, c0); c0 = fma2(qa[3], kB.y, c0);
            u64 c1 = mul2(qa[4], kC.x); c1 = fma2(qa[5], kC.y, c1);
            c1 = fma2(qa[6], kD.x, c1); c1 = fma2(qa[7], kD.y, c1);
            u64 d0 = mul2(qb[0], kA.x); d0 = fma2(qb[1], kA.y, d0);
            d0 = fma2(qb[2], kB.x, d0); d0 = fma2(qb[3], kB.y, d0);
            u64 d1 = mul2(qb[4], kC.x); d1 = fma2(qb[5], kC.y, d1);
            d1 = fma2(qb[6], kD.x, d1); d1 = fma2(qb[7], kD.y, d1);
            float2 e0 = unpack2(c0), e1 = unpack2(c1);
            float2 f0 = unpack2(d0), f1 = unpack2(d1);
            float l0 = (e0.x + e0.y) + (e1.x + e1.y);
            float l1 = (f0.x + f0.y) + (f1.x + f1.y);
            float kfj = kf[j];
            float p0 = ex2f(l0) * kfj;
            float p1 = ex2f(l1) * kfj;
            Z0 += p0; Z1 += p1;
            u64 pp0 = pack2(p0, p0), pp1 = pack2(p1, p1);
            const ulonglong2* vp = (const ulonglong2*)Vt[j];
            ulonglong2 vA = vp[0], vB = vp[1], vC = vp[2], vD = vp[3];
            a0[0] = fma2(pp0, vA.x, a0[0]); a0[1] = fma2(pp0, vA.y, a0[1]);
            a0[2] = fma2(pp0, vB.x, a0[2]); a0[3] = fma2(pp0, vB.y, a0[3]);
            a0[4] = fma2(pp0, vC.x, a0[4]); a0[5] = fma2(pp0, vC.y, a0[5]);
            a0[6] = fma2(pp0, vD.x, a0[6]); a0[7] = fma2(pp0, vD.y, a0[7]);
            a1[0] = fma2(pp1, vA.x, a1[0]); a1[1] = fma2(pp1, vA.y, a1[1]);
            a1[2] = fma2(pp1, vB.x, a1[2]); a1[3] = fma2(pp1, vB.y, a1[3]);
            a1[4] = fma2(pp1, vC.x, a1[4]); a1[5] = fma2(pp1, vC.y, a1[5]);
            a1[6] = fma2(pp1, vD.x, a1[6]); a1[7] = fma2(pp1, vD.y, a1[7]);
        }
    }

    float rz0 = (nq0 == 0.f && Z0 > 0.f) ? (1.f / Z0) : 0.f;
    float rz1 = (nq1 == 0.f && Z1 > 0.f) ? (1.f / Z1) : 0.f;
    float4* o0 = (float4*)(ctx + r0 * 64 + h * 16);
    float4* o1 = (float4*)(ctx + r1 * 64 + h * 16);
    #pragma unroll
    for (int t = 0; t < 4; ++t) {
        float2 x0 = unpack2(a0[2 * t]), x1 = unpack2(a0[2 * t + 1]);
        o0[t] = make_float4(x0.x * rz0, x0.y * rz0, x1.x * rz0, x1.y * rz0);
        float2 y0 = unpack2(a1[2 * t]), y1 = unpack2(a1[2 * t + 1]);
        o1[t] = make_float4(y0.x * rz1, y0.y * rz1, y1.x * rz1, y1.y * rz1);
    }
}

// ------------------------- GEMM (N=64) + residual + LN + keep -----------------
__global__ void __launch_bounds__(256) gemm_ln_kernel(
    const float* __restrict__ A, const float* __restrict__ W,
    const float* __restrict__ resid,
    const float* __restrict__ g, const float* __restrict__ be,
    const float* __restrict__ keep, float* __restrict__ C, int K) {
    __shared__ float As[64][65];
    __shared__ __align__(16) float Ws[64][64];
    int tid = threadIdx.x;
    int tx = tid & 15, ty = tid >> 4;
    int m0 = blockIdx.x * 64;

    u64 acc[4][2];
    #pragma unroll
    for (int i = 0; i < 4; ++i) { acc[i][0] = 0ull; acc[i][1] = 0ull; }

    for (int k0 = 0; k0 < K; k0 += 64) {
        for (int i = tid; i < 64 * 64; i += 256) {
            int r = i >> 6, c = i & 63;
            As[r][c] = A[(size_t)(m0 + r) * K + k0 + c];
            Ws[r][c] = W[(size_t)(k0 + r) * 64 + c];
        }
        __syncthreads();
        #pragma unroll 8
        for (int kk = 0; kk < 64; ++kk) {
            ulonglong2 w2 = *(const ulonglong2*)&Ws[kk][tx * 4];
            #pragma unroll
            for (int i = 0; i < 4; ++i) {
                float a = As[ty * 4 + i][kk];
                u64 ap = pack2(a, a);
                acc[i][0] = fma2(ap, w2.x, acc[i][0]);
                acc[i][1] = fma2(ap, w2.y, acc[i][1]);
            }
        }
        __syncthreads();
    }

    // overlay As with (gemm + resid)
    #pragma unroll
    for (int i = 0; i < 4; ++i) {
        int row = ty * 4 + i;
        float4 rv = *(const float4*)&resid[(size_t)(m0 + row) * 64 + tx * 4];
        float2 p0 = unpack2(acc[i][0]);
        float2 p1 = unpack2(acc[i][1]);
        As[row][tx * 4 + 0] = p0.x + rv.x;
        As[row][tx * 4 + 1] = p0.y + rv.y;
        As[row][tx * 4 + 2] = p1.x + rv.z;
        As[row][tx * 4 + 3] = p1.y + rv.w;
    }
    __syncthreads();

    int row = tid >> 2, part = tid & 3;
    const float* rp = &As[row][part * 16];
    float s = 0.f, ss = 0.f;
    #pragma unroll
    for (int c = 0; c < 16; ++c) { float vv = rp[c]; s += vv; ss += vv * vv; }
    s  += __shfl_xor_sync(0xffffffffu, s, 1);  s  += __shfl_xor_sync(0xffffffffu, s, 2);
    ss += __shfl_xor_sync(0xffffffffu, ss, 1); ss += __shfl_xor_sync(0xffffffffu, ss, 2);
    float mean = s * (1.f / 64.f);
    float var  = ss * (1.f / 64.f) - mean * mean;
    float inv  = rsqrtf(var + 1e-6f);
    float kp   = keep[m0 + row];
    float* op = &C[(size_t)(m0 + row) * 64 + part * 16];
    #pragma unroll
    for (int c4 = 0; c4 < 4; ++c4) {
        int c = part * 16 + c4 * 4;
        float4 o;
        o.x = ((rp[c4 * 4 + 0] - mean) * inv * g[c + 0] + be[c + 0]) * kp;
        o.y = ((rp[c4 * 4 + 1] - mean) * inv * g[c + 1] + be[c + 1]) * kp;
        o.z = ((rp[c4 * 4 + 2] - mean) * inv * g[c + 2] + be[c + 2]) * kp;
        o.w = ((rp[c4 * 4 + 3] - mean) * inv * g[c + 3] + be[c + 3]) * kp;
        *(float4*)&op[c4 * 4] = o;
    }
}

// ------------------------- FFN1: relu(A@W1), K=64, N=256 ----------------------
__global__ void __launch_bounds__(256) ffn1_kernel(
    const float* __restrict__ A, const float* __restrict__ W, float* __restrict__ C) {
    __shared__ float As[64][65];
    __shared__ __align__(16) float Ws[64][64];
    int tid = threadIdx.x;
    int tx = tid & 15, ty = tid >> 4;
    int m0 = blockIdx.x * 64;
    int n0 = blockIdx.y * 64;

    for (int i = tid; i < 64 * 64; i += 256) {
        int r = i >> 6, c = i & 63;
        As[r][c] = A[(size_t)(m0 + r) * 64 + c];
        Ws[r][c] = W[(size_t)r * DFF + n0 + c];
    }
    __syncthreads();

    u64 acc[4][2];
    #pragma unroll
    for (int i = 0; i < 4; ++i) { acc[i][0] = 0ull; acc[i][1] = 0ull; }
    #pragma unroll 8
    for (int kk = 0; kk < 64; ++kk) {
        ulonglong2 w2 = *(const ulonglong2*)&Ws[kk][tx * 4];
        #pragma unroll
        for (int i = 0; i < 4; ++i) {
            float a = As[ty * 4 + i][kk];
            u64 ap = pack2(a, a);
            acc[i][0] = fma2(ap, w2.x, acc[i][0]);
            acc[i][1] = fma2(ap, w2.y, acc[i][1]);
        }
    }

    #pragma unroll
    for (int i = 0; i < 4; ++i) {
        float2 p0 = unpack2(acc[i][0]);
        float2 p1 = unpack2(acc[i][1]);
        float4 o = make_float4(fmaxf(p0.x, 0.f), fmaxf(p0.y, 0.f),
                               fmaxf(p1.x, 0.f), fmaxf(p1.y, 0.f));
        *(float4*)&C[(size_t)(m0 + ty * 4 + i) * DFF + n0 + tx * 4] = o;
    }
}

// ------------------------- classifier fused -----------------------------------
__global__ void __launch_bounds__(256) cls_kernel(
    const float* __restrict__ x,
    const float* __restrict__ w1, const float* __restrict__ b1,
    const float* __restrict__ w2, const float* __restrict__ b2,
    const float* __restrict__ w3, const float* __restrict__ b3,
    float* __restrict__ part) {
    __shared__ float Xs[64][65];            // reused as Hs after gemm1
    __shared__ __align__(16) float Ws[64][64];
    __shared__ float w3s[64];
    __shared__ float red[256];
    int tid = threadIdx.x;
    int tx = tid & 15, ty = tid >> 4;
    int m0 = blockIdx.x * 64;

    for (int i = tid; i < 64 * 64; i += 256) {
        int r = i >> 6, c = i & 63;
        Xs[r][c] = x[(size_t)(m0 + r) * 64 + c];
        Ws[r][c] = w1[i];
    }
    if (tid < 64) w3s[tid] = w3[tid];
    __syncthreads();

    // gemm1: h1 = relu(x @ w1 + b1)
    u64 acc[4][2];
    #pragma unroll
    for (int i = 0; i < 4; ++i) { acc[i][0] = 0ull; acc[i][1] = 0ull; }
    #pragma unroll 8
    for (int kk = 0; kk < 64; ++kk) {
        ulonglong2 w2v = *(const ulonglong2*)&Ws[kk][tx * 4];
        #pragma unroll
        for (int i = 0; i < 4; ++i) {
            float a = Xs[ty * 4 + i][kk];
            u64 ap = pack2(a, a);
            acc[i][0] = fma2(ap, w2v.x, acc[i][0]);
            acc[i][1] = fma2(ap, w2v.y, acc[i][1]);
        }
    }
    __syncthreads();   // all reads of Xs / Ws done

    float4 b1v = *(const float4*)&b1[tx * 4];
    #pragma unroll
    for (int i = 0; i < 4; ++i) {
        int row = ty * 4 + i;
        float2 p0 = unpack2(acc[i][0]);
        float2 p1 = unpack2(acc[i][1]);
        Xs[row][tx * 4 + 0] = fmaxf(p0.x + b1v.x, 0.f);
        Xs[row][tx * 4 + 1] = fmaxf(p0.y + b1v.y, 0.f);
        Xs[row][tx * 4 + 2] = fmaxf(p1.x + b1v.z, 0.f);
        Xs[row][tx * 4 + 3] = fmaxf(p1.y + b1v.w, 0.f);
    }
    for (int i = tid; i < 64 * 64; i += 256) Ws[i >> 6][i & 63] = w2[i];
    __syncthreads();

    // gemm2: h2 = relu(h1 @ w2 + b2), then phi partial = sum h2 * w3
    #pragma unroll
    for (int i = 0; i < 4; ++i) { acc[i][0] = 0ull; acc[i][1] = 0ull; }
    #pragma unroll 8
    for (int kk = 0; kk < 64; ++kk) {
        ulonglong2 w2v = *(const ulonglong2*)&Ws[kk][tx * 4];
        #pragma unroll
        for (int i = 0; i < 4; ++i) {
            float a = Xs[ty * 4 + i][kk];
            u64 ap = pack2(a, a);
            acc[i][0] = fma2(ap, w2v.x, acc[i][0]);
            acc[i][1] = fma2(ap, w2v.y, acc[i][1]);
        }
    }

    float4 b2v = *(const float4*)&b2[tx * 4];
    float partial = 0.f;
    #pragma unroll
    for (int i = 0; i < 4; ++i) {
        float2 p0 = unpack2(acc[i][0]);
        float2 p1 = unpack2(acc[i][1]);
        partial += fmaxf(p0.x + b2v.x, 0.f) * w3s[tx * 4 + 0];
        partial += fmaxf(p0.y + b2v.y, 0.f) * w3s[tx * 4 + 1];
        partial += fmaxf(p1.x + b2v.z, 0.f) * w3s[tx * 4 + 2];
        partial += fmaxf(p1.y + b2v.w, 0.f) * w3s[tx * 4 + 3];
    }
    red[tid] = partial;
    __syncthreads();
    for (int st = 128; st > 0; st >>= 1) {
        if (tid < st) red[tid] += red[tid + st];
        __syncthreads();
    }
    if (tid == 0) part[blockIdx.x] = red[0] + 64.f * b3[0];
}

// ------------------------- deterministic final reduction ----------------------
__global__ void reduce_y(const float* __restrict__ part,
                         const float* __restrict__ ob, float* __restrict__ y) {
    int b = threadIdx.x;   // 16
    float s = ob[0];
    #pragma unroll
    for (int i = 0; i < 16; ++i) s += part[b * 16 + i];
    y[b] = s;
}

// ------------------------- launcher ------------------------------------------
extern "C" void kernel_launch(void* const* d_in, const int* in_sizes, int n_in,
                              void* d_out, int out_size) {
    const float* input  = (const float*)d_in[0];
    const float* emb    = (const float*)d_in[1];
    const float* wq     = (const float*)d_in[2];
    const float* wq_b   = (const float*)d_in[3];
    const float* wk     = (const float*)d_in[4];
    const float* wk_b   = (const float*)d_in[5];
    const float* wv     = (const float*)d_in[6];
    const float* wv_b   = (const float*)d_in[7];
    const float* wo     = (const float*)d_in[8];
    const float* ffn_w1 = (const float*)d_in[9];
    const float* ffn_w2 = (const float*)d_in[10];
    const float* ln1_g  = (const float*)d_in[11];
    const float* ln1_b  = (const float*)d_in[12];
    const float* ln2_g  = (const float*)d_in[13];
    const float* ln2_b  = (const float*)d_in[14];
    const float* c_w1   = (const float*)d_in[15];
    const float* c_b1   = (const float*)d_in[16];
    const float* c_w2   = (const float*)d_in[17];
    const float* c_b2   = (const float*)d_in[18];
    const float* c_w3   = (const float*)d_in[19];
    const float* c_b3   = (const float*)d_in[20];
    const float* ob     = (const float*)d_in[21];
    float* y = (float*)d_out;

    float *x, *q, *k, *v, *ctx, *out1, *h, *keep, *nanf, *part;
    cudaGetSymbolAddress((void**)&x,    g_x);
    cudaGetSymbolAddress((void**)&q,    g_q);
    cudaGetSymbolAddress((void**)&k,    g_k);
    cudaGetSymbolAddress((void**)&v,    g_v);
    cudaGetSymbolAddress((void**)&ctx,  g_ctx);
    cudaGetSymbolAddress((void**)&out1, g_out1);
    cudaGetSymbolAddress((void**)&h,    g_h);
    cudaGetSymbolAddress((void**)&keep, g_keep);
    cudaGetSymbolAddress((void**)&nanf, g_nanf);
    cudaGetSymbolAddress((void**)&part, g_part);

    prep_kernel<<<B_, S_>>>(input, keep, nanf);
    build_x_kernel<<<(BS * D_) / 256, 256>>>(input, emb, keep, x);

    for (int l = 0; l < L_; ++l) {
        const float* wq_l  = wq  + l * D_ * D_;
        const float* wk_l  = wk  + l * D_ * D_;
        const float* wv_l  = wv  + l * D_ * D_;
        const float* wo_l  = wo  + l * D_ * D_;
        const float* w1_l  = ffn_w1 + l * D_ * DFF;
        const float* w2_l  = ffn_w2 + l * DFF * D_;

        qkv_kernel<<<BS / 64, 256>>>(x, wq_l, wk_l, wv_l,
                                     wq_b + l * D_, wk_b + l * D_, wv_b + l * D_,
                                     q, k, v);
        attn_kernel<<<dim3(S_ / 256, B_ * H_), 128>>>(q, k, v, nanf, ctx);
        gemm_ln_kernel<<<BS / 64, 256>>>(ctx, wo_l, x,
                                         ln1_g + l * D_, ln1_b + l * D_, keep, out1, 64);
        ffn1_kernel<<<dim3(BS / 64, DFF / 64), 256>>>(out1, w1_l, h);
        gemm_ln_kernel<<<BS / 64, 256>>>(h, w2_l, out1,
                                         ln2_g + l * D_, ln2_b + l * D_, keep, x, DFF);
    }

    cls_kernel<<<BS / 64, 256>>>(x, c_w1, c_b1, c_w2, c_b2, c_w3, c_b3, part);
    reduce_y<<<1, 16>>>(part, ob, y);
}

// round 3
// speedup vs baseline: 1.3976x; 1.1530x over previous
#include <cuda_runtime.h>

#define B_  16
#define S_  1024
#define D_  64
#define H_  4
#define DFF 256
#define L_  2
#define BS  (B_ * S_)
#define KT  128
#define NSPLIT 4
#define QH  (B_ * S_ * H_)   // 65536 query-head rows

typedef unsigned long long u64;

// ------------------------- device scratch ------------------------------------
__device__ float g_x   [BS * D_];
__device__ float g_q   [BS * D_];
__device__ float g_k   [BS * D_];
__device__ float g_v   [BS * D_];
__device__ float g_ctx [BS * D_];
__device__ float g_out1[BS * D_];
__device__ float g_h   [BS * DFF];
__device__ float g_keep[BS];
__device__ float g_nanf[BS];
__device__ float g_part[BS / 64];
__device__ float g_pctx[NSPLIT * QH * 16];
__device__ float g_pz  [NSPLIT * QH];

// ------------------------- f32x2 helpers --------------------------------------
__device__ __forceinline__ u64 fma2(u64 a, u64 b, u64 c) {
    u64 d; asm("fma.rn.f32x2 %0, %1, %2, %3;" : "=l"(d) : "l"(a), "l"(b), "l"(c)); return d;
}
__device__ __forceinline__ u64 mul2(u64 a, u64 b) {
    u64 d; asm("mul.rn.f32x2 %0, %1, %2;" : "=l"(d) : "l"(a), "l"(b)); return d;
}
__device__ __forceinline__ u64 pack2(float x, float y) {
    u64 d; asm("mov.b64 %0, {%1, %2};" : "=l"(d) : "f"(x), "f"(y)); return d;
}
__device__ __forceinline__ float2 unpack2(u64 a) {
    float lo, hi; asm("mov.b64 {%0, %1}, %2;" : "=f"(lo), "=f"(hi) : "l"(a));
    return make_float2(lo, hi);
}
__device__ __forceinline__ float ex2f(float x) {
    float r; asm("ex2.approx.f32 %0, %1;" : "=f"(r) : "f"(x)); return r;
}

// ------------------------- prep: nan flags + keep ----------------------------
__global__ void prep_kernel(const float* __restrict__ in,
                            float* __restrict__ keepv, float* __restrict__ nanf) {
    int b = blockIdx.x;
    int s = threadIdx.x;            // 1024 threads
    float v = in[b * S_ + s];
    bool nan = (v != v);
    unsigned bal = __ballot_sync(0xffffffffu, nan);
    __shared__ int warp_all[32];
    __shared__ int allnan_s;
    if ((s & 31) == 0) warp_all[s >> 5] = (bal == 0xffffffffu);
    __syncthreads();
    if (s == 0) {
        int a = 1;
        #pragma unroll
        for (int i = 0; i < 32; ++i) a &= warp_all[i];
        allnan_s = a;
    }
    __syncthreads();
    float kp = (nan || allnan_s) ? 0.f : 1.f;
    keepv[b * S_ + s] = kp;
    nanf [b * S_ + s] = nan ? 1.f : 0.f;
}

// ------------------------- build x -------------------------------------------
__global__ void build_x_kernel(const float* __restrict__ in,
                               const float* __restrict__ emb,
                               const float* __restrict__ keepv,
                               float* __restrict__ x) {
    int idx = blockIdx.x * 256 + threadIdx.x;
    int d   = idx & 63;
    int row = idx >> 6;
    int s   = row & (S_ - 1);
    float kp = keepv[row];
    float val;
    const float SQF = 7.93725393319377f * 8.0f;  // sqrt(63)*sqrt(64)
    if (d < 63) {
        val = emb[s * 63 + d] * SQF;
    } else {
        float v = in[row];
        val = (v != v) ? 0.f : v;
    }
    x[idx] = val * kp;
}

// ------------------------- fused QKV GEMM -------------------------------------
__global__ void __launch_bounds__(256) qkv_kernel(
    const float* __restrict__ x,
    const float* __restrict__ wq, const float* __restrict__ wk, const float* __restrict__ wv,
    const float* __restrict__ bq, const float* __restrict__ bk, const float* __restrict__ bv_,
    float* __restrict__ q, float* __restrict__ k, float* __restrict__ v) {
    __shared__ float As[64][65];
    __shared__ __align__(16) float Ws[64][64];
    int tid = threadIdx.x;
    int tx = tid & 15, ty = tid >> 4;
    int m0 = blockIdx.x * 64;

    for (int i = tid; i < 64 * 64; i += 256) {
        int r = i >> 6, c = i & 63;
        As[r][c] = x[(size_t)(m0 + r) * 64 + c];
    }

    u64 acc[3][4][2];
    #pragma unroll
    for (int w = 0; w < 3; ++w)
        #pragma unroll
        for (int i = 0; i < 4; ++i) { acc[w][i][0] = 0ull; acc[w][i][1] = 0ull; }

    const float* wptr[3] = {wq, wk, wv};
    for (int w = 0; w < 3; ++w) {
        __syncthreads();
        const float* W = wptr[w];
        for (int i = tid; i < 64 * 64; i += 256) Ws[i >> 6][i & 63] = W[i];
        __syncthreads();
        #pragma unroll 8
        for (int kk = 0; kk < 64; ++kk) {
            ulonglong2 w2 = *(const ulonglong2*)&Ws[kk][tx * 4];
            #pragma unroll
            for (int i = 0; i < 4; ++i) {
                float a = As[ty * 4 + i][kk];
                u64 ap = pack2(a, a);
                acc[w][i][0] = fma2(ap, w2.x, acc[w][i][0]);
                acc[w][i][1] = fma2(ap, w2.y, acc[w][i][1]);
            }
        }
    }

    const float* bptr[3] = {bq, bk, bv_};
    float* optr[3] = {q, k, v};
    #pragma unroll
    for (int w = 0; w < 3; ++w) {
        float4 bv4 = *(const float4*)&bptr[w][tx * 4];
        #pragma unroll
        for (int i = 0; i < 4; ++i) {
            float2 p0 = unpack2(acc[w][i][0]);
            float2 p1 = unpack2(acc[w][i][1]);
            float4 o = make_float4(p0.x + bv4.x, p0.y + bv4.y, p1.x + bv4.z, p1.y + bv4.w);
            *(float4*)&optr[w][(size_t)(m0 + ty * 4 + i) * 64 + tx * 4] = o;
        }
    }
}

// ------------------------- attention partial (key-split, branch-free) ---------
__global__ void __launch_bounds__(128) attn_kernel(
    const float* __restrict__ q, const float* __restrict__ k,
    const float* __restrict__ v, const float* __restrict__ nanf,
    float* __restrict__ pctx, float* __restrict__ pz) {
    __shared__ __align__(16) float Kt[KT][16];
    __shared__ __align__(16) float Vt[KT][16];
    __shared__ float kf[KT];

    int tid = threadIdx.x;
    int bh = blockIdx.y;
    int split = blockIdx.z;
    int b = bh >> 2, h = bh & 3;
    int q0i = blockIdx.x * 256 + tid;
    size_t r0 = (size_t)b * S_ + q0i;
    size_t r1 = r0 + 128;

    const float SC = 0.25f * 1.4426950408889634f;  // 1/sqrt(16) * log2(e)
    u64 qa[8], qb[8];
    {
        const float4* p = (const float4*)(q + r0 * 64 + h * 16);
        #pragma unroll
        for (int t = 0; t < 4; ++t) {
            float4 f = p[t];
            qa[2 * t]     = pack2(f.x * SC, f.y * SC);
            qa[2 * t + 1] = pack2(f.z * SC, f.w * SC);
        }
        p = (const float4*)(q + r1 * 64 + h * 16);
        #pragma unroll
        for (int t = 0; t < 4; ++t) {
            float4 f = p[t];
            qb[2 * t]     = pack2(f.x * SC, f.y * SC);
            qb[2 * t + 1] = pack2(f.z * SC, f.w * SC);
        }
    }

    u64 a0[8], a1[8];
    #pragma unroll
    for (int i = 0; i < 8; ++i) { a0[i] = 0ull; a1[i] = 0ull; }
    float Z0 = 0.f, Z1 = 0.f;

    int t_begin = split * (S_ / KT / NSPLIT);
    for (int t = t_begin; t < t_begin + S_ / KT / NSPLIT; ++t) {
        __syncthreads();
        size_t base = (size_t)b * S_ + t * KT;
        #pragma unroll
        for (int i = tid; i < KT * 4; i += 128) {
            int j = i >> 2, d4 = i & 3;
            ((float4*)Kt[j])[d4] = ((const float4*)(k + (base + j) * 64 + h * 16))[d4];
            ((float4*)Vt[j])[d4] = ((const float4*)(v + (base + j) * 64 + h * 16))[d4];
        }
        kf[tid] = 1.f - nanf[base + tid];   // blockDim == KT
        __syncthreads();

        #pragma unroll 2
        for (int j = 0; j < KT; ++j) {
            const ulonglong2* kp = (const ulonglong2*)Kt[j];
            ulonglong2 kA = kp[0], kB = kp[1], kC = kp[2], kD = kp[3];
            u64 c0 = mul2(qa[0], kA.x); c0 = fma2(qa[1], kA.y, c0);
            c0 = fma2(qa[2], kB.x, c0); c0 = fma2(qa[3], kB.y, c0);
            u64 c1 = mul2(qa[4], kC.x); c1 = fma2(qa[5], kC.y, c1);
            c1 = fma2(qa[6], kD.x, c1); c1 = fma2(qa[7], kD.y, c1);
            u64 d0 = mul2(qb[0], kA.x); d0 = fma2(qb[1], kA.y, d0);
            d0 = fma2(qb[2], kB.x, d0); d0 = fma2(qb[3], kB.y, d0);
            u64 d1 = mul2(qb[4], kC.x); d1 = fma2(qb[5], kC.y, d1);
            d1 = fma2(qb[6], kD.x, d1); d1 = fma2(qb[7], kD.y, d1);
            float2 e0 = unpack2(c0), e1 = unpack2(c1);
            float2 f0 = unpack2(d0), f1 = unpack2(d1);
            float l0 = (e0.x + e0.y) + (e1.x + e1.y);
            float l1 = (f0.x + f0.y) + (f1.x + f1.y);
            float kfj = kf[j];
            float p0 = ex2f(l0) * kfj;
            float p1 = ex2f(l1) * kfj;
            Z0 += p0; Z1 += p1;
            u64 pp0 = pack2(p0, p0), pp1 = pack2(p1, p1);
            const ulonglong2* vp = (const ulonglong2*)Vt[j];
            ulonglong2 vA = vp[0], vB = vp[1], vC = vp[2], vD = vp[3];
            a0[0] = fma2(pp0, vA.x, a0[0]); a0[1] = fma2(pp0, vA.y, a0[1]);
            a0[2] = fma2(pp0, vB.x, a0[2]); a0[3] = fma2(pp0, vB.y, a0[3]);
            a0[4] = fma2(pp0, vC.x, a0[4]); a0[5] = fma2(pp0, vC.y, a0[5]);
            a0[6] = fma2(pp0, vD.x, a0[6]); a0[7] = fma2(pp0, vD.y, a0[7]);
            a1[0] = fma2(pp1, vA.x, a1[0]); a1[1] = fma2(pp1, vA.y, a1[1]);
            a1[2] = fma2(pp1, vB.x, a1[2]); a1[3] = fma2(pp1, vB.y, a1[3]);
            a1[4] = fma2(pp1, vC.x, a1[4]); a1[5] = fma2(pp1, vC.y, a1[5]);
            a1[6] = fma2(pp1, vD.x, a1[6]); a1[7] = fma2(pp1, vD.y, a1[7]);
        }
    }

    size_t pi0 = (size_t)bh * S_ + q0i;           // query-head row id
    size_t pi1 = pi0 + 128;
    float4* o0 = (float4*)(pctx + ((size_t)split * QH + pi0) * 16);
    float4* o1 = (float4*)(pctx + ((size_t)split * QH + pi1) * 16);
    #pragma unroll
    for (int t = 0; t < 4; ++t) {
        float2 x0 = unpack2(a0[2 * t]), x1 = unpack2(a0[2 * t + 1]);
        o0[t] = make_float4(x0.x, x0.y, x1.x, x1.y);
        float2 y0 = unpack2(a1[2 * t]), y1 = unpack2(a1[2 * t + 1]);
        o1[t] = make_float4(y0.x, y0.y, y1.x, y1.y);
    }
    pz[(size_t)split * QH + pi0] = Z0;
    pz[(size_t)split * QH + pi1] = Z1;
}

// ------------------------- attention combine ----------------------------------
__global__ void __launch_bounds__(256) attn_combine(
    const float* __restrict__ pctx, const float* __restrict__ pz,
    const float* __restrict__ nanf, float* __restrict__ ctx) {
    int i = blockIdx.x * 256 + threadIdx.x;   // [0, QH)
    int bh = i >> 10, qq = i & 1023;
    int b = bh >> 2, h = bh & 3;

    float Z = 0.f;
    float4 a[4];
    #pragma unroll
    for (int t = 0; t < 4; ++t) a[t] = make_float4(0.f, 0.f, 0.f, 0.f);
    #pragma unroll
    for (int s = 0; s < NSPLIT; ++s) {
        Z += pz[(size_t)s * QH + i];
        const float4* p = (const float4*)(pctx + ((size_t)s * QH + i) * 16);
        #pragma unroll
        for (int t = 0; t < 4; ++t) {
            float4 f = p[t];
            a[t].x += f.x; a[t].y += f.y; a[t].z += f.z; a[t].w += f.w;
        }
    }
    float nq = nanf[b * S_ + qq];
    float rz = (nq == 0.f && Z > 0.f) ? (1.f / Z) : 0.f;
    float4* o = (float4*)(ctx + ((size_t)b * S_ + qq) * 64 + h * 16);
    #pragma unroll
    for (int t = 0; t < 4; ++t)
        o[t] = make_float4(a[t].x * rz, a[t].y * rz, a[t].z * rz, a[t].w * rz);
}

// ------------------------- GEMM (N=64) + residual + LN + keep -----------------
__global__ void __launch_bounds__(256) gemm_ln_kernel(
    const float* __restrict__ A, const float* __restrict__ W,
    const float* __restrict__ resid,
    const float* __restrict__ g, const float* __restrict__ be,
    const float* __restrict__ keep, float* __restrict__ C, int K) {
    __shared__ float As[64][65];
    __shared__ __align__(16) float Ws[64][64];
    int tid = threadIdx.x;
    int tx = tid & 15, ty = tid >> 4;
    int m0 = blockIdx.x * 64;

    u64 acc[4][2];
    #pragma unroll
    for (int i = 0; i < 4; ++i) { acc[i][0] = 0ull; acc[i][1] = 0ull; }

    for (int k0 = 0; k0 < K; k0 += 64) {
        for (int i = tid; i < 64 * 64; i += 256) {
            int r = i >> 6, c = i & 63;
            As[r][c] = A[(size_t)(m0 + r) * K + k0 + c];
            Ws[r][c] = W[(size_t)(k0 + r) * 64 + c];
        }
        __syncthreads();
        #pragma unroll 8
        for (int kk = 0; kk < 64; ++kk) {
            ulonglong2 w2 = *(const ulonglong2*)&Ws[kk][tx * 4];
            #pragma unroll
            for (int i = 0; i < 4; ++i) {
                float a = As[ty * 4 + i][kk];
                u64 ap = pack2(a, a);
                acc[i][0] = fma2(ap, w2.x, acc[i][0]);
                acc[i][1] = fma2(ap, w2.y, acc[i][1]);
            }
        }
        __syncthreads();
    }

    // overlay As with (gemm + resid)
    #pragma unroll
    for (int i = 0; i < 4; ++i) {
        int row = ty * 4 + i;
        float4 rv = *(const float4*)&resid[(size_t)(m0 + row) * 64 + tx * 4];
        float2 p0 = unpack2(acc[i][0]);
        float2 p1 = unpack2(acc[i][1]);
        As[row][tx * 4 + 0] = p0.x + rv.x;
        As[row][tx * 4 + 1] = p0.y + rv.y;
        As[row][tx * 4 + 2] = p1.x + rv.z;
        As[row][tx * 4 + 3] = p1.y + rv.w;
    }
    __syncthreads();

    int row = tid >> 2, part = tid & 3;
    const float* rp = &As[row][part * 16];
    float s = 0.f, ss = 0.f;
    #pragma unroll
    for (int c = 0; c < 16; ++c) { float vv = rp[c]; s += vv; ss += vv * vv; }
    s  += __shfl_xor_sync(0xffffffffu, s, 1);  s  += __shfl_xor_sync(0xffffffffu, s, 2);
    ss += __shfl_xor_sync(0xffffffffu, ss, 1); ss += __shfl_xor_sync(0xffffffffu, ss, 2);
    float mean = s * (1.f / 64.f);
    float var  = ss * (1.f / 64.f) - mean * mean;
    float inv  = rsqrtf(var + 1e-6f);
    float kp   = keep[m0 + row];
    float* op = &C[(size_t)(m0 + row) * 64 + part * 16];
    #pragma unroll
    for (int c4 = 0; c4 < 4; ++c4) {
        int c = part * 16 + c4 * 4;
        float4 o;
        o.x = ((rp[c4 * 4 + 0] - mean) * inv * g[c + 0] + be[c + 0]) * kp;
        o.y = ((rp[c4 * 4 + 1] - mean) * inv * g[c + 1] + be[c + 1]) * kp;
        o.z = ((rp[c4 * 4 + 2] - mean) * inv * g[c + 2] + be[c + 2]) * kp;
        o.w = ((rp[c4 * 4 + 3] - mean) * inv * g[c + 3] + be[c + 3]) * kp;
        *(float4*)&op[c4 * 4] = o;
    }
}

// ------------------------- FFN1: relu(A@W1), K=64, N=256 ----------------------
__global__ void __launch_bounds__(256) ffn1_kernel(
    const float* __restrict__ A, const float* __restrict__ W, float* __restrict__ C) {
    __shared__ float As[64][65];
    __shared__ __align__(16) float Ws[64][64];
    int tid = threadIdx.x;
    int tx = tid & 15, ty = tid >> 4;
    int m0 = blockIdx.x * 64;
    int n0 = blockIdx.y * 64;

    for (int i = tid; i < 64 * 64; i += 256) {
        int r = i >> 6, c = i & 63;
        As[r][c] = A[(size_t)(m0 + r) * 64 + c];
        Ws[r][c] = W[(size_t)r * DFF + n0 + c];
    }
    __syncthreads();

    u64 acc[4][2];
    #pragma unroll
    for (int i = 0; i < 4; ++i) { acc[i][0] = 0ull; acc[i][1] = 0ull; }
    #pragma unroll 8
    for (int kk = 0; kk < 64; ++kk) {
        ulonglong2 w2 = *(const ulonglong2*)&Ws[kk][tx * 4];
        #pragma unroll
        for (int i = 0; i < 4; ++i) {
            float a = As[ty * 4 + i][kk];
            u64 ap = pack2(a, a);
            acc[i][0] = fma2(ap, w2.x, acc[i][0]);
            acc[i][1] = fma2(ap, w2.y, acc[i][1]);
        }
    }

    #pragma unroll
    for (int i = 0; i < 4; ++i) {
        float2 p0 = unpack2(acc[i][0]);
        float2 p1 = unpack2(acc[i][1]);
        float4 o = make_float4(fmaxf(p0.x, 0.f), fmaxf(p0.y, 0.f),
                               fmaxf(p1.x, 0.f), fmaxf(p1.y, 0.f));
        *(float4*)&C[(size_t)(m0 + ty * 4 + i) * DFF + n0 + tx * 4] = o;
    }
}

// ------------------------- classifier fused -----------------------------------
__global__ void __launch_bounds__(256) cls_kernel(
    const float* __restrict__ x,
    const float* __restrict__ w1, const float* __restrict__ b1,
    const float* __restrict__ w2, const float* __restrict__ b2,
    const float* __restrict__ w3, const float* __restrict__ b3,
    float* __restrict__ part) {
    __shared__ float Xs[64][65];            // reused as Hs after gemm1
    __shared__ __align__(16) float Ws[64][64];
    __shared__ float w3s[64];
    __shared__ float red[256];
    int tid = threadIdx.x;
    int tx = tid & 15, ty = tid >> 4;
    int m0 = blockIdx.x * 64;

    for (int i = tid; i < 64 * 64; i += 256) {
        int r = i >> 6, c = i & 63;
        Xs[r][c] = x[(size_t)(m0 + r) * 64 + c];
        Ws[r][c] = w1[i];
    }
    if (tid < 64) w3s[tid] = w3[tid];
    __syncthreads();

    // gemm1: h1 = relu(x @ w1 + b1)
    u64 acc[4][2];
    #pragma unroll
    for (int i = 0; i < 4; ++i) { acc[i][0] = 0ull; acc[i][1] = 0ull; }
    #pragma unroll 8
    for (int kk = 0; kk < 64; ++kk) {
        ulonglong2 w2v = *(const ulonglong2*)&Ws[kk][tx * 4];
        #pragma unroll
        for (int i = 0; i < 4; ++i) {
            float a = Xs[ty * 4 + i][kk];
            u64 ap = pack2(a, a);
            acc[i][0] = fma2(ap, w2v.x, acc[i][0]);
            acc[i][1] = fma2(ap, w2v.y, acc[i][1]);
        }
    }
    __syncthreads();   // all reads of Xs / Ws done

    float4 b1v = *(const float4*)&b1[tx * 4];
    #pragma unroll
    for (int i = 0; i < 4; ++i) {
        int row = ty * 4 + i;
        float2 p0 = unpack2(acc[i][0]);
        float2 p1 = unpack2(acc[i][1]);
        Xs[row][tx * 4 + 0] = fmaxf(p0.x + b1v.x, 0.f);
        Xs[row][tx * 4 + 1] = fmaxf(p0.y + b1v.y, 0.f);
        Xs[row][tx * 4 + 2] = fmaxf(p1.x + b1v.z, 0.f);
        Xs[row][tx * 4 + 3] = fmaxf(p1.y + b1v.w, 0.f);
    }
    for (int i = tid; i < 64 * 64; i += 256) Ws[i >> 6][i & 63] = w2[i];
    __syncthreads();

    // gemm2: h2 = relu(h1 @ w2 + b2), then phi partial = sum h2 * w3
    #pragma unroll
    for (int i = 0; i < 4; ++i) { acc[i][0] = 0ull; acc[i][1] = 0ull; }
    #pragma unroll 8
    for (int kk = 0; kk < 64; ++kk) {
        ulonglong2 w2v = *(const ulonglong2*)&Ws[kk][tx * 4];
        #pragma unroll
        for (int i = 0; i < 4; ++i) {
            float a = Xs[ty * 4 + i][kk];
            u64 ap = pack2(a, a);
            acc[i][0] = fma2(ap, w2v.x, acc[i][0]);
            acc[i][1] = fma2(ap, w2v.y, acc[i][1]);
        }
    }

    float4 b2v = *(const float4*)&b2[tx * 4];
    float partial = 0.f;
    #pragma unroll
    for (int i = 0; i < 4; ++i) {
        float2 p0 = unpack2(acc[i][0]);
        float2 p1 = unpack2(acc[i][1]);
        partial += fmaxf(p0.x + b2v.x, 0.f) * w3s[tx * 4 + 0];
        partial += fmaxf(p0.y + b2v.y, 0.f) * w3s[tx * 4 + 1];
        partial += fmaxf(p1.x + b2v.z, 0.f) * w3s[tx * 4 + 2];
        partial += fmaxf(p1.y + b2v.w, 0.f) * w3s[tx * 4 + 3];
    }
    red[tid] = partial;
    __syncthreads();
    for (int st = 128; st > 0; st >>= 1) {
        if (tid < st) red[tid] += red[tid + st];
        __syncthreads();
    }
    if (tid == 0) part[blockIdx.x] = red[0] + 64.f * b3[0];
}

// ------------------------- deterministic final reduction ----------------------
__global__ void reduce_y(const float* __restrict__ part,
                         const float* __restrict__ ob, float* __restrict__ y) {
    int b = threadIdx.x;   // 16
    float s = ob[0];
    #pragma unroll
    for (int i = 0; i < 16; ++i) s += part[b * 16 + i];
    y[b] = s;
}

// ------------------------- launcher ------------------------------------------
extern "C" void kernel_launch(void* const* d_in, const int* in_sizes, int n_in,
                              void* d_out, int out_size) {
    const float* input  = (const float*)d_in[0];
    const float* emb    = (const float*)d_in[1];
    const float* wq     = (const float*)d_in[2];
    const float* wq_b   = (const float*)d_in[3];
    const float* wk     = (const float*)d_in[4];
    const float* wk_b   = (const float*)d_in[5];
    const float* wv     = (const float*)d_in[6];
    const float* wv_b   = (const float*)d_in[7];
    const float* wo     = (const float*)d_in[8];
    const float* ffn_w1 = (const float*)d_in[9];
    const float* ffn_w2 = (const float*)d_in[10];
    const float* ln1_g  = (const float*)d_in[11];
    const float* ln1_b  = (const float*)d_in[12];
    const float* ln2_g  = (const float*)d_in[13];
    const float* ln2_b  = (const float*)d_in[14];
    const float* c_w1   = (const float*)d_in[15];
    const float* c_b1   = (const float*)d_in[16];
    const float* c_w2   = (const float*)d_in[17];
    const float* c_b2   = (const float*)d_in[18];
    const float* c_w3   = (const float*)d_in[19];
    const float* c_b3   = (const float*)d_in[20];
    const float* ob     = (const float*)d_in[21];
    float* y = (float*)d_out;

    float *x, *q, *k, *v, *ctx, *out1, *h, *keep, *nanf, *part, *pctx, *pz;
    cudaGetSymbolAddress((void**)&x,    g_x);
    cudaGetSymbolAddress((void**)&q,    g_q);
    cudaGetSymbolAddress((void**)&k,    g_k);
    cudaGetSymbolAddress((void**)&v,    g_v);
    cudaGetSymbolAddress((void**)&ctx,  g_ctx);
    cudaGetSymbolAddress((void**)&out1, g_out1);
    cudaGetSymbolAddress((void**)&h,    g_h);
    cudaGetSymbolAddress((void**)&keep, g_keep);
    cudaGetSymbolAddress((void**)&nanf, g_nanf);
    cudaGetSymbolAddress((void**)&part, g_part);
    cudaGetSymbolAddress((void**)&pctx, g_pctx);
    cudaGetSymbolAddress((void**)&pz,   g_pz);

    prep_kernel<<<B_, S_>>>(input, keep, nanf);
    build_x_kernel<<<(BS * D_) / 256, 256>>>(input, emb, keep, x);

    for (int l = 0; l < L_; ++l) {
        const float* wq_l  = wq  + l * D_ * D_;
        const float* wk_l  = wk  + l * D_ * D_;
        const float* wv_l  = wv  + l * D_ * D_;
        const float* wo_l  = wo  + l * D_ * D_;
        const float* w1_l  = ffn_w1 + l * D_ * DFF;
        const float* w2_l  = ffn_w2 + l * DFF * D_;

        qkv_kernel<<<BS / 64, 256>>>(x, wq_l, wk_l, wv_l,
                                     wq_b + l * D_, wk_b + l * D_, wv_b + l * D_,
                                     q, k, v);
        attn_kernel<<<dim3(S_ / 256, B_ * H_, NSPLIT), 128>>>(q, k, v, nanf, pctx, pz);
        attn_combine<<<QH / 256, 256>>>(pctx, pz, nanf, ctx);
        gemm_ln_kernel<<<BS / 64, 256>>>(ctx, wo_l, x,
                                         ln1_g + l * D_, ln1_b + l * D_, keep, out1, 64);
        ffn1_kernel<<<dim3(BS / 64, DFF / 64), 256>>>(out1, w1_l, h);
        gemm_ln_kernel<<<BS / 64, 256>>>(h, w2_l, out1,
                                         ln2_g + l * D_, ln2_b + l * D_, keep, x, DFF);
    }

    cls_kernel<<<BS / 64, 256>>>(x, c_w1, c_b1, c_w2, c_b2, c_w3, c_b3, part);
    reduce_y<<<1, 16>>>(part, ob, y);
}

// round 4
// speedup vs baseline: 1.4341x; 1.0261x over previous
#include <cuda_runtime.h>

#define B_  16
#define S_  1024
#define D_  64
#define H_  4
#define DFF 256
#define L_  2
#define BS  (B_ * S_)
#define KT  128
#define NSPLIT 8
#define QH  (B_ * S_ * H_)   // 65536 query-head rows

typedef unsigned long long u64;

// ------------------------- device scratch ------------------------------------
__device__ float g_x   [BS * D_];
__device__ float g_q   [BS * D_];
__device__ float g_k   [BS * D_];
__device__ float g_v   [BS * D_];
__device__ float g_ctx [BS * D_];
__device__ float g_out1[BS * D_];
__device__ float g_keep[BS];
__device__ float g_nanf[BS];
__device__ float g_part[BS / 64];
__device__ float g_pctx[NSPLIT * QH * 16];
__device__ float g_pz  [NSPLIT * QH];

// ------------------------- f32x2 helpers --------------------------------------
__device__ __forceinline__ u64 fma2(u64 a, u64 b, u64 c) {
    u64 d; asm("fma.rn.f32x2 %0, %1, %2, %3;" : "=l"(d) : "l"(a), "l"(b), "l"(c)); return d;
}
__device__ __forceinline__ u64 mul2(u64 a, u64 b) {
    u64 d; asm("mul.rn.f32x2 %0, %1, %2;" : "=l"(d) : "l"(a), "l"(b)); return d;
}
__device__ __forceinline__ u64 add2(u64 a, u64 b) {
    u64 d; asm("add.rn.f32x2 %0, %1, %2;" : "=l"(d) : "l"(a), "l"(b)); return d;
}
__device__ __forceinline__ u64 pack2(float x, float y) {
    u64 d; asm("mov.b64 %0, {%1, %2};" : "=l"(d) : "f"(x), "f"(y)); return d;
}
__device__ __forceinline__ float2 unpack2(u64 a) {
    float lo, hi; asm("mov.b64 {%0, %1}, %2;" : "=f"(lo), "=f"(hi) : "l"(a));
    return make_float2(lo, hi);
}
__device__ __forceinline__ float ex2f(float x) {
    float r; asm("ex2.approx.f32 %0, %1;" : "=f"(r) : "f"(x)); return r;
}

// ------------------------- prep: nan flags + keep ----------------------------
__global__ void prep_kernel(const float* __restrict__ in,
                            float* __restrict__ keepv, float* __restrict__ nanf) {
    int b = blockIdx.x;
    int s = threadIdx.x;            // 1024 threads
    float v = in[b * S_ + s];
    bool nan = (v != v);
    unsigned bal = __ballot_sync(0xffffffffu, nan);
    __shared__ int warp_all[32];
    __shared__ int allnan_s;
    if ((s & 31) == 0) warp_all[s >> 5] = (bal == 0xffffffffu);
    __syncthreads();
    if (s == 0) {
        int a = 1;
        #pragma unroll
        for (int i = 0; i < 32; ++i) a &= warp_all[i];
        allnan_s = a;
    }
    __syncthreads();
    float kp = (nan || allnan_s) ? 0.f : 1.f;
    keepv[b * S_ + s] = kp;
    nanf [b * S_ + s] = nan ? 1.f : 0.f;
}

// ------------------------- build x -------------------------------------------
__global__ void build_x_kernel(const float* __restrict__ in,
                               const float* __restrict__ emb,
                               const float* __restrict__ keepv,
                               float* __restrict__ x) {
    int idx = blockIdx.x * 256 + threadIdx.x;
    int d   = idx & 63;
    int row = idx >> 6;
    int s   = row & (S_ - 1);
    float kp = keepv[row];
    float val;
    const float SQF = 7.93725393319377f * 8.0f;  // sqrt(63)*sqrt(64)
    if (d < 63) {
        val = emb[s * 63 + d] * SQF;
    } else {
        float v = in[row];
        val = (v != v) ? 0.f : v;
    }
    x[idx] = val * kp;
}

// ------------------------- fused QKV GEMM (all weights preloaded) -------------
__global__ void __launch_bounds__(256) qkv_kernel(
    const float* __restrict__ x,
    const float* __restrict__ wq, const float* __restrict__ wk, const float* __restrict__ wv,
    const float* __restrict__ bq, const float* __restrict__ bk, const float* __restrict__ bv_,
    float* __restrict__ q, float* __restrict__ k, float* __restrict__ v) {
    extern __shared__ float sm[];
    float (*As)[65] = (float(*)[65])sm;                 // 4160 floats
    float (*Ws)[64] = (float(*)[64])(sm + 4160);        // 3*4096 floats
    int tid = threadIdx.x;
    int tx = tid & 15, ty = tid >> 4;
    int m0 = blockIdx.x * 64;

    for (int i = tid; i < 64 * 64; i += 256)
        As[i >> 6][i & 63] = x[(size_t)(m0 + (i >> 6)) * 64 + (i & 63)];
    for (int i = tid; i < 64 * 64; i += 256) {
        Ws[i >> 6][i & 63]            = wq[i];
        Ws[64 + (i >> 6)][i & 63]     = wk[i];
        Ws[128 + (i >> 6)][i & 63]    = wv[i];
    }
    __syncthreads();

    u64 acc[3][4][2];
    #pragma unroll
    for (int w = 0; w < 3; ++w)
        #pragma unroll
        for (int i = 0; i < 4; ++i) { acc[w][i][0] = 0ull; acc[w][i][1] = 0ull; }

    #pragma unroll
    for (int w = 0; w < 3; ++w) {
        #pragma unroll 8
        for (int kk = 0; kk < 64; ++kk) {
            ulonglong2 w2 = *(const ulonglong2*)&Ws[w * 64 + kk][tx * 4];
            #pragma unroll
            for (int i = 0; i < 4; ++i) {
                float a = As[ty * 4 + i][kk];
                u64 ap = pack2(a, a);
                acc[w][i][0] = fma2(ap, w2.x, acc[w][i][0]);
                acc[w][i][1] = fma2(ap, w2.y, acc[w][i][1]);
            }
        }
    }

    const float* bptr[3] = {bq, bk, bv_};
    float* optr[3] = {q, k, v};
    #pragma unroll
    for (int w = 0; w < 3; ++w) {
        float4 bv4 = *(const float4*)&bptr[w][tx * 4];
        #pragma unroll
        for (int i = 0; i < 4; ++i) {
            float2 p0 = unpack2(acc[w][i][0]);
            float2 p1 = unpack2(acc[w][i][1]);
            float4 o = make_float4(p0.x + bv4.x, p0.y + bv4.y, p1.x + bv4.z, p1.y + bv4.w);
            *(float4*)&optr[w][(size_t)(m0 + ty * 4 + i) * 64 + tx * 4] = o;
        }
    }
}

// ------------------------- attention partial (1 key tile per block) -----------
__global__ void __launch_bounds__(128, 5) attn_kernel(
    const float* __restrict__ q, const float* __restrict__ k,
    const float* __restrict__ v, const float* __restrict__ nanf,
    float* __restrict__ pctx, float* __restrict__ pz) {
    __shared__ __align__(16) float Kt[KT][16];
    __shared__ __align__(16) float Vt[KT][16];
    __shared__ float bias[KT];

    int tid = threadIdx.x;
    int bh = blockIdx.y;
    int b = bh >> 2, h = bh & 3;
    int q0i = blockIdx.x * 256 + tid;
    size_t r0 = (size_t)b * S_ + q0i;
    size_t r1 = r0 + 128;
    int t = blockIdx.z;                          // one tile per block
    size_t base = (size_t)b * S_ + t * KT;

    // tile loads first (overlap with q LDG latency)
    #pragma unroll
    for (int i = tid; i < KT * 4; i += 128) {
        int j = i >> 2, d4 = i & 3;
        ((float4*)Kt[j])[d4] = ((const float4*)(k + (base + j) * 64 + h * 16))[d4];
        ((float4*)Vt[j])[d4] = ((const float4*)(v + (base + j) * 64 + h * 16))[d4];
    }
    bias[tid] = (nanf[base + tid] != 0.f) ? -1e30f : 0.f;

    const float SC = 0.25f * 1.4426950408889634f;  // 1/sqrt(16) * log2(e)
    u64 qa[8], qb[8];
    {
        const float4* p = (const float4*)(q + r0 * 64 + h * 16);
        #pragma unroll
        for (int tt = 0; tt < 4; ++tt) {
            float4 f = p[tt];
            qa[2 * tt]     = pack2(f.x * SC, f.y * SC);
            qa[2 * tt + 1] = pack2(f.z * SC, f.w * SC);
        }
        p = (const float4*)(q + r1 * 64 + h * 16);
        #pragma unroll
        for (int tt = 0; tt < 4; ++tt) {
            float4 f = p[tt];
            qb[2 * tt]     = pack2(f.x * SC, f.y * SC);
            qb[2 * tt + 1] = pack2(f.z * SC, f.w * SC);
        }
    }

    u64 a0[8], a1[8];
    #pragma unroll
    for (int i = 0; i < 8; ++i) { a0[i] = 0ull; a1[i] = 0ull; }
    float Z0 = 0.f, Z1 = 0.f;

    __syncthreads();

    #pragma unroll 2
    for (int j = 0; j < KT; ++j) {
        const ulonglong2* kp = (const ulonglong2*)Kt[j];
        ulonglong2 kA = kp[0], kB = kp[1], kC = kp[2], kD = kp[3];
        u64 c0 = mul2(qa[0], kA.x); c0 = fma2(qa[1], kA.y, c0);
        c0 = fma2(qa[2], kB.x, c0); c0 = fma2(qa[3], kB.y, c0);
        u64 c1 = mul2(qa[4], kC.x); c1 = fma2(qa[5], kC.y, c1);
        c1 = fma2(qa[6], kD.x, c1); c1 = fma2(qa[7], kD.y, c1);
        u64 d0 = mul2(qb[0], kA.x); d0 = fma2(qb[1], kA.y, d0);
        d0 = fma2(qb[2], kB.x, d0); d0 = fma2(qb[3], kB.y, d0);
        u64 d1 = mul2(qb[4], kC.x); d1 = fma2(qb[5], kC.y, d1);
        d1 = fma2(qb[6], kD.x, d1); d1 = fma2(qb[7], kD.y, d1);
        float bj = bias[j];
        float2 e = unpack2(add2(c0, c1));
        float2 f = unpack2(add2(d0, d1));
        float p0 = ex2f(e.x + e.y + bj);
        float p1 = ex2f(f.x + f.y + bj);
        Z0 += p0; Z1 += p1;
        u64 pp0 = pack2(p0, p0), pp1 = pack2(p1, p1);
        const ulonglong2* vp = (const ulonglong2*)Vt[j];
        ulonglong2 vA = vp[0], vB = vp[1], vC = vp[2], vD = vp[3];
        a0[0] = fma2(pp0, vA.x, a0[0]); a0[1] = fma2(pp0, vA.y, a0[1]);
        a0[2] = fma2(pp0, vB.x, a0[2]); a0[3] = fma2(pp0, vB.y, a0[3]);
        a0[4] = fma2(pp0, vC.x, a0[4]); a0[5] = fma2(pp0, vC.y, a0[5]);
        a0[6] = fma2(pp0, vD.x, a0[6]); a0[7] = fma2(pp0, vD.y, a0[7]);
        a1[0] = fma2(pp1, vA.x, a1[0]); a1[1] = fma2(pp1, vA.y, a1[1]);
        a1[2] = fma2(pp1, vB.x, a1[2]); a1[3] = fma2(pp1, vB.y, a1[3]);
        a1[4] = fma2(pp1, vC.x, a1[4]); a1[5] = fma2(pp1, vC.y, a1[5]);
        a1[6] = fma2(pp1, vD.x, a1[6]); a1[7] = fma2(pp1, vD.y, a1[7]);
    }

    size_t pi0 = (size_t)bh * S_ + q0i;
    size_t pi1 = pi0 + 128;
    int split = t;
    float4* o0 = (float4*)(pctx + ((size_t)split * QH + pi0) * 16);
    float4* o1 = (float4*)(pctx + ((size_t)split * QH + pi1) * 16);
    #pragma unroll
    for (int tt = 0; tt < 4; ++tt) {
        float2 x0 = unpack2(a0[2 * tt]), x1 = unpack2(a0[2 * tt + 1]);
        o0[tt] = make_float4(x0.x, x0.y, x1.x, x1.y);
        float2 y0 = unpack2(a1[2 * tt]), y1 = unpack2(a1[2 * tt + 1]);
        o1[tt] = make_float4(y0.x, y0.y, y1.x, y1.y);
    }
    pz[(size_t)split * QH + pi0] = Z0;
    pz[(size_t)split * QH + pi1] = Z1;
}

// ------------------------- attention combine ----------------------------------
__global__ void __launch_bounds__(256) attn_combine(
    const float* __restrict__ pctx, const float* __restrict__ pz,
    const float* __restrict__ nanf, float* __restrict__ ctx) {
    int i = blockIdx.x * 256 + threadIdx.x;   // [0, QH)
    int bh = i >> 10, qq = i & 1023;
    int b = bh >> 2, h = bh & 3;

    float Z = 0.f;
    float4 a[4];
    #pragma unroll
    for (int t = 0; t < 4; ++t) a[t] = make_float4(0.f, 0.f, 0.f, 0.f);
    #pragma unroll
    for (int s = 0; s < NSPLIT; ++s) {
        Z += pz[(size_t)s * QH + i];
        const float4* p = (const float4*)(pctx + ((size_t)s * QH + i) * 16);
        #pragma unroll
        for (int t = 0; t < 4; ++t) {
            float4 f = p[t];
            a[t].x += f.x; a[t].y += f.y; a[t].z += f.z; a[t].w += f.w;
        }
    }
    float nq = nanf[b * S_ + qq];
    float rz = (nq == 0.f && Z > 0.f) ? (1.f / Z) : 0.f;
    float4* o = (float4*)(ctx + ((size_t)b * S_ + qq) * 64 + h * 16);
    #pragma unroll
    for (int t = 0; t < 4; ++t)
        o[t] = make_float4(a[t].x * rz, a[t].y * rz, a[t].z * rz, a[t].w * rz);
}

// ------------------------- GEMM (K=64,N=64) + residual + LN + keep ------------
__global__ void __launch_bounds__(256) gemm_ln_kernel(
    const float* __restrict__ A, const float* __restrict__ W,
    const float* __restrict__ resid,
    const float* __restrict__ g, const float* __restrict__ be,
    const float* __restrict__ keep, float* __restrict__ C) {
    __shared__ float As[64][65];
    __shared__ __align__(16) float Ws[64][64];
    int tid = threadIdx.x;
    int tx = tid & 15, ty = tid >> 4;
    int m0 = blockIdx.x * 64;

    for (int i = tid; i < 64 * 64; i += 256) {
        int r = i >> 6, c = i & 63;
        As[r][c] = A[(size_t)(m0 + r) * 64 + c];
        Ws[r][c] = W[i];
    }
    __syncthreads();

    u64 acc[4][2];
    #pragma unroll
    for (int i = 0; i < 4; ++i) { acc[i][0] = 0ull; acc[i][1] = 0ull; }
    #pragma unroll 8
    for (int kk = 0; kk < 64; ++kk) {
        ulonglong2 w2 = *(const ulonglong2*)&Ws[kk][tx * 4];
        #pragma unroll
        for (int i = 0; i < 4; ++i) {
            float a = As[ty * 4 + i][kk];
            u64 ap = pack2(a, a);
            acc[i][0] = fma2(ap, w2.x, acc[i][0]);
            acc[i][1] = fma2(ap, w2.y, acc[i][1]);
        }
    }
    __syncthreads();

    // overlay As with (gemm + resid)
    #pragma unroll
    for (int i = 0; i < 4; ++i) {
        int row = ty * 4 + i;
        float4 rv = *(const float4*)&resid[(size_t)(m0 + row) * 64 + tx * 4];
        float2 p0 = unpack2(acc[i][0]);
        float2 p1 = unpack2(acc[i][1]);
        As[row][tx * 4 + 0] = p0.x + rv.x;
        As[row][tx * 4 + 1] = p0.y + rv.y;
        As[row][tx * 4 + 2] = p1.x + rv.z;
        As[row][tx * 4 + 3] = p1.y + rv.w;
    }
    __syncthreads();

    int row = tid >> 2, part = tid & 3;
    const float* rp = &As[row][part * 16];
    float s = 0.f, ss = 0.f;
    #pragma unroll
    for (int c = 0; c < 16; ++c) { float vv = rp[c]; s += vv; ss += vv * vv; }
    s  += __shfl_xor_sync(0xffffffffu, s, 1);  s  += __shfl_xor_sync(0xffffffffu, s, 2);
    ss += __shfl_xor_sync(0xffffffffu, ss, 1); ss += __shfl_xor_sync(0xffffffffu, ss, 2);
    float mean = s * (1.f / 64.f);
    float var  = ss * (1.f / 64.f) - mean * mean;
    float inv  = rsqrtf(var + 1e-6f);
    float kp   = keep[m0 + row];
    float* op = &C[(size_t)(m0 + row) * 64 + part * 16];
    #pragma unroll
    for (int c4 = 0; c4 < 4; ++c4) {
        int c = part * 16 + c4 * 4;
        float4 o;
        o.x = ((rp[c4 * 4 + 0] - mean) * inv * g[c + 0] + be[c + 0]) * kp;
        o.y = ((rp[c4 * 4 + 1] - mean) * inv * g[c + 1] + be[c + 1]) * kp;
        o.z = ((rp[c4 * 4 + 2] - mean) * inv * g[c + 2] + be[c + 2]) * kp;
        o.w = ((rp[c4 * 4 + 3] - mean) * inv * g[c + 3] + be[c + 3]) * kp;
        *(float4*)&op[c4 * 4] = o;
    }
}

// ------------------------- fused FFN: relu(A@W1)@W2 + resid -> LN -> keep -----
__global__ void __launch_bounds__(256) ffn_kernel(
    const float* __restrict__ A, const float* __restrict__ w1,
    const float* __restrict__ w2,
    const float* __restrict__ g, const float* __restrict__ be,
    const float* __restrict__ keep, float* __restrict__ C) {
    extern __shared__ float sm[];
    float (*As)[65]  = (float(*)[65])sm;                       // 4160
    float (*W1s)[64] = (float(*)[64])(sm + 4160);              // 4096
    float (*Hs)[65]  = (float(*)[65])(sm + 4160 + 4096);       // 4160
    float (*W2s)[64] = (float(*)[64])(sm + 4160 + 4096 + 4160);// 4096
    int tid = threadIdx.x, tx = tid & 15, ty = tid >> 4;
    int m0 = blockIdx.x * 64;

    for (int i = tid; i < 64 * 64; i += 256)
        As[i >> 6][i & 63] = A[(size_t)(m0 + (i >> 6)) * 64 + (i & 63)];

    u64 facc[4][2];
    #pragma unroll
    for (int i = 0; i < 4; ++i) { facc[i][0] = 0ull; facc[i][1] = 0ull; }

    for (int nt = 0; nt < 4; ++nt) {
        __syncthreads();
        for (int i = tid; i < 64 * 64; i += 256) {
            int r = i >> 6, c = i & 63;
            W1s[r][c] = w1[(size_t)r * DFF + nt * 64 + c];
            W2s[r][c] = w2[(size_t)(nt * 64 + r) * 64 + c];
        }
        __syncthreads();

        u64 hacc[4][2];
        #pragma unroll
        for (int i = 0; i < 4; ++i) { hacc[i][0] = 0ull; hacc[i][1] = 0ull; }
        #pragma unroll 8
        for (int kk = 0; kk < 64; ++kk) {
            ulonglong2 wv = *(const ulonglong2*)&W1s[kk][tx * 4];
            #pragma unroll
            for (int i = 0; i < 4; ++i) {
                float a = As[ty * 4 + i][kk];
                u64 ap = pack2(a, a);
                hacc[i][0] = fma2(ap, wv.x, hacc[i][0]);
                hacc[i][1] = fma2(ap, wv.y, hacc[i][1]);
            }
        }
        #pragma unroll
        for (int i = 0; i < 4; ++i) {
            float2 p0 = unpack2(hacc[i][0]), p1 = unpack2(hacc[i][1]);
            Hs[ty * 4 + i][tx * 4 + 0] = fmaxf(p0.x, 0.f);
            Hs[ty * 4 + i][tx * 4 + 1] = fmaxf(p0.y, 0.f);
            Hs[ty * 4 + i][tx * 4 + 2] = fmaxf(p1.x, 0.f);
            Hs[ty * 4 + i][tx * 4 + 3] = fmaxf(p1.y, 0.f);
        }
        __syncthreads();
        #pragma unroll 8
        for (int kk = 0; kk < 64; ++kk) {
            ulonglong2 wv = *(const ulonglong2*)&W2s[kk][tx * 4];
            #pragma unroll
            for (int i = 0; i < 4; ++i) {
                float a = Hs[ty * 4 + i][kk];
                u64 ap = pack2(a, a);
                facc[i][0] = fma2(ap, wv.x, facc[i][0]);
                facc[i][1] = fma2(ap, wv.y, facc[i][1]);
            }
        }
    }

    __syncthreads();
    #pragma unroll
    for (int i = 0; i < 4; ++i) {
        int row = ty * 4 + i;
        float2 p0 = unpack2(facc[i][0]), p1 = unpack2(facc[i][1]);
        Hs[row][tx * 4 + 0] = p0.x + As[row][tx * 4 + 0];
        Hs[row][tx * 4 + 1] = p0.y + As[row][tx * 4 + 1];
        Hs[row][tx * 4 + 2] = p1.x + As[row][tx * 4 + 2];
        Hs[row][tx * 4 + 3] = p1.y + As[row][tx * 4 + 3];
    }
    __syncthreads();

    int row = tid >> 2, part = tid & 3;
    const float* rp = &Hs[row][part * 16];
    float s = 0.f, ss = 0.f;
    #pragma unroll
    for (int c = 0; c < 16; ++c) { float vv = rp[c]; s += vv; ss += vv * vv; }
    s  += __shfl_xor_sync(0xffffffffu, s, 1);  s  += __shfl_xor_sync(0xffffffffu, s, 2);
    ss += __shfl_xor_sync(0xffffffffu, ss, 1); ss += __shfl_xor_sync(0xffffffffu, ss, 2);
    float mean = s * (1.f / 64.f);
    float var  = ss * (1.f / 64.f) - mean * mean;
    float inv  = rsqrtf(var + 1e-6f);
    float kp   = keep[m0 + row];
    float* op = &C[(size_t)(m0 + row) * 64 + part * 16];
    #pragma unroll
    for (int c4 = 0; c4 < 4; ++c4) {
        int c = part * 16 + c4 * 4;
        float4 o;
        o.x = ((rp[c4 * 4 + 0] - mean) * inv * g[c + 0] + be[c + 0]) * kp;
        o.y = ((rp[c4 * 4 + 1] - mean) * inv * g[c + 1] + be[c + 1]) * kp;
        o.z = ((rp[c4 * 4 + 2] - mean) * inv * g[c + 2] + be[c + 2]) * kp;
        o.w = ((rp[c4 * 4 + 3] - mean) * inv * g[c + 3] + be[c + 3]) * kp;
        *(float4*)&op[c4 * 4] = o;
    }
}

// ------------------------- classifier fused -----------------------------------
__global__ void __launch_bounds__(256) cls_kernel(
    const float* __restrict__ x,
    const float* __restrict__ w1, const float* __restrict__ b1,
    const float* __restrict__ w2, const float* __restrict__ b2,
    const float* __restrict__ w3, const float* __restrict__ b3,
    float* __restrict__ part) {
    __shared__ float Xs[64][65];
    __shared__ __align__(16) float Ws[64][64];
    __shared__ float w3s[64];
    __shared__ float red[256];
    int tid = threadIdx.x;
    int tx = tid & 15, ty = tid >> 4;
    int m0 = blockIdx.x * 64;

    for (int i = tid; i < 64 * 64; i += 256) {
        int r = i >> 6, c = i & 63;
        Xs[r][c] = x[(size_t)(m0 + r) * 64 + c];
        Ws[r][c] = w1[i];
    }
    if (tid < 64) w3s[tid] = w3[tid];
    __syncthreads();

    u64 acc[4][2];
    #pragma unroll
    for (int i = 0; i < 4; ++i) { acc[i][0] = 0ull; acc[i][1] = 0ull; }
    #pragma unroll 8
    for (int kk = 0; kk < 64; ++kk) {
        ulonglong2 w2v = *(const ulonglong2*)&Ws[kk][tx * 4];
        #pragma unroll
        for (int i = 0; i < 4; ++i) {
            float a = Xs[ty * 4 + i][kk];
            u64 ap = pack2(a, a);
            acc[i][0] = fma2(ap, w2v.x, acc[i][0]);
            acc[i][1] = fma2(ap, w2v.y, acc[i][1]);
        }
    }
    __syncthreads();

    float4 b1v = *(const float4*)&b1[tx * 4];
    #pragma unroll
    for (int i = 0; i < 4; ++i) {
        int row = ty * 4 + i;
        float2 p0 = unpack2(acc[i][0]);
        float2 p1 = unpack2(acc[i][1]);
        Xs[row][tx * 4 + 0] = fmaxf(p0.x + b1v.x, 0.f);
        Xs[row][tx * 4 + 1] = fmaxf(p0.y + b1v.y, 0.f);
        Xs[row][tx * 4 + 2] = fmaxf(p1.x + b1v.z, 0.f);
        Xs[row][tx * 4 + 3] = fmaxf(p1.y + b1v.w, 0.f);
    }
    for (int i = tid; i < 64 * 64; i += 256) Ws[i >> 6][i & 63] = w2[i];
    __syncthreads();

    #pragma unroll
    for (int i = 0; i < 4; ++i) { acc[i][0] = 0ull; acc[i][1] = 0ull; }
    #pragma unroll 8
    for (int kk = 0; kk < 64; ++kk) {
        ulonglong2 w2v = *(const ulonglong2*)&Ws[kk][tx * 4];
        #pragma unroll
        for (int i = 0; i < 4; ++i) {
            float a = Xs[ty * 4 + i][kk];
            u64 ap = pack2(a, a);
            acc[i][0] = fma2(ap, w2v.x, acc[i][0]);
            acc[i][1] = fma2(ap, w2v.y, acc[i][1]);
        }
    }

    float4 b2v = *(const float4*)&b2[tx * 4];
    float partial = 0.f;
    #pragma unroll
    for (int i = 0; i < 4; ++i) {
        float2 p0 = unpack2(acc[i][0]);
        float2 p1 = unpack2(acc[i][1]);
        partial += fmaxf(p0.x + b2v.x, 0.f) * w3s[tx * 4 + 0];
        partial += fmaxf(p0.y + b2v.y, 0.f) * w3s[tx * 4 + 1];
        partial += fmaxf(p1.x + b2v.z, 0.f) * w3s[tx * 4 + 2];
        partial += fmaxf(p1.y + b2v.w, 0.f) * w3s[tx * 4 + 3];
    }
    red[tid] = partial;
    __syncthreads();
    for (int st = 128; st > 0; st >>= 1) {
        if (tid < st) red[tid] += red[tid + st];
        __syncthreads();
    }
    if (tid == 0) part[blockIdx.x] = red[0] + 64.f * b3[0];
}

// ------------------------- deterministic final reduction ----------------------
__global__ void reduce_y(const float* __restrict__ part,
                         const float* __restrict__ ob, float* __restrict__ y) {
    int b = threadIdx.x;   // 16
    float s = ob[0];
    #pragma unroll
    for (int i = 0; i < 16; ++i) s += part[b * 16 + i];
    y[b] = s;
}

// ------------------------- launcher ------------------------------------------
extern "C" void kernel_launch(void* const* d_in, const int* in_sizes, int n_in,
                              void* d_out, int out_size) {
    const float* input  = (const float*)d_in[0];
    const float* emb    = (const float*)d_in[1];
    const float* wq     = (const float*)d_in[2];
    const float* wq_b   = (const float*)d_in[3];
    const float* wk     = (const float*)d_in[4];
    const float* wk_b   = (const float*)d_in[5];
    const float* wv     = (const float*)d_in[6];
    const float* wv_b   = (const float*)d_in[7];
    const float* wo     = (const float*)d_in[8];
    const float* ffn_w1 = (const float*)d_in[9];
    const float* ffn_w2 = (const float*)d_in[10];
    const float* ln1_g  = (const float*)d_in[11];
    const float* ln1_b  = (const float*)d_in[12];
    const float* ln2_g  = (const float*)d_in[13];
    const float* ln2_b  = (const float*)d_in[14];
    const float* c_w1   = (const float*)d_in[15];
    const float* c_b1   = (const float*)d_in[16];
    const float* c_w2   = (const float*)d_in[17];
    const float* c_b2   = (const float*)d_in[18];
    const float* c_w3   = (const float*)d_in[19];
    const float* c_b3   = (const float*)d_in[20];
    const float* ob     = (const float*)d_in[21];
    float* y = (float*)d_out;

    float *x, *q, *k, *v, *ctx, *out1, *keep, *nanf, *part, *pctx, *pz;
    cudaGetSymbolAddress((void**)&x,    g_x);
    cudaGetSymbolAddress((void**)&q,    g_q);
    cudaGetSymbolAddress((void**)&k,    g_k);
    cudaGetSymbolAddress((void**)&v,    g_v);
    cudaGetSymbolAddress((void**)&ctx,  g_ctx);
    cudaGetSymbolAddress((void**)&out1, g_out1);
    cudaGetSymbolAddress((void**)&keep, g_keep);
    cudaGetSymbolAddress((void**)&nanf, g_nanf);
    cudaGetSymbolAddress((void**)&part, g_part);
    cudaGetSymbolAddress((void**)&pctx, g_pctx);
    cudaGetSymbolAddress((void**)&pz,   g_pz);

    const int QKV_SMEM = (4160 + 3 * 4096) * 4;        // 65792 B
    const int FFN_SMEM = (4160 + 4096 + 4160 + 4096) * 4;  // 66048 B
    cudaFuncSetAttribute(qkv_kernel, cudaFuncAttributeMaxDynamicSharedMemorySize, QKV_SMEM);
    cudaFuncSetAttribute(ffn_kernel, cudaFuncAttributeMaxDynamicSharedMemorySize, FFN_SMEM);

    prep_kernel<<<B_, S_>>>(input, keep, nanf);
    build_x_kernel<<<(BS * D_) / 256, 256>>>(input, emb, keep, x);

    for (int l = 0; l < L_; ++l) {
        const float* wq_l  = wq  + l * D_ * D_;
        const float* wk_l  = wk  + l * D_ * D_;
        const float* wv_l  = wv  + l * D_ * D_;
        const float* wo_l  = wo  + l * D_ * D_;
        const float* w1_l  = ffn_w1 + l * D_ * DFF;
        const float* w2_l  = ffn_w2 + l * DFF * D_;

        qkv_kernel<<<BS / 64, 256, QKV_SMEM>>>(x, wq_l, wk_l, wv_l,
                                     wq_b + l * D_, wk_b + l * D_, wv_b + l * D_,
                                     q, k, v);
        attn_kernel<<<dim3(S_ / 256, B_ * H_, NSPLIT), 128>>>(q, k, v, nanf, pctx, pz);
        attn_combine<<<QH / 256, 256>>>(pctx, pz, nanf, ctx);
        gemm_ln_kernel<<<BS / 64, 256>>>(ctx, wo_l, x,
                                         ln1_g + l * D_, ln1_b + l * D_, keep, out1);
        ffn_kernel<<<BS / 64, 256, FFN_SMEM>>>(out1, w1_l, w2_l,
                                               ln2_g + l * D_, ln2_b + l * D_, keep, x);
    }

    cls_kernel<<<BS / 64, 256>>>(x, c_w1, c_b1, c_w2, c_b2, c_w3, c_b3, part);
    reduce_y<<<1, 16>>>(part, ob, y);
}

// round 5
// speedup vs baseline: 2.2786x; 1.5889x over previous
#include <cuda_runtime.h>

#define B_  16
#define S_  1024
#define D_  64
#define H_  4
#define DFF 256
#define L_  2
#define BS  (B_ * S_)

typedef unsigned long long u64;
typedef unsigned int u32;
typedef unsigned short u16;

// ------------------------- device scratch ------------------------------------
__device__ float g_x   [BS * D_];
__device__ float g_q   [BS * D_];
__device__ float g_k   [BS * D_];
__device__ float g_v   [BS * D_];
__device__ float g_ctx [BS * D_];
__device__ float g_out1[BS * D_];
__device__ float g_keep[BS];
__device__ float g_nanf[BS];
__device__ float g_part[BS / 64];

// ------------------------- f32x2 / misc helpers --------------------------------
__device__ __forceinline__ u64 fma2(u64 a, u64 b, u64 c) {
    u64 d; asm("fma.rn.f32x2 %0, %1, %2, %3;" : "=l"(d) : "l"(a), "l"(b), "l"(c)); return d;
}
__device__ __forceinline__ u64 pack2(float x, float y) {
    u64 d; asm("mov.b64 %0, {%1, %2};" : "=l"(d) : "f"(x), "f"(y)); return d;
}
__device__ __forceinline__ float2 unpack2(u64 a) {
    float lo, hi; asm("mov.b64 {%0, %1}, %2;" : "=f"(lo), "=f"(hi) : "l"(a));
    return make_float2(lo, hi);
}
__device__ __forceinline__ float ex2f(float x) {
    float r; asm("ex2.approx.f32 %0, %1;" : "=f"(r) : "f"(x)); return r;
}
// pack two floats -> bf16x2 (lo = first arg)
__device__ __forceinline__ u32 bf2(float lo, float hi) {
    u32 r; asm("cvt.rn.bf16x2.f32 %0, %1, %2;" : "=r"(r) : "f"(hi), "f"(lo)); return r;
}
__device__ __forceinline__ u16 bf1(float f) {
    u16 h; asm("cvt.rn.bf16.f32 %0, %1;" : "=h"(h) : "f"(f)); return h;
}
__device__ __forceinline__ void mma_bf16(
    float& c0, float& c1, float& c2, float& c3,
    u32 a0, u32 a1, u32 a2, u32 a3, u32 b0, u32 b1) {
    asm volatile(
        "mma.sync.aligned.m16n8k16.row.col.f32.bf16.bf16.f32 "
        "{%0,%1,%2,%3},{%4,%5,%6,%7},{%8,%9},{%0,%1,%2,%3};"
        : "+f"(c0), "+f"(c1), "+f"(c2), "+f"(c3)
        : "r"(a0), "r"(a1), "r"(a2), "r"(a3), "r"(b0), "r"(b1));
}

// ------------------------- prep: nan flags + keep ----------------------------
__global__ void prep_kernel(const float* __restrict__ in,
                            float* __restrict__ keepv, float* __restrict__ nanf) {
    int b = blockIdx.x;
    int s = threadIdx.x;            // 1024 threads
    float v = in[b * S_ + s];
    bool nan = (v != v);
    unsigned bal = __ballot_sync(0xffffffffu, nan);
    __shared__ int warp_all[32];
    __shared__ int allnan_s;
    if ((s & 31) == 0) warp_all[s >> 5] = (bal == 0xffffffffu);
    __syncthreads();
    if (s == 0) {
        int a = 1;
        #pragma unroll
        for (int i = 0; i < 32; ++i) a &= warp_all[i];
        allnan_s = a;
    }
    __syncthreads();
    float kp = (nan || allnan_s) ? 0.f : 1.f;
    keepv[b * S_ + s] = kp;
    nanf [b * S_ + s] = nan ? 1.f : 0.f;
}

// ------------------------- build x -------------------------------------------
__global__ void build_x_kernel(const float* __restrict__ in,
                               const float* __restrict__ emb,
                               const float* __restrict__ keepv,
                               float* __restrict__ x) {
    int idx = blockIdx.x * 256 + threadIdx.x;
    int d   = idx & 63;
    int row = idx >> 6;
    int s   = row & (S_ - 1);
    float kp = keepv[row];
    float val;
    const float SQF = 7.93725393319377f * 8.0f;  // sqrt(63)*sqrt(64)
    if (d < 63) {
        val = emb[s * 63 + d] * SQF;
    } else {
        float v = in[row];
        val = (v != v) ? 0.f : v;
    }
    x[idx] = val * kp;
}

// ------------------------- fused QKV GEMM (all weights preloaded) -------------
__global__ void __launch_bounds__(256) qkv_kernel(
    const float* __restrict__ x,
    const float* __restrict__ wq, const float* __restrict__ wk, const float* __restrict__ wv,
    const float* __restrict__ bq, const float* __restrict__ bk, const float* __restrict__ bv_,
    float* __restrict__ q, float* __restrict__ k, float* __restrict__ v) {
    extern __shared__ float sm[];
    float (*As)[65] = (float(*)[65])sm;                 // 4160 floats
    float (*Ws)[64] = (float(*)[64])(sm + 4160);        // 3*4096 floats
    int tid = threadIdx.x;
    int tx = tid & 15, ty = tid >> 4;
    int m0 = blockIdx.x * 64;

    for (int i = tid; i < 64 * 64; i += 256)
        As[i >> 6][i & 63] = x[(size_t)(m0 + (i >> 6)) * 64 + (i & 63)];
    for (int i = tid; i < 64 * 64; i += 256) {
        Ws[i >> 6][i & 63]            = wq[i];
        Ws[64 + (i >> 6)][i & 63]     = wk[i];
        Ws[128 + (i >> 6)][i & 63]    = wv[i];
    }
    __syncthreads();

    u64 acc[3][4][2];
    #pragma unroll
    for (int w = 0; w < 3; ++w)
        #pragma unroll
        for (int i = 0; i < 4; ++i) { acc[w][i][0] = 0ull; acc[w][i][1] = 0ull; }

    #pragma unroll
    for (int w = 0; w < 3; ++w) {
        #pragma unroll 8
        for (int kk = 0; kk < 64; ++kk) {
            ulonglong2 w2 = *(const ulonglong2*)&Ws[w * 64 + kk][tx * 4];
            #pragma unroll
            for (int i = 0; i < 4; ++i) {
                float a = As[ty * 4 + i][kk];
                u64 ap = pack2(a, a);
                acc[w][i][0] = fma2(ap, w2.x, acc[w][i][0]);
                acc[w][i][1] = fma2(ap, w2.y, acc[w][i][1]);
            }
        }
    }

    const float* bptr[3] = {bq, bk, bv_};
    float* optr[3] = {q, k, v};
    #pragma unroll
    for (int w = 0; w < 3; ++w) {
        float4 bv4 = *(const float4*)&bptr[w][tx * 4];
        #pragma unroll
        for (int i = 0; i < 4; ++i) {
            float2 p0 = unpack2(acc[w][i][0]);
            float2 p1 = unpack2(acc[w][i][1]);
            float4 o = make_float4(p0.x + bv4.x, p0.y + bv4.y, p1.x + bv4.z, p1.y + bv4.w);
            *(float4*)&optr[w][(size_t)(m0 + ty * 4 + i) * 64 + tx * 4] = o;
        }
    }
}

// ------------------------- tensor-core flash attention -------------------------
// Block: 256 threads = 8 warps. Each warp owns 16 queries; block owns 128.
// Streams all 1024 keys in 64-key smem chunks. bf16 mma, fp32 accum.
#define KCHUNK 64
__global__ void __launch_bounds__(256) attn_mma_kernel(
    const float* __restrict__ q, const float* __restrict__ k,
    const float* __restrict__ v, const float* __restrict__ nanf,
    float* __restrict__ ctx) {
    __shared__ __align__(16) u16 Qs[128 * 16];      // [query][dim] bf16
    __shared__ __align__(16) u16 Ks[KCHUNK * 18];   // [key][dim] bf16, padded stride 18
    __shared__ __align__(16) u16 Vt[16 * 66];       // [dim][key] bf16, padded stride 66
    __shared__ float bias[KCHUNK];
    __shared__ float rkeep[128];

    int tid = threadIdx.x;
    int w   = tid >> 5;
    int lane = tid & 31;
    int gid = lane >> 2;        // 0..7 (row group)
    int tig = lane & 3;         // 0..3
    int bh = blockIdx.y;
    int b = bh >> 2, h = bh & 3;
    int qbase = blockIdx.x * 128;
    size_t bS = (size_t)b * S_;

    const float SC = 0.25f * 1.4426950408889634f;  // 1/sqrt(16) * log2(e)

    // ---- load Q tile (128 x 16), scale, convert to bf16 ----
    #pragma unroll
    for (int it = 0; it < 2; ++it) {
        int idx = tid + it * 256;           // 0..511
        int qq = idx >> 2, d4 = idx & 3;
        float4 f = *(const float4*)(q + (bS + qbase + qq) * 64 + h * 16 + d4 * 4);
        u32 r0 = bf2(f.x * SC, f.y * SC);
        u32 r1 = bf2(f.z * SC, f.w * SC);
        *(u32*)((char*)Qs + qq * 32 + d4 * 8)     = r0;
        *(u32*)((char*)Qs + qq * 32 + d4 * 8 + 4) = r1;
    }
    if (tid < 128) rkeep[tid] = (nanf[bS + qbase + tid] == 0.f) ? 1.f : 0.f;
    __syncthreads();

    // ---- Q fragment (constant across all keys) ----
    u32 qa0 = *(const u32*)((char*)Qs + (w * 16 + gid) * 32 + tig * 4);
    u32 qa1 = *(const u32*)((char*)Qs + (w * 16 + gid + 8) * 32 + tig * 4);
    u32 qa2 = *(const u32*)((char*)Qs + (w * 16 + gid) * 32 + tig * 4 + 16);
    u32 qa3 = *(const u32*)((char*)Qs + (w * 16 + gid + 8) * 32 + tig * 4 + 16);

    float z0 = 0.f, z1 = 0.f;
    float cd0[4] = {0.f, 0.f, 0.f, 0.f};   // ctx dims 0-7
    float cd1[4] = {0.f, 0.f, 0.f, 0.f};   // ctx dims 8-15

    for (int ch = 0; ch < S_ / KCHUNK; ++ch) {
        __syncthreads();
        int kg = ch * KCHUNK;
        {   // load K (convert) and V (convert + transpose)
            int key = tid >> 2, d4 = tid & 3;
            float4 kf = *(const float4*)(k + (bS + kg + key) * 64 + h * 16 + d4 * 4);
            *(u32*)((char*)Ks + key * 36 + d4 * 8)     = bf2(kf.x, kf.y);
            *(u32*)((char*)Ks + key * 36 + d4 * 8 + 4) = bf2(kf.z, kf.w);
            float4 vf = *(const float4*)(v + (bS + kg + key) * 64 + h * 16 + d4 * 4);
            Vt[(d4 * 4 + 0) * 66 + key] = bf1(vf.x);
            Vt[(d4 * 4 + 1) * 66 + key] = bf1(vf.y);
            Vt[(d4 * 4 + 2) * 66 + key] = bf1(vf.z);
            Vt[(d4 * 4 + 3) * 66 + key] = bf1(vf.w);
            if (tid < KCHUNK) bias[tid] = (nanf[bS + kg + tid] != 0.f) ? -1e30f : 0.f;
        }
        __syncthreads();

        #pragma unroll
        for (int kb = 0; kb < KCHUNK; kb += 16) {
            // ---- QK^T: two n-tiles of 8 keys ----
            u32 b0, b1;
            float c0 = 0.f, c1 = 0.f, c2 = 0.f, c3 = 0.f;
            b0 = *(const u32*)((char*)Ks + (kb + gid) * 36 + tig * 4);
            b1 = *(const u32*)((char*)Ks + (kb + gid) * 36 + tig * 4 + 16);
            mma_bf16(c0, c1, c2, c3, qa0, qa1, qa2, qa3, b0, b1);
            float d0 = 0.f, d1 = 0.f, d2 = 0.f, d3 = 0.f;
            b0 = *(const u32*)((char*)Ks + (kb + 8 + gid) * 36 + tig * 4);
            b1 = *(const u32*)((char*)Ks + (kb + 8 + gid) * 36 + tig * 4 + 16);
            mma_bf16(d0, d1, d2, d3, qa0, qa1, qa2, qa3, b0, b1);

            // ---- softmax numerators ----
            float2 bv0 = *(const float2*)(bias + kb + 2 * tig);
            float2 bv1 = *(const float2*)(bias + kb + 8 + 2 * tig);
            float p0 = ex2f(c0 + bv0.x), p1 = ex2f(c1 + bv0.y);
            float p2 = ex2f(c2 + bv0.x), p3 = ex2f(c3 + bv0.y);
            float p4 = ex2f(d0 + bv1.x), p5 = ex2f(d1 + bv1.y);
            float p6 = ex2f(d2 + bv1.x), p7 = ex2f(d3 + bv1.y);
            z0 += (p0 + p1) + (p4 + p5);
            z1 += (p2 + p3) + (p6 + p7);

            // ---- P fragment (16q x 16k) ----
            u32 pa0 = bf2(p0, p1);
            u32 pa1 = bf2(p2, p3);
            u32 pa2 = bf2(p4, p5);
            u32 pa3 = bf2(p6, p7);

            // ---- PV: two n-tiles of 8 dims ----
            u32 vb0 = *(const u32*)((char*)Vt + (gid * 66 + kb + 2 * tig) * 2);
            u32 vb1 = *(const u32*)((char*)Vt + (gid * 66 + kb + 8 + 2 * tig) * 2);
            mma_bf16(cd0[0], cd0[1], cd0[2], cd0[3], pa0, pa1, pa2, pa3, vb0, vb1);
            vb0 = *(const u32*)((char*)Vt + ((gid + 8) * 66 + kb + 2 * tig) * 2);
            vb1 = *(const u32*)((char*)Vt + ((gid + 8) * 66 + kb + 8 + 2 * tig) * 2);
            mma_bf16(cd1[0], cd1[1], cd1[2], cd1[3], pa0, pa1, pa2, pa3, vb0, vb1);
        }
    }

    // ---- reduce Z across the 4 lanes of each row group ----
    z0 += __shfl_xor_sync(0xffffffffu, z0, 1);
    z0 += __shfl_xor_sync(0xffffffffu, z0, 2);
    z1 += __shfl_xor_sync(0xffffffffu, z1, 1);
    z1 += __shfl_xor_sync(0xffffffffu, z1, 2);

    int q0 = w * 16 + gid;
    int q1 = q0 + 8;
    float rk0 = rkeep[q0], rk1 = rkeep[q1];
    float rz0 = (rk0 != 0.f && z0 > 0.f) ? (1.f / z0) : 0.f;
    float rz1 = (rk1 != 0.f && z1 > 0.f) ? (1.f / z1) : 0.f;

    float* o0 = ctx + (bS + qbase + q0) * 64 + h * 16;
    float* o1 = ctx + (bS + qbase + q1) * 64 + h * 16;
    *(float2*)(o0 + 2 * tig)     = make_float2(cd0[0] * rz0, cd0[1] * rz0);
    *(float2*)(o0 + 8 + 2 * tig) = make_float2(cd1[0] * rz0, cd1[1] * rz0);
    *(float2*)(o1 + 2 * tig)     = make_float2(cd0[2] * rz1, cd0[3] * rz1);
    *(float2*)(o1 + 8 + 2 * tig) = make_float2(cd1[2] * rz1, cd1[3] * rz1);
}

// ------------------------- GEMM (K=64,N=64) + residual + LN + keep ------------
__global__ void __launch_bounds__(256) gemm_ln_kernel(
    const float* __restrict__ A, const float* __restrict__ W,
    const float* __restrict__ resid,
    const float* __restrict__ g, const float* __restrict__ be,
    const float* __restrict__ keep, float* __restrict__ C) {
    __shared__ float As[64][65];
    __shared__ __align__(16) float Ws[64][64];
    int tid = threadIdx.x;
    int tx = tid & 15, ty = tid >> 4;
    int m0 = blockIdx.x * 64;

    for (int i = tid; i < 64 * 64; i += 256) {
        int r = i >> 6, c = i & 63;
        As[r][c] = A[(size_t)(m0 + r) * 64 + c];
        Ws[r][c] = W[i];
    }
    __syncthreads();

    u64 acc[4][2];
    #pragma unroll
    for (int i = 0; i < 4; ++i) { acc[i][0] = 0ull; acc[i][1] = 0ull; }
    #pragma unroll 8
    for (int kk = 0; kk < 64; ++kk) {
        ulonglong2 w2 = *(const ulonglong2*)&Ws[kk][tx * 4];
        #pragma unroll
        for (int i = 0; i < 4; ++i) {
            float a = As[ty * 4 + i][kk];
            u64 ap = pack2(a, a);
            acc[i][0] = fma2(ap, w2.x, acc[i][0]);
            acc[i][1] = fma2(ap, w2.y, acc[i][1]);
        }
    }
    __syncthreads();

    #pragma unroll
    for (int i = 0; i < 4; ++i) {
        int row = ty * 4 + i;
        float4 rv = *(const float4*)&resid[(size_t)(m0 + row) * 64 + tx * 4];
        float2 p0 = unpack2(acc[i][0]);
        float2 p1 = unpack2(acc[i][1]);
        As[row][tx * 4 + 0] = p0.x + rv.x;
        As[row][tx * 4 + 1] = p0.y + rv.y;
        As[row][tx * 4 + 2] = p1.x + rv.z;
        As[row][tx * 4 + 3] = p1.y + rv.w;
    }
    __syncthreads();

    int row = tid >> 2, part = tid & 3;
    const float* rp = &As[row][part * 16];
    float s = 0.f, ss = 0.f;
    #pragma unroll
    for (int c = 0; c < 16; ++c) { float vv = rp[c]; s += vv; ss += vv * vv; }
    s  += __shfl_xor_sync(0xffffffffu, s, 1);  s  += __shfl_xor_sync(0xffffffffu, s, 2);
    ss += __shfl_xor_sync(0xffffffffu, ss, 1); ss += __shfl_xor_sync(0xffffffffu, ss, 2);
    float mean = s * (1.f / 64.f);
    float var  = ss * (1.f / 64.f) - mean * mean;
    float inv  = rsqrtf(var + 1e-6f);
    float kp   = keep[m0 + row];
    float* op = &C[(size_t)(m0 + row) * 64 + part * 16];
    #pragma unroll
    for (int c4 = 0; c4 < 4; ++c4) {
        int c = part * 16 + c4 * 4;
        float4 o;
        o.x = ((rp[c4 * 4 + 0] - mean) * inv * g[c + 0] + be[c + 0]) * kp;
        o.y = ((rp[c4 * 4 + 1] - mean) * inv * g[c + 1] + be[c + 1]) * kp;
        o.z = ((rp[c4 * 4 + 2] - mean) * inv * g[c + 2] + be[c + 2]) * kp;
        o.w = ((rp[c4 * 4 + 3] - mean) * inv * g[c + 3] + be[c + 3]) * kp;
        *(float4*)&op[c4 * 4] = o;
    }
}

// ------------------------- fused FFN: relu(A@W1)@W2 + resid -> LN -> keep -----
__global__ void __launch_bounds__(256) ffn_kernel(
    const float* __restrict__ A, const float* __restrict__ w1,
    const float* __restrict__ w2,
    const float* __restrict__ g, const float* __restrict__ be,
    const float* __restrict__ keep, float* __restrict__ C) {
    extern __shared__ float sm[];
    float (*As)[65]  = (float(*)[65])sm;                       // 4160
    float (*W1s)[64] = (float(*)[64])(sm + 4160);              // 4096
    float (*Hs)[65]  = (float(*)[65])(sm + 4160 + 4096);       // 4160
    float (*W2s)[64] = (float(*)[64])(sm + 4160 + 4096 + 4160);// 4096
    int tid = threadIdx.x, tx = tid & 15, ty = tid >> 4;
    int m0 = blockIdx.x * 64;

    for (int i = tid; i < 64 * 64; i += 256)
        As[i >> 6][i & 63] = A[(size_t)(m0 + (i >> 6)) * 64 + (i & 63)];

    u64 facc[4][2];
    #pragma unroll
    for (int i = 0; i < 4; ++i) { facc[i][0] = 0ull; facc[i][1] = 0ull; }

    for (int nt = 0; nt < 4; ++nt) {
        __syncthreads();
        for (int i = tid; i < 64 * 64; i += 256) {
            int r = i >> 6, c = i & 63;
            W1s[r][c] = w1[(size_t)r * DFF + nt * 64 + c];
            W2s[r][c] = w2[(size_t)(nt * 64 + r) * 64 + c];
        }
        __syncthreads();

        u64 hacc[4][2];
        #pragma unroll
        for (int i = 0; i < 4; ++i) { hacc[i][0] = 0ull; hacc[i][1] = 0ull; }
        #pragma unroll 8
        for (int kk = 0; kk < 64; ++kk) {
            ulonglong2 wv = *(const ulonglong2*)&W1s[kk][tx * 4];
            #pragma unroll
            for (int i = 0; i < 4; ++i) {
                float a = As[ty * 4 + i][kk];
                u64 ap = pack2(a, a);
                hacc[i][0] = fma2(ap, wv.x, hacc[i][0]);
                hacc[i][1] = fma2(ap, wv.y, hacc[i][1]);
            }
        }
        #pragma unroll
        for (int i = 0; i < 4; ++i) {
            float2 p0 = unpack2(hacc[i][0]), p1 = unpack2(hacc[i][1]);
            Hs[ty * 4 + i][tx * 4 + 0] = fmaxf(p0.x, 0.f);
            Hs[ty * 4 + i][tx * 4 + 1] = fmaxf(p0.y, 0.f);
            Hs[ty * 4 + i][tx * 4 + 2] = fmaxf(p1.x, 0.f);
            Hs[ty * 4 + i][tx * 4 + 3] = fmaxf(p1.y, 0.f);
        }
        __syncthreads();
        #pragma unroll 8
        for (int kk = 0; kk < 64; ++kk) {
            ulonglong2 wv = *(const ulonglong2*)&W2s[kk][tx * 4];
            #pragma unroll
            for (int i = 0; i < 4; ++i) {
                float a = Hs[ty * 4 + i][kk];
                u64 ap = pack2(a, a);
                facc[i][0] = fma2(ap, wv.x, facc[i][0]);
                facc[i][1] = fma2(ap, wv.y, facc[i][1]);
            }
        }
    }

    __syncthreads();
    #pragma unroll
    for (int i = 0; i < 4; ++i) {
        int row = ty * 4 + i;
        float2 p0 = unpack2(facc[i][0]), p1 = unpack2(facc[i][1]);
        Hs[row][tx * 4 + 0] = p0.x + As[row][tx * 4 + 0];
        Hs[row][tx * 4 + 1] = p0.y + As[row][tx * 4 + 1];
        Hs[row][tx * 4 + 2] = p1.x + As[row][tx * 4 + 2];
        Hs[row][tx * 4 + 3] = p1.y + As[row][tx * 4 + 3];
    }
    __syncthreads();

    int row = tid >> 2, part = tid & 3;
    const float* rp = &Hs[row][part * 16];
    float s = 0.f, ss = 0.f;
    #pragma unroll
    for (int c = 0; c < 16; ++c) { float vv = rp[c]; s += vv; ss += vv * vv; }
    s  += __shfl_xor_sync(0xffffffffu, s, 1);  s  += __shfl_xor_sync(0xffffffffu, s, 2);
    ss += __shfl_xor_sync(0xffffffffu, ss, 1); ss += __shfl_xor_sync(0xffffffffu, ss, 2);
    float mean = s * (1.f / 64.f);
    float var  = ss * (1.f / 64.f) - mean * mean;
    float inv  = rsqrtf(var + 1e-6f);
    float kp   = keep[m0 + row];
    float* op = &C[(size_t)(m0 + row) * 64 + part * 16];
    #pragma unroll
    for (int c4 = 0; c4 < 4; ++c4) {
        int c = part * 16 + c4 * 4;
        float4 o;
        o.x = ((rp[c4 * 4 + 0] - mean) * inv * g[c + 0] + be[c + 0]) * kp;
        o.y = ((rp[c4 * 4 + 1] - mean) * inv * g[c + 1] + be[c + 1]) * kp;
        o.z = ((rp[c4 * 4 + 2] - mean) * inv * g[c + 2] + be[c + 2]) * kp;
        o.w = ((rp[c4 * 4 + 3] - mean) * inv * g[c + 3] + be[c + 3]) * kp;
        *(float4*)&op[c4 * 4] = o;
    }
}

// ------------------------- classifier fused -----------------------------------
__global__ void __launch_bounds__(256) cls_kernel(
    const float* __restrict__ x,
    const float* __restrict__ w1, const float* __restrict__ b1,
    const float* __restrict__ w2, const float* __restrict__ b2,
    const float* __restrict__ w3, const float* __restrict__ b3,
    float* __restrict__ part) {
    __shared__ float Xs[64][65];
    __shared__ __align__(16) float Ws[64][64];
    __shared__ float w3s[64];
    __shared__ float red[256];
    int tid = threadIdx.x;
    int tx = tid & 15, ty = tid >> 4;
    int m0 = blockIdx.x * 64;

    for (int i = tid; i < 64 * 64; i += 256) {
        int r = i >> 6, c = i & 63;
        Xs[r][c] = x[(size_t)(m0 + r) * 64 + c];
        Ws[r][c] = w1[i];
    }
    if (tid < 64) w3s[tid] = w3[tid];
    __syncthreads();

    u64 acc[4][2];
    #pragma unroll
    for (int i = 0; i < 4; ++i) { acc[i][0] = 0ull; acc[i][1] = 0ull; }
    #pragma unroll 8
    for (int kk = 0; kk < 64; ++kk) {
        ulonglong2 w2v = *(const ulonglong2*)&Ws[kk][tx * 4];
        #pragma unroll
        for (int i = 0; i < 4; ++i) {
            float a = Xs[ty * 4 + i][kk];
            u64 ap = pack2(a, a);
            acc[i][0] = fma2(ap, w2v.x, acc[i][0]);
            acc[i][1] = fma2(ap, w2v.y, acc[i][1]);
        }
    }
    __syncthreads();

    float4 b1v = *(const float4*)&b1[tx * 4];
    #pragma unroll
    for (int i = 0; i < 4; ++i) {
        int row = ty * 4 + i;
        float2 p0 = unpack2(acc[i][0]);
        float2 p1 = unpack2(acc[i][1]);
        Xs[row][tx * 4 + 0] = fmaxf(p0.x + b1v.x, 0.f);
        Xs[row][tx * 4 + 1] = fmaxf(p0.y + b1v.y, 0.f);
        Xs[row][tx * 4 + 2] = fmaxf(p1.x + b1v.z, 0.f);
        Xs[row][tx * 4 + 3] = fmaxf(p1.y + b1v.w, 0.f);
    }
    for (int i = tid; i < 64 * 64; i += 256) Ws[i >> 6][i & 63] = w2[i];
    __syncthreads();

    #pragma unroll
    for (int i = 0; i < 4; ++i) { acc[i][0] = 0ull; acc[i][1] = 0ull; }
    #pragma unroll 8
    for (int kk = 0; kk < 64; ++kk) {
        ulonglong2 w2v = *(const ulonglong2*)&Ws[kk][tx * 4];
        #pragma unroll
        for (int i = 0; i < 4; ++i) {
            float a = Xs[ty * 4 + i][kk];
            u64 ap = pack2(a, a);
            acc[i][0] = fma2(ap, w2v.x, acc[i][0]);
            acc[i][1] = fma2(ap, w2v.y, acc[i][1]);
        }
    }

    float4 b2v = *(const float4*)&b2[tx * 4];
    float partial = 0.f;
    #pragma unroll
    for (int i = 0; i < 4; ++i) {
        float2 p0 = unpack2(acc[i][0]);
        float2 p1 = unpack2(acc[i][1]);
        partial += fmaxf(p0.x + b2v.x, 0.f) * w3s[tx * 4 + 0];
        partial += fmaxf(p0.y + b2v.y, 0.f) * w3s[tx * 4 + 1];
        partial += fmaxf(p1.x + b2v.z, 0.f) * w3s[tx * 4 + 2];
        partial += fmaxf(p1.y + b2v.w, 0.f) * w3s[tx * 4 + 3];
    }
    red[tid] = partial;
    __syncthreads();
    for (int st = 128; st > 0; st >>= 1) {
        if (tid < st) red[tid] += red[tid + st];
        __syncthreads();
    }
    if (tid == 0) part[blockIdx.x] = red[0] + 64.f * b3[0];
}

// ------------------------- deterministic final reduction ----------------------
__global__ void reduce_y(const float* __restrict__ part,
                         const float* __restrict__ ob, float* __restrict__ y) {
    int b = threadIdx.x;   // 16
    float s = ob[0];
    #pragma unroll
    for (int i = 0; i < 16; ++i) s += part[b * 16 + i];
    y[b] = s;
}

// ------------------------- launcher ------------------------------------------
extern "C" void kernel_launch(void* const* d_in, const int* in_sizes, int n_in,
                              void* d_out, int out_size) {
    const float* input  = (const float*)d_in[0];
    const float* emb    = (const float*)d_in[1];
    const float* wq     = (const float*)d_in[2];
    const float* wq_b   = (const float*)d_in[3];
    const float* wk     = (const float*)d_in[4];
    const float* wk_b   = (const float*)d_in[5];
    const float* wv     = (const float*)d_in[6];
    const float* wv_b   = (const float*)d_in[7];
    const float* wo     = (const float*)d_in[8];
    const float* ffn_w1 = (const float*)d_in[9];
    const float* ffn_w2 = (const float*)d_in[10];
    const float* ln1_g  = (const float*)d_in[11];
    const float* ln1_b  = (const float*)d_in[12];
    const float* ln2_g  = (const float*)d_in[13];
    const float* ln2_b  = (const float*)d_in[14];
    const float* c_w1   = (const float*)d_in[15];
    const float* c_b1   = (const float*)d_in[16];
    const float* c_w2   = (const float*)d_in[17];
    const float* c_b2   = (const float*)d_in[18];
    const float* c_w3   = (const float*)d_in[19];
    const float* c_b3   = (const float*)d_in[20];
    const float* ob     = (const float*)d_in[21];
    float* y = (float*)d_out;

    float *x, *q, *k, *v, *ctx, *out1, *keep, *nanf, *part;
    cudaGetSymbolAddress((void**)&x,    g_x);
    cudaGetSymbolAddress((void**)&q,    g_q);
    cudaGetSymbolAddress((void**)&k,    g_k);
    cudaGetSymbolAddress((void**)&v,    g_v);
    cudaGetSymbolAddress((void**)&ctx,  g_ctx);
    cudaGetSymbolAddress((void**)&out1, g_out1);
    cudaGetSymbolAddress((void**)&keep, g_keep);
    cudaGetSymbolAddress((void**)&nanf, g_nanf);
    cudaGetSymbolAddress((void**)&part, g_part);

    const int QKV_SMEM = (4160 + 3 * 4096) * 4;            // 65792 B
    const int FFN_SMEM = (4160 + 4096 + 4160 + 4096) * 4;  // 66048 B
    cudaFuncSetAttribute(qkv_kernel, cudaFuncAttributeMaxDynamicSharedMemorySize, QKV_SMEM);
    cudaFuncSetAttribute(ffn_kernel, cudaFuncAttributeMaxDynamicSharedMemorySize, FFN_SMEM);

    prep_kernel<<<B_, S_>>>(input, keep, nanf);
    build_x_kernel<<<(BS * D_) / 256, 256>>>(input, emb, keep, x);

    for (int l = 0; l < L_; ++l) {
        const float* wq_l  = wq  + l * D_ * D_;
        const float* wk_l  = wk  + l * D_ * D_;
        const float* wv_l  = wv  + l * D_ * D_;
        const float* wo_l  = wo  + l * D_ * D_;
        const float* w1_l  = ffn_w1 + l * D_ * DFF;
        const float* w2_l  = ffn_w2 + l * DFF * D_;

        qkv_kernel<<<BS / 64, 256, QKV_SMEM>>>(x, wq_l, wk_l, wv_l,
                                     wq_b + l * D_, wk_b + l * D_, wv_b + l * D_,
                                     q, k, v);
        attn_mma_kernel<<<dim3(S_ / 128, B_ * H_), 256>>>(q, k, v, nanf, ctx);
        gemm_ln_kernel<<<BS / 64, 256>>>(ctx, wo_l, x,
                                         ln1_g + l * D_, ln1_b + l * D_, keep, out1);
        ffn_kernel<<<BS / 64, 256, FFN_SMEM>>>(out1, w1_l, w2_l,
                                               ln2_g + l * D_, ln2_b + l * D_, keep, x);
    }

    cls_kernel<<<BS / 64, 256>>>(x, c_w1, c_b1, c_w2, c_b2, c_w3, c_b3, part);
    reduce_y<<<1, 16>>>(part, ob, y);
}

// round 6
// speedup vs baseline: 2.8202x; 1.2377x over previous
#include <cuda_runtime.h>

#define B_  16
#define S_  1024
#define D_  64
#define H_  4
#define DFF 256
#define L_  2
#define BS  (B_ * S_)

typedef unsigned long long u64;
typedef unsigned int u32;
typedef unsigned short u16;

// ------------------------- device scratch ------------------------------------
__device__ float g_x   [BS * D_];
__device__ float g_q   [BS * D_];
__device__ float g_k   [BS * D_];
__device__ float g_v   [BS * D_];
__device__ float g_ctx [BS * D_];
__device__ float g_out1[BS * D_];
__device__ float g_keep[BS];
__device__ float g_nanf[BS];
__device__ float g_part[BS / 64];
__device__ u16   g_ws  [L_ * 4 * 4 * 64 * 72];   // split ffn weights, frag layout
__device__ u16   g_o1h [BS * 72];                // out1 bf16-hi, frag layout
__device__ u16   g_o1l [BS * 72];                // out1 bf16-lo

// ------------------------- helpers --------------------------------------------
__device__ __forceinline__ u64 fma2(u64 a, u64 b, u64 c) {
    u64 d; asm("fma.rn.f32x2 %0, %1, %2, %3;" : "=l"(d) : "l"(a), "l"(b), "l"(c)); return d;
}
__device__ __forceinline__ u64 pack2(float x, float y) {
    u64 d; asm("mov.b64 %0, {%1, %2};" : "=l"(d) : "f"(x), "f"(y)); return d;
}
__device__ __forceinline__ float2 unpack2(u64 a) {
    float lo, hi; asm("mov.b64 {%0, %1}, %2;" : "=f"(lo), "=f"(hi) : "l"(a));
    return make_float2(lo, hi);
}
__device__ __forceinline__ float ex2f(float x) {
    float r; asm("ex2.approx.f32 %0, %1;" : "=f"(r) : "f"(x)); return r;
}
// pack two floats -> bf16x2 (low half = first arg)
__device__ __forceinline__ u32 bf2(float lo, float hi) {
    u32 r; asm("cvt.rn.bf16x2.f32 %0, %1, %2;" : "=r"(r) : "f"(hi), "f"(lo)); return r;
}
__device__ __forceinline__ u16 bf1(float f) {
    u16 h; asm("cvt.rn.bf16.f32 %0, %1;" : "=h"(h) : "f"(f)); return h;
}
__device__ __forceinline__ float bf16f(u16 h) { return __uint_as_float((u32)h << 16); }
__device__ __forceinline__ void mma_bf16(
    float& c0, float& c1, float& c2, float& c3,
    u32 a0, u32 a1, u32 a2, u32 a3, u32 b0, u32 b1) {
    asm volatile(
        "mma.sync.aligned.m16n8k16.row.col.f32.bf16.bf16.f32 "
        "{%0,%1,%2,%3},{%4,%5,%6,%7},{%8,%9},{%0,%1,%2,%3};"
        : "+f"(c0), "+f"(c1), "+f"(c2), "+f"(c3)
        : "r"(a0), "r"(a1), "r"(a2), "r"(a3), "r"(b0), "r"(b1));
}
// permuted k-position inside a 16-group: pairs ordered (0,8,1,9,2,10,3,11)*2
__device__ __forceinline__ int permpos(int j) {   // j in 0..15
    int p = j >> 1, l = j & 1;
    return (p & 3) * 4 + ((p >> 2) << 1) + l;
}

// ------------------------- prep: nan flags + keep ----------------------------
__global__ void prep_kernel(const float* __restrict__ in,
                            float* __restrict__ keepv, float* __restrict__ nanf) {
    int b = blockIdx.x;
    int s = threadIdx.x;            // 1024 threads
    float v = in[b * S_ + s];
    bool nan = (v != v);
    unsigned bal = __ballot_sync(0xffffffffu, nan);
    __shared__ int warp_all[32];
    __shared__ int allnan_s;
    if ((s & 31) == 0) warp_all[s >> 5] = (bal == 0xffffffffu);
    __syncthreads();
    if (s == 0) {
        int a = 1;
        #pragma unroll
        for (int i = 0; i < 32; ++i) a &= warp_all[i];
        allnan_s = a;
    }
    __syncthreads();
    float kp = (nan || allnan_s) ? 0.f : 1.f;
    keepv[b * S_ + s] = kp;
    nanf [b * S_ + s] = nan ? 1.f : 0.f;
}

// ------------------------- build x -------------------------------------------
__global__ void build_x_kernel(const float* __restrict__ in,
                               const float* __restrict__ emb,
                               const float* __restrict__ keepv,
                               float* __restrict__ x) {
    int idx = blockIdx.x * 256 + threadIdx.x;
    int d   = idx & 63;
    int row = idx >> 6;
    int s   = row & (S_ - 1);
    float kp = keepv[row];
    float val;
    const float SQF = 7.93725393319377f * 8.0f;  // sqrt(63)*sqrt(64)
    if (d < 63) {
        val = emb[s * 63 + d] * SQF;
    } else {
        float v = in[row];
        val = (v != v) ? 0.f : v;
    }
    x[idx] = val * kp;
}

// ------------------------- split ffn weights into frag layout ------------------
// region per (l,nt): [W1h | W1l | W2h | W2l], each [n=64][72] u16
__global__ void wprep_kernel(const float* __restrict__ w1, const float* __restrict__ w2,
                             u16* __restrict__ ws) {
    int l = blockIdx.x >> 2, nt = blockIdx.x & 3;
    u16* dst = ws + (size_t)(l * 4 + nt) * (4 * 64 * 72);
    int tid = threadIdx.x;
    for (int i = tid; i < 4096; i += 256) {
        int k = i >> 6, n = i & 63;
        int pos = (k >> 4) * 16 + permpos(k & 15);
        float wa = w1[(size_t)l * 64 * 256 + k * 256 + nt * 64 + n];
        u16 h = bf1(wa);
        dst[0 * 64 * 72 + n * 72 + pos] = h;
        dst[1 * 64 * 72 + n * 72 + pos] = bf1(wa - bf16f(h));
        float wb = w2[(size_t)l * 256 * 64 + (nt * 64 + k) * 64 + n];
        u16 h2 = bf1(wb);
        dst[2 * 64 * 72 + n * 72 + pos] = h2;
        dst[3 * 64 * 72 + n * 72 + pos] = bf1(wb - bf16f(h2));
    }
}

// ------------------------- fused QKV GEMM (all weights preloaded) -------------
__global__ void __launch_bounds__(256) qkv_kernel(
    const float* __restrict__ x,
    const float* __restrict__ wq, const float* __restrict__ wk, const float* __restrict__ wv,
    const float* __restrict__ bq, const float* __restrict__ bk, const float* __restrict__ bv_,
    float* __restrict__ q, float* __restrict__ k, float* __restrict__ v) {
    extern __shared__ float sm[];
    float (*As)[65] = (float(*)[65])sm;
    float (*Ws)[64] = (float(*)[64])(sm + 4160);
    int tid = threadIdx.x;
    int tx = tid & 15, ty = tid >> 4;
    int m0 = blockIdx.x * 64;

    for (int i = tid; i < 64 * 64; i += 256)
        As[i >> 6][i & 63] = x[(size_t)(m0 + (i >> 6)) * 64 + (i & 63)];
    for (int i = tid; i < 64 * 64; i += 256) {
        Ws[i >> 6][i & 63]         = wq[i];
        Ws[64 + (i >> 6)][i & 63]  = wk[i];
        Ws[128 + (i >> 6)][i & 63] = wv[i];
    }
    __syncthreads();

    u64 acc[3][4][2];
    #pragma unroll
    for (int w = 0; w < 3; ++w)
        #pragma unroll
        for (int i = 0; i < 4; ++i) { acc[w][i][0] = 0ull; acc[w][i][1] = 0ull; }

    #pragma unroll
    for (int w = 0; w < 3; ++w) {
        #pragma unroll 8
        for (int kk = 0; kk < 64; ++kk) {
            ulonglong2 w2 = *(const ulonglong2*)&Ws[w * 64 + kk][tx * 4];
            #pragma unroll
            for (int i = 0; i < 4; ++i) {
                float a = As[ty * 4 + i][kk];
                u64 ap = pack2(a, a);
                acc[w][i][0] = fma2(ap, w2.x, acc[w][i][0]);
                acc[w][i][1] = fma2(ap, w2.y, acc[w][i][1]);
            }
        }
    }

    const float* bptr[3] = {bq, bk, bv_};
    float* optr[3] = {q, k, v};
    #pragma unroll
    for (int w = 0; w < 3; ++w) {
        float4 bv4 = *(const float4*)&bptr[w][tx * 4];
        #pragma unroll
        for (int i = 0; i < 4; ++i) {
            float2 p0 = unpack2(acc[w][i][0]);
            float2 p1 = unpack2(acc[w][i][1]);
            float4 o = make_float4(p0.x + bv4.x, p0.y + bv4.y, p1.x + bv4.z, p1.y + bv4.w);
            *(float4*)&optr[w][(size_t)(m0 + ty * 4 + i) * 64 + tx * 4] = o;
        }
    }
}

// ------------------------- tensor-core flash attention -------------------------
// 256 threads = 8 warps, each warp owns 32 queries (two 16-row A-sets). Block: 256 q.
#define KCHUNK 64
__global__ void __launch_bounds__(256) attn_mma_kernel(
    const float* __restrict__ q, const float* __restrict__ k,
    const float* __restrict__ v, const float* __restrict__ nanf,
    float* __restrict__ ctx) {
    __shared__ __align__(16) u16 Qs[256 * 16];      // [query][dim]
    __shared__ __align__(16) u16 Ks[KCHUNK * 18];   // [key][dim], stride 18 u16
    __shared__ __align__(16) u16 Vt[16 * 66];       // [dim][key], stride 66 u16
    __shared__ float bias[KCHUNK];
    __shared__ float rkeep[256];

    int tid = threadIdx.x;
    int w   = tid >> 5;
    int lane = tid & 31;
    int gid = lane >> 2;
    int tig = lane & 3;
    int bh = blockIdx.y;
    int b = bh >> 2, h = bh & 3;
    int qbase = blockIdx.x * 256;
    size_t bS = (size_t)b * S_;

    const float SC = 0.25f * 1.4426950408889634f;

    #pragma unroll
    for (int it = 0; it < 4; ++it) {
        int idx = tid + it * 256;           // 0..1023
        int qq = idx >> 2, d4 = idx & 3;
        float4 f = *(const float4*)(q + (bS + qbase + qq) * 64 + h * 16 + d4 * 4);
        *(u32*)((char*)Qs + qq * 32 + d4 * 8)     = bf2(f.x * SC, f.y * SC);
        *(u32*)((char*)Qs + qq * 32 + d4 * 8 + 4) = bf2(f.z * SC, f.w * SC);
    }
    rkeep[tid] = (nanf[bS + qbase + tid] == 0.f) ? 1.f : 0.f;
    __syncthreads();

    u32 qa[2][4];
    #pragma unroll
    for (int s = 0; s < 2; ++s) {
        int row = w * 32 + s * 16 + gid;
        qa[s][0] = *(const u32*)((char*)Qs + row * 32 + tig * 4);
        qa[s][1] = *(const u32*)((char*)Qs + (row + 8) * 32 + tig * 4);
        qa[s][2] = *(const u32*)((char*)Qs + row * 32 + tig * 4 + 16);
        qa[s][3] = *(const u32*)((char*)Qs + (row + 8) * 32 + tig * 4 + 16);
    }

    float z[2][2] = {{0.f, 0.f}, {0.f, 0.f}};
    float cd[2][2][4];
    #pragma unroll
    for (int s = 0; s < 2; ++s)
        #pragma unroll
        for (int dt = 0; dt < 2; ++dt)
            #pragma unroll
            for (int i = 0; i < 4; ++i) cd[s][dt][i] = 0.f;

    for (int ch = 0; ch < S_ / KCHUNK; ++ch) {
        __syncthreads();
        int kg = ch * KCHUNK;
        {
            int key = tid >> 2, d4 = tid & 3;
            float4 kf = *(const float4*)(k + (bS + kg + key) * 64 + h * 16 + d4 * 4);
            *(u32*)((char*)Ks + key * 36 + d4 * 8)     = bf2(kf.x, kf.y);
            *(u32*)((char*)Ks + key * 36 + d4 * 8 + 4) = bf2(kf.z, kf.w);
            float4 vf = *(const float4*)(v + (bS + kg + key) * 64 + h * 16 + d4 * 4);
            Vt[(d4 * 4 + 0) * 66 + key] = bf1(vf.x);
            Vt[(d4 * 4 + 1) * 66 + key] = bf1(vf.y);
            Vt[(d4 * 4 + 2) * 66 + key] = bf1(vf.z);
            Vt[(d4 * 4 + 3) * 66 + key] = bf1(vf.w);
            if (tid < KCHUNK) bias[tid] = (nanf[bS + kg + tid] != 0.f) ? -1e30f : 0.f;
        }
        __syncthreads();

        #pragma unroll
        for (int kb = 0; kb < KCHUNK; kb += 16) {
            // shared K fragments
            u32 kb0a = *(const u32*)((char*)Ks + (kb + gid) * 36 + tig * 4);
            u32 kb1a = *(const u32*)((char*)Ks + (kb + gid) * 36 + tig * 4 + 16);
            u32 kb0b = *(const u32*)((char*)Ks + (kb + 8 + gid) * 36 + tig * 4);
            u32 kb1b = *(const u32*)((char*)Ks + (kb + 8 + gid) * 36 + tig * 4 + 16);
            // shared V fragments
            u32 vb00 = *(const u32*)((char*)Vt + (gid * 66 + kb + 2 * tig) * 2);
            u32 vb01 = *(const u32*)((char*)Vt + (gid * 66 + kb + 8 + 2 * tig) * 2);
            u32 vb10 = *(const u32*)((char*)Vt + ((gid + 8) * 66 + kb + 2 * tig) * 2);
            u32 vb11 = *(const u32*)((char*)Vt + ((gid + 8) * 66 + kb + 8 + 2 * tig) * 2);
            float2 bv0 = *(const float2*)(bias + kb + 2 * tig);
            float2 bv1 = *(const float2*)(bias + kb + 8 + 2 * tig);

            #pragma unroll
            for (int s = 0; s < 2; ++s) {
                float c0 = 0.f, c1 = 0.f, c2 = 0.f, c3 = 0.f;
                mma_bf16(c0, c1, c2, c3, qa[s][0], qa[s][1], qa[s][2], qa[s][3], kb0a, kb1a);
                float d0 = 0.f, d1 = 0.f, d2 = 0.f, d3 = 0.f;
                mma_bf16(d0, d1, d2, d3, qa[s][0], qa[s][1], qa[s][2], qa[s][3], kb0b, kb1b);

                float p0 = ex2f(c0 + bv0.x), p1 = ex2f(c1 + bv0.y);
                float p2 = ex2f(c2 + bv0.x), p3 = ex2f(c3 + bv0.y);
                float p4 = ex2f(d0 + bv1.x), p5 = ex2f(d1 + bv1.y);
                float p6 = ex2f(d2 + bv1.x), p7 = ex2f(d3 + bv1.y);
                z[s][0] += (p0 + p1) + (p4 + p5);
                z[s][1] += (p2 + p3) + (p6 + p7);

                u32 pa0 = bf2(p0, p1), pa1 = bf2(p2, p3);
                u32 pa2 = bf2(p4, p5), pa3 = bf2(p6, p7);
                mma_bf16(cd[s][0][0], cd[s][0][1], cd[s][0][2], cd[s][0][3],
                         pa0, pa1, pa2, pa3, vb00, vb01);
                mma_bf16(cd[s][1][0], cd[s][1][1], cd[s][1][2], cd[s][1][3],
                         pa0, pa1, pa2, pa3, vb10, vb11);
            }
        }
    }

    #pragma unroll
    for (int s = 0; s < 2; ++s) {
        float z0 = z[s][0], z1 = z[s][1];
        z0 += __shfl_xor_sync(0xffffffffu, z0, 1);
        z0 += __shfl_xor_sync(0xffffffffu, z0, 2);
        z1 += __shfl_xor_sync(0xffffffffu, z1, 1);
        z1 += __shfl_xor_sync(0xffffffffu, z1, 2);

        int q0 = w * 32 + s * 16 + gid;
        int q1 = q0 + 8;
        float rk0 = rkeep[q0], rk1 = rkeep[q1];
        float rz0 = (rk0 != 0.f && z0 > 0.f) ? (1.f / z0) : 0.f;
        float rz1 = (rk1 != 0.f && z1 > 0.f) ? (1.f / z1) : 0.f;

        float* o0 = ctx + (bS + qbase + q0) * 64 + h * 16;
        float* o1 = ctx + (bS + qbase + q1) * 64 + h * 16;
        *(float2*)(o0 + 2 * tig)     = make_float2(cd[s][0][0] * rz0, cd[s][0][1] * rz0);
        *(float2*)(o0 + 8 + 2 * tig) = make_float2(cd[s][1][0] * rz0, cd[s][1][1] * rz0);
        *(float2*)(o1 + 2 * tig)     = make_float2(cd[s][0][2] * rz1, cd[s][0][3] * rz1);
        *(float2*)(o1 + 8 + 2 * tig) = make_float2(cd[s][1][2] * rz1, cd[s][1][3] * rz1);
    }
}

// ------------------------- GEMM + residual + LN + keep (+ split emit) ---------
__global__ void __launch_bounds__(256) gemm_ln_kernel(
    const float* __restrict__ A, const float* __restrict__ W,
    const float* __restrict__ resid,
    const float* __restrict__ g, const float* __restrict__ be,
    const float* __restrict__ keep, float* __restrict__ C,
    u16* __restrict__ outh, u16* __restrict__ outl) {
    __shared__ float As[64][65];
    __shared__ __align__(16) float Ws[64][64];
    int tid = threadIdx.x;
    int tx = tid & 15, ty = tid >> 4;
    int m0 = blockIdx.x * 64;

    for (int i = tid; i < 64 * 64; i += 256) {
        int r = i >> 6, c = i & 63;
        As[r][c] = A[(size_t)(m0 + r) * 64 + c];
        Ws[r][c] = W[i];
    }
    __syncthreads();

    u64 acc[4][2];
    #pragma unroll
    for (int i = 0; i < 4; ++i) { acc[i][0] = 0ull; acc[i][1] = 0ull; }
    #pragma unroll 8
    for (int kk = 0; kk < 64; ++kk) {
        ulonglong2 w2 = *(const ulonglong2*)&Ws[kk][tx * 4];
        #pragma unroll
        for (int i = 0; i < 4; ++i) {
            float a = As[ty * 4 + i][kk];
            u64 ap = pack2(a, a);
            acc[i][0] = fma2(ap, w2.x, acc[i][0]);
            acc[i][1] = fma2(ap, w2.y, acc[i][1]);
        }
    }
    __syncthreads();

    #pragma unroll
    for (int i = 0; i < 4; ++i) {
        int row = ty * 4 + i;
        float4 rv = *(const float4*)&resid[(size_t)(m0 + row) * 64 + tx * 4];
        float2 p0 = unpack2(acc[i][0]);
        float2 p1 = unpack2(acc[i][1]);
        As[row][tx * 4 + 0] = p0.x + rv.x;
        As[row][tx * 4 + 1] = p0.y + rv.y;
        As[row][tx * 4 + 2] = p1.x + rv.z;
        As[row][tx * 4 + 3] = p1.y + rv.w;
    }
    __syncthreads();

    int row = tid >> 2, part = tid & 3;
    const float* rp = &As[row][part * 16];
    float s = 0.f, ss = 0.f;
    #pragma unroll
    for (int c = 0; c < 16; ++c) { float vv = rp[c]; s += vv; ss += vv * vv; }
    s  += __shfl_xor_sync(0xffffffffu, s, 1);  s  += __shfl_xor_sync(0xffffffffu, s, 2);
    ss += __shfl_xor_sync(0xffffffffu, ss, 1); ss += __shfl_xor_sync(0xffffffffu, ss, 2);
    float mean = s * (1.f / 64.f);
    float var  = ss * (1.f / 64.f) - mean * mean;
    float inv  = rsqrtf(var + 1e-6f);
    float kp   = keep[m0 + row];
    float* op = &C[(size_t)(m0 + row) * 64 + part * 16];
    size_t srow = (size_t)(m0 + row) * 72;
    #pragma unroll
    for (int c4 = 0; c4 < 4; ++c4) {
        int c = part * 16 + c4 * 4;
        float4 o;
        o.x = ((rp[c4 * 4 + 0] - mean) * inv * g[c + 0] + be[c + 0]) * kp;
        o.y = ((rp[c4 * 4 + 1] - mean) * inv * g[c + 1] + be[c + 1]) * kp;
        o.z = ((rp[c4 * 4 + 2] - mean) * inv * g[c + 2] + be[c + 2]) * kp;
        o.w = ((rp[c4 * 4 + 3] - mean) * inv * g[c + 3] + be[c + 3]) * kp;
        *(float4*)&op[c4 * 4] = o;
        // bf16 split emit (frag layout, pairs)
        int pA = 2 * c4, pB = 2 * c4 + 1;
        int posA = part * 16 + (pA & 3) * 4 + ((pA >> 2) << 1);
        int posB = part * 16 + (pB & 3) * 4 + ((pB >> 2) << 1);
        u32 hA = bf2(o.x, o.y);
        float eA0 = __uint_as_float(hA << 16), eA1 = __uint_as_float(hA & 0xffff0000u);
        u32 lA = bf2(o.x - eA0, o.y - eA1);
        u32 hB = bf2(o.z, o.w);
        float eB0 = __uint_as_float(hB << 16), eB1 = __uint_as_float(hB & 0xffff0000u);
        u32 lB = bf2(o.z - eB0, o.w - eB1);
        *(u32*)&outh[srow + posA] = hA;
        *(u32*)&outl[srow + posA] = lA;
        *(u32*)&outh[srow + posB] = hB;
        *(u32*)&outl[srow + posB] = lB;
    }
}

// ------------------------- tensor-core FFN (bf16-split, 3-mma) ----------------
// 128 threads = 4 warps, 64 rows/block. A frags direct from global split out1.
__global__ void __launch_bounds__(128) ffn_mma_kernel(
    const u16* __restrict__ a_h, const u16* __restrict__ a_l,
    const float* __restrict__ resid, const u16* __restrict__ ws,
    const float* __restrict__ g, const float* __restrict__ be,
    const float* __restrict__ keep, float* __restrict__ C) {
    extern __shared__ u16 sw[];   // 4 * 64 * 72 u16 = 36864 B
    int tid = threadIdx.x, w = tid >> 5, lane = tid & 31;
    int gid = lane >> 2, tig = lane & 3;
    int m0 = blockIdx.x * 64;
    int r0 = m0 + w * 16 + gid;

    // A fragments (out1 split) from global, once
    u32 Ah[4][4], Al[4][4];
    {
        const u16* ph0 = a_h + (size_t)r0 * 72;
        const u16* ph8 = a_h + (size_t)(r0 + 8) * 72;
        const u16* pl0 = a_l + (size_t)r0 * 72;
        const u16* pl8 = a_l + (size_t)(r0 + 8) * 72;
        #pragma unroll
        for (int gk = 0; gk < 4; ++gk) {
            uint2 t0 = *(const uint2*)(ph0 + gk * 16 + tig * 4);
            uint2 t1 = *(const uint2*)(ph8 + gk * 16 + tig * 4);
            Ah[gk][0] = t0.x; Ah[gk][2] = t0.y;
            Ah[gk][1] = t1.x; Ah[gk][3] = t1.y;
            uint2 s0 = *(const uint2*)(pl0 + gk * 16 + tig * 4);
            uint2 s1 = *(const uint2*)(pl8 + gk * 16 + tig * 4);
            Al[gk][0] = s0.x; Al[gk][2] = s0.y;
            Al[gk][1] = s1.x; Al[gk][3] = s1.y;
        }
    }

    float C2[8][4];
    #pragma unroll
    for (int j = 0; j < 8; ++j)
        #pragma unroll
        for (int i = 0; i < 4; ++i) C2[j][i] = 0.f;

    for (int nt = 0; nt < 4; ++nt) {
        __syncthreads();
        {   // copy chunk region (36864 B) global -> smem
            const float4* src = (const float4*)(ws + (size_t)nt * 4 * 64 * 72);
            float4* dst = (float4*)sw;
            #pragma unroll
            for (int i = 0; i < 18; ++i) dst[tid + i * 128] = src[tid + i * 128];
        }
        __syncthreads();
        const u16* W1h = sw;
        const u16* W1l = sw + 64 * 72;
        const u16* W2h = sw + 2 * 64 * 72;
        const u16* W2l = sw + 3 * 64 * 72;

        // GEMM1 + relu + split -> A2 fragments
        u32 A2h[4][4], A2l[4][4];
        #pragma unroll
        for (int t = 0; t < 4; ++t) {
            float Ca[4] = {0.f, 0.f, 0.f, 0.f};
            float Cb[4] = {0.f, 0.f, 0.f, 0.f};
            #pragma unroll
            for (int gk = 0; gk < 4; ++gk) {
                uint2 bha = *(const uint2*)(W1h + (16 * t + gid) * 72 + gk * 16 + tig * 4);
                uint2 bla = *(const uint2*)(W1l + (16 * t + gid) * 72 + gk * 16 + tig * 4);
                mma_bf16(Ca[0], Ca[1], Ca[2], Ca[3], Ah[gk][0], Ah[gk][1], Ah[gk][2], Ah[gk][3], bha.x, bha.y);
                mma_bf16(Ca[0], Ca[1], Ca[2], Ca[3], Ah[gk][0], Ah[gk][1], Ah[gk][2], Ah[gk][3], bla.x, bla.y);
                mma_bf16(Ca[0], Ca[1], Ca[2], Ca[3], Al[gk][0], Al[gk][1], Al[gk][2], Al[gk][3], bha.x, bha.y);
                uint2 bhb = *(const uint2*)(W1h + (16 * t + 8 + gid) * 72 + gk * 16 + tig * 4);
                uint2 blb = *(const uint2*)(W1l + (16 * t + 8 + gid) * 72 + gk * 16 + tig * 4);
                mma_bf16(Cb[0], Cb[1], Cb[2], Cb[3], Ah[gk][0], Ah[gk][1], Ah[gk][2], Ah[gk][3], bhb.x, bhb.y);
                mma_bf16(Cb[0], Cb[1], Cb[2], Cb[3], Ah[gk][0], Ah[gk][1], Ah[gk][2], Ah[gk][3], blb.x, blb.y);
                mma_bf16(Cb[0], Cb[1], Cb[2], Cb[3], Al[gk][0], Al[gk][1], Al[gk][2], Al[gk][3], bhb.x, bhb.y);
            }
            #pragma unroll
            for (int i = 0; i < 4; ++i) { Ca[i] = fmaxf(Ca[i], 0.f); Cb[i] = fmaxf(Cb[i], 0.f); }
            // h split -> A2 frag regs: a0=(Ca0,Ca1) a1=(Ca2,Ca3) a2=(Cb0,Cb1) a3=(Cb2,Cb3)
            u32 h0 = bf2(Ca[0], Ca[1]);
            A2h[t][0] = h0;
            A2l[t][0] = bf2(Ca[0] - __uint_as_float(h0 << 16), Ca[1] - __uint_as_float(h0 & 0xffff0000u));
            u32 h1 = bf2(Ca[2], Ca[3]);
            A2h[t][1] = h1;
            A2l[t][1] = bf2(Ca[2] - __uint_as_float(h1 << 16), Ca[3] - __uint_as_float(h1 & 0xffff0000u));
            u32 h2 = bf2(Cb[0], Cb[1]);
            A2h[t][2] = h2;
            A2l[t][2] = bf2(Cb[0] - __uint_as_float(h2 << 16), Cb[1] - __uint_as_float(h2 & 0xffff0000u));
            u32 h3 = bf2(Cb[2], Cb[3]);
            A2h[t][3] = h3;
            A2l[t][3] = bf2(Cb[2] - __uint_as_float(h3 << 16), Cb[3] - __uint_as_float(h3 & 0xffff0000u));
        }

        // GEMM2: accumulate into C2
        #pragma unroll
        for (int j = 0; j < 8; ++j) {
            #pragma unroll
            for (int t = 0; t < 4; ++t) {
                uint2 bh = *(const uint2*)(W2h + (8 * j + gid) * 72 + t * 16 + tig * 4);
                uint2 bl = *(const uint2*)(W2l + (8 * j + gid) * 72 + t * 16 + tig * 4);
                mma_bf16(C2[j][0], C2[j][1], C2[j][2], C2[j][3], A2h[t][0], A2h[t][1], A2h[t][2], A2h[t][3], bh.x, bh.y);
                mma_bf16(C2[j][0], C2[j][1], C2[j][2], C2[j][3], A2h[t][0], A2h[t][1], A2h[t][2], A2h[t][3], bl.x, bl.y);
                mma_bf16(C2[j][0], C2[j][1], C2[j][2], C2[j][3], A2l[t][0], A2l[t][1], A2l[t][2], A2l[t][3], bh.x, bh.y);
            }
        }
    }

    // epilogue: + resid, LN, keep
    float v0[16], v1[16];
    float s0 = 0.f, q0 = 0.f, s1 = 0.f, q1 = 0.f;
    #pragma unroll
    for (int j = 0; j < 8; ++j) {
        float2 ra = *(const float2*)(resid + (size_t)r0 * 64 + 8 * j + 2 * tig);
        float2 rb = *(const float2*)(resid + (size_t)(r0 + 8) * 64 + 8 * j + 2 * tig);
        float a0v = C2[j][0] + ra.x, a1v = C2[j][1] + ra.y;
        float b0v = C2[j][2] + rb.x, b1v = C2[j][3] + rb.y;
        v0[2 * j] = a0v; v0[2 * j + 1] = a1v;
        v1[2 * j] = b0v; v1[2 * j + 1] = b1v;
        s0 += a0v + a1v; q0 += a0v * a0v + a1v * a1v;
        s1 += b0v + b1v; q1 += b0v * b0v + b1v * b1v;
    }
    s0 += __shfl_xor_sync(0xffffffffu, s0, 1); s0 += __shfl_xor_sync(0xffffffffu, s0, 2);
    q0 += __shfl_xor_sync(0xffffffffu, q0, 1); q0 += __shfl_xor_sync(0xffffffffu, q0, 2);
    s1 += __shfl_xor_sync(0xffffffffu, s1, 1); s1 += __shfl_xor_sync(0xffffffffu, s1, 2);
    q1 += __shfl_xor_sync(0xffffffffu, q1, 1); q1 += __shfl_xor_sync(0xffffffffu, q1, 2);
    float m0v = s0 * (1.f / 64.f), m1v = s1 * (1.f / 64.f);
    float i0 = rsqrtf(q0 * (1.f / 64.f) - m0v * m0v + 1e-6f);
    float i1 = rsqrtf(q1 * (1.f / 64.f) - m1v * m1v + 1e-6f);
    float kp0 = keep[r0], kp1 = keep[r0 + 8];
    #pragma unroll
    for (int j = 0; j < 8; ++j) {
        int c = 8 * j + 2 * tig;
        float2 gg = *(const float2*)(g + c);
        float2 bb = *(const float2*)(be + c);
        float2 oa = make_float2(((v0[2 * j] - m0v) * i0 * gg.x + bb.x) * kp0,
                                ((v0[2 * j + 1] - m0v) * i0 * gg.y + bb.y) * kp0);
        float2 ob = make_float2(((v1[2 * j] - m1v) * i1 * gg.x + bb.x) * kp1,
                                ((v1[2 * j + 1] - m1v) * i1 * gg.y + bb.y) * kp1);
        *(float2*)(C + (size_t)r0 * 64 + c) = oa;
        *(float2*)(C + (size_t)(r0 + 8) * 64 + c) = ob;
    }
}

// ------------------------- classifier fused -----------------------------------
__global__ void __launch_bounds__(256) cls_kernel(
    const float* __restrict__ x,
    const float* __restrict__ w1, const float* __restrict__ b1,
    const float* __restrict__ w2, const float* __restrict__ b2,
    const float* __restrict__ w3, const float* __restrict__ b3,
    float* __restrict__ part) {
    __shared__ float Xs[64][65];
    __shared__ __align__(16) float Ws[64][64];
    __shared__ float w3s[64];
    __shared__ float red[256];
    int tid = threadIdx.x;
    int tx = tid & 15, ty = tid >> 4;
    int m0 = blockIdx.x * 64;

    for (int i = tid; i < 64 * 64; i += 256) {
        int r = i >> 6, c = i & 63;
        Xs[r][c] = x[(size_t)(m0 + r) * 64 + c];
        Ws[r][c] = w1[i];
    }
    if (tid < 64) w3s[tid] = w3[tid];
    __syncthreads();

    u64 acc[4][2];
    #pragma unroll
    for (int i = 0; i < 4; ++i) { acc[i][0] = 0ull; acc[i][1] = 0ull; }
    #pragma unroll 8
    for (int kk = 0; kk < 64; ++kk) {
        ulonglong2 w2v = *(const ulonglong2*)&Ws[kk][tx * 4];
        #pragma unroll
        for (int i = 0; i < 4; ++i) {
            float a = Xs[ty * 4 + i][kk];
            u64 ap = pack2(a, a);
            acc[i][0] = fma2(ap, w2v.x, acc[i][0]);
            acc[i][1] = fma2(ap, w2v.y, acc[i][1]);
        }
    }
    __syncthreads();

    float4 b1v = *(const float4*)&b1[tx * 4];
    #pragma unroll
    for (int i = 0; i < 4; ++i) {
        int row = ty * 4 + i;
        float2 p0 = unpack2(acc[i][0]);
        float2 p1 = unpack2(acc[i][1]);
        Xs[row][tx * 4 + 0] = fmaxf(p0.x + b1v.x, 0.f);
        Xs[row][tx * 4 + 1] = fmaxf(p0.y + b1v.y, 0.f);
        Xs[row][tx * 4 + 2] = fmaxf(p1.x + b1v.z, 0.f);
        Xs[row][tx * 4 + 3] = fmaxf(p1.y + b1v.w, 0.f);
    }
    for (int i = tid; i < 64 * 64; i += 256) Ws[i >> 6][i & 63] = w2[i];
    __syncthreads();

    #pragma unroll
    for (int i = 0; i < 4; ++i) { acc[i][0] = 0ull; acc[i][1] = 0ull; }
    #pragma unroll 8
    for (int kk = 0; kk < 64; ++kk) {
        ulonglong2 w2v = *(const ulonglong2*)&Ws[kk][tx * 4];
        #pragma unroll
        for (int i = 0; i < 4; ++i) {
            float a = Xs[ty * 4 + i][kk];
            u64 ap = pack2(a, a);
            acc[i][0] = fma2(ap, w2v.x, acc[i][0]);
            acc[i][1] = fma2(ap, w2v.y, acc[i][1]);
        }
    }

    float4 b2v = *(const float4*)&b2[tx * 4];
    float partial = 0.f;
    #pragma unroll
    for (int i = 0; i < 4; ++i) {
        float2 p0 = unpack2(acc[i][0]);
        float2 p1 = unpack2(acc[i][1]);
        partial += fmaxf(p0.x + b2v.x, 0.f) * w3s[tx * 4 + 0];
        partial += fmaxf(p0.y + b2v.y, 0.f) * w3s[tx * 4 + 1];
        partial += fmaxf(p1.x + b2v.z, 0.f) * w3s[tx * 4 + 2];
        partial += fmaxf(p1.y + b2v.w, 0.f) * w3s[tx * 4 + 3];
    }
    red[tid] = partial;
    __syncthreads();
    for (int st = 128; st > 0; st >>= 1) {
        if (tid < st) red[tid] += red[tid + st];
        __syncthreads();
    }
    if (tid == 0) part[blockIdx.x] = red[0] + 64.f * b3[0];
}

// ------------------------- deterministic final reduction ----------------------
__global__ void reduce_y(const float* __restrict__ part,
                         const float* __restrict__ ob, float* __restrict__ y) {
    int b = threadIdx.x;   // 16
    float s = ob[0];
    #pragma unroll
    for (int i = 0; i < 16; ++i) s += part[b * 16 + i];
    y[b] = s;
}

// ------------------------- launcher ------------------------------------------
extern "C" void kernel_launch(void* const* d_in, const int* in_sizes, int n_in,
                              void* d_out, int out_size) {
    const float* input  = (const float*)d_in[0];
    const float* emb    = (const float*)d_in[1];
    const float* wq     = (const float*)d_in[2];
    const float* wq_b   = (const float*)d_in[3];
    const float* wk     = (const float*)d_in[4];
    const float* wk_b   = (const float*)d_in[5];
    const float* wv     = (const float*)d_in[6];
    const float* wv_b   = (const float*)d_in[7];
    const float* wo     = (const float*)d_in[8];
    const float* ffn_w1 = (const float*)d_in[9];
    const float* ffn_w2 = (const float*)d_in[10];
    const float* ln1_g  = (const float*)d_in[11];
    const float* ln1_b  = (const float*)d_in[12];
    const float* ln2_g  = (const float*)d_in[13];
    const float* ln2_b  = (const float*)d_in[14];
    const float* c_w1   = (const float*)d_in[15];
    const float* c_b1   = (const float*)d_in[16];
    const float* c_w2   = (const float*)d_in[17];
    const float* c_b2   = (const float*)d_in[18];
    const float* c_w3   = (const float*)d_in[19];
    const float* c_b3   = (const float*)d_in[20];
    const float* ob     = (const float*)d_in[21];
    float* y = (float*)d_out;

    float *x, *q, *k, *v, *ctx, *out1, *keep, *nanf, *part;
    u16 *ws, *o1h, *o1l;
    cudaGetSymbolAddress((void**)&x,    g_x);
    cudaGetSymbolAddress((void**)&q,    g_q);
    cudaGetSymbolAddress((void**)&k,    g_k);
    cudaGetSymbolAddress((void**)&v,    g_v);
    cudaGetSymbolAddress((void**)&ctx,  g_ctx);
    cudaGetSymbolAddress((void**)&out1, g_out1);
    cudaGetSymbolAddress((void**)&keep, g_keep);
    cudaGetSymbolAddress((void**)&nanf, g_nanf);
    cudaGetSymbolAddress((void**)&part, g_part);
    cudaGetSymbolAddress((void**)&ws,   g_ws);
    cudaGetSymbolAddress((void**)&o1h,  g_o1h);
    cudaGetSymbolAddress((void**)&o1l,  g_o1l);

    const int QKV_SMEM = (4160 + 3 * 4096) * 4;   // 65792 B
    const int FFN_SMEM = 4 * 64 * 72 * 2;         // 36864 B
    cudaFuncSetAttribute(qkv_kernel, cudaFuncAttributeMaxDynamicSharedMemorySize, QKV_SMEM);
    cudaFuncSetAttribute(ffn_mma_kernel, cudaFuncAttributeMaxDynamicSharedMemorySize, FFN_SMEM);

    prep_kernel<<<B_, S_>>>(input, keep, nanf);
    build_x_kernel<<<(BS * D_) / 256, 256>>>(input, emb, keep, x);
    wprep_kernel<<<L_ * 4, 256>>>(ffn_w1, ffn_w2, ws);

    for (int l = 0; l < L_; ++l) {
        const float* wq_l  = wq  + l * D_ * D_;
        const float* wk_l  = wk  + l * D_ * D_;
        const float* wv_l  = wv  + l * D_ * D_;
        const float* wo_l  = wo  + l * D_ * D_;

        qkv_kernel<<<BS / 64, 256, QKV_SMEM>>>(x, wq_l, wk_l, wv_l,
                                     wq_b + l * D_, wk_b + l * D_, wv_b + l * D_,
                                     q, k, v);
        attn_mma_kernel<<<dim3(S_ / 256, B_ * H_), 256>>>(q, k, v, nanf, ctx);
        gemm_ln_kernel<<<BS / 64, 256>>>(ctx, wo_l, x,
                                         ln1_g + l * D_, ln1_b + l * D_, keep, out1,
                                         o1h, o1l);
        ffn_mma_kernel<<<BS / 64, 128, FFN_SMEM>>>(o1h, o1l, out1,
                                                   ws + (size_t)l * 4 * 4 * 64 * 72,
                                                   ln2_g + l * D_, ln2_b + l * D_, keep, x);
    }

    cls_kernel<<<BS / 64, 256>>>(x, c_w1, c_b1, c_w2, c_b2, c_w3, c_b3, part);
    reduce_y<<<1, 16>>>(part, ob, y);
}

// round 7
// speedup vs baseline: 3.1010x; 1.0996x over previous
#include <cuda_runtime.h>

#define B_  16
#define S_  1024
#define D_  64
#define H_  4
#define DFF 256
#define L_  2
#define BS  (B_ * S_)

typedef unsigned long long u64;
typedef unsigned int u32;
typedef unsigned short u16;

// ------------------------- device scratch ------------------------------------
__device__ float g_x   [BS * D_];
__device__ float g_q   [BS * D_];
__device__ float g_k   [BS * D_];
__device__ float g_v   [BS * D_];
__device__ float g_out1[BS * D_];
__device__ float g_keep[BS];
__device__ float g_nanf[BS];
__device__ float g_part[BS / 64];
__device__ u16   g_ws   [L_ * 4 * 4 * 64 * 72];  // split ffn weights, frag layout
__device__ u16   g_wqkvo[L_ * 8 * 64 * 72];      // split q,k,v,o weights (hi/lo each)
__device__ u16   g_xh  [BS * 72];                // x bf16-hi frag layout
__device__ u16   g_xl  [BS * 72];
__device__ u16   g_cxh [BS * 72];                // ctx split frag layout
__device__ u16   g_cxl [BS * 72];
__device__ u16   g_o1h [BS * 72];                // out1 split frag layout
__device__ u16   g_o1l [BS * 72];

// ------------------------- helpers --------------------------------------------
__device__ __forceinline__ u64 fma2(u64 a, u64 b, u64 c) {
    u64 d; asm("fma.rn.f32x2 %0, %1, %2, %3;" : "=l"(d) : "l"(a), "l"(b), "l"(c)); return d;
}
__device__ __forceinline__ u64 pack2(float x, float y) {
    u64 d; asm("mov.b64 %0, {%1, %2};" : "=l"(d) : "f"(x), "f"(y)); return d;
}
__device__ __forceinline__ float2 unpack2(u64 a) {
    float lo, hi; asm("mov.b64 {%0, %1}, %2;" : "=f"(lo), "=f"(hi) : "l"(a));
    return make_float2(lo, hi);
}
__device__ __forceinline__ float ex2f(float x) {
    float r; asm("ex2.approx.f32 %0, %1;" : "=f"(r) : "f"(x)); return r;
}
__device__ __forceinline__ u32 bf2(float lo, float hi) {
    u32 r; asm("cvt.rn.bf16x2.f32 %0, %1, %2;" : "=r"(r) : "f"(hi), "f"(lo)); return r;
}
__device__ __forceinline__ u16 bf1(float f) {
    u16 h; asm("cvt.rn.bf16.f32 %0, %1;" : "=h"(h) : "f"(f)); return h;
}
__device__ __forceinline__ float bf16f(u16 h) { return __uint_as_float((u32)h << 16); }
__device__ __forceinline__ void mma_bf16(
    float& c0, float& c1, float& c2, float& c3,
    u32 a0, u32 a1, u32 a2, u32 a3, u32 b0, u32 b1) {
    asm volatile(
        "mma.sync.aligned.m16n8k16.row.col.f32.bf16.bf16.f32 "
        "{%0,%1,%2,%3},{%4,%5,%6,%7},{%8,%9},{%0,%1,%2,%3};"
        : "+f"(c0), "+f"(c1), "+f"(c2), "+f"(c3)
        : "r"(a0), "r"(a1), "r"(a2), "r"(a3), "r"(b0), "r"(b1));
}
// permuted k-position inside a 16-group
__device__ __forceinline__ int permpos(int j) {   // j in 0..15
    int p = j >> 1, l = j & 1;
    return (p & 3) * 4 + ((p >> 2) << 1) + l;
}
// pos of an even column pair (c,c+1) in the 72-wide frag row
__device__ __forceinline__ int pairpos(int c) {
    int p = (c & 15) >> 1;
    return (c >> 4) * 16 + (p & 3) * 4 + ((p >> 2) << 1);
}
// split a float pair into hi/lo bf16x2
__device__ __forceinline__ void split2(float a, float b, u32& h, u32& l) {
    h = bf2(a, b);
    l = bf2(a - __uint_as_float(h << 16), b - __uint_as_float(h & 0xffff0000u));
}

// ------------------------- prep: nan flags + keep ----------------------------
__global__ void prep_kernel(const float* __restrict__ in,
                            float* __restrict__ keepv, float* __restrict__ nanf) {
    int b = blockIdx.x;
    int s = threadIdx.x;            // 1024 threads
    float v = in[b * S_ + s];
    bool nan = (v != v);
    unsigned bal = __ballot_sync(0xffffffffu, nan);
    __shared__ int warp_all[32];
    __shared__ int allnan_s;
    if ((s & 31) == 0) warp_all[s >> 5] = (bal == 0xffffffffu);
    __syncthreads();
    if (s == 0) {
        int a = 1;
        #pragma unroll
        for (int i = 0; i < 32; ++i) a &= warp_all[i];
        allnan_s = a;
    }
    __syncthreads();
    float kp = (nan || allnan_s) ? 0.f : 1.f;
    keepv[b * S_ + s] = kp;
    nanf [b * S_ + s] = nan ? 1.f : 0.f;
}

// ------------------------- build x (fp32 + split frag emit) -------------------
__global__ void build_x_kernel(const float* __restrict__ in,
                               const float* __restrict__ emb,
                               const float* __restrict__ keepv,
                               float* __restrict__ x,
                               u16* __restrict__ xh, u16* __restrict__ xl) {
    int idx = blockIdx.x * 256 + threadIdx.x;   // BS*32
    int cp  = idx & 31;
    int row = idx >> 5;
    int s   = row & (S_ - 1);
    int c   = cp * 2;
    float kp = keepv[row];
    const float SQF = 7.93725393319377f * 8.0f;  // sqrt(63)*sqrt(64)
    float v0 = emb[s * 63 + c] * SQF * kp;
    float v1;
    if (c + 1 == 63) {
        float t = in[row];
        v1 = ((t != t) ? 0.f : t) * kp;
    } else {
        v1 = emb[s * 63 + c + 1] * SQF * kp;
    }
    x[row * 64 + c] = v0;
    x[row * 64 + c + 1] = v1;
    int pos = pairpos(c);
    u32 h, l; split2(v0, v1, h, l);
    *(u32*)&xh[(size_t)row * 72 + pos] = h;
    *(u32*)&xl[(size_t)row * 72 + pos] = l;
}

// ------------------------- weight prep: ffn ----------------------------------
__global__ void wprep_kernel(const float* __restrict__ w1, const float* __restrict__ w2,
                             u16* __restrict__ ws) {
    int l = blockIdx.x >> 2, nt = blockIdx.x & 3;
    u16* dst = ws + (size_t)(l * 4 + nt) * (4 * 64 * 72);
    int tid = threadIdx.x;
    for (int i = tid; i < 4096; i += 256) {
        int k = i >> 6, n = i & 63;
        int pos = (k >> 4) * 16 + permpos(k & 15);
        float wa = w1[(size_t)l * 64 * 256 + k * 256 + nt * 64 + n];
        u16 h = bf1(wa);
        dst[0 * 64 * 72 + n * 72 + pos] = h;
        dst[1 * 64 * 72 + n * 72 + pos] = bf1(wa - bf16f(h));
        float wb = w2[(size_t)l * 256 * 64 + (nt * 64 + k) * 64 + n];
        u16 h2 = bf1(wb);
        dst[2 * 64 * 72 + n * 72 + pos] = h2;
        dst[3 * 64 * 72 + n * 72 + pos] = bf1(wb - bf16f(h2));
    }
}

// ------------------------- weight prep: q,k,v,o -------------------------------
__global__ void wprep_qkvo_kernel(const float* __restrict__ wq, const float* __restrict__ wk,
                                  const float* __restrict__ wv, const float* __restrict__ wo,
                                  u16* __restrict__ dstall) {
    int l = blockIdx.x >> 2, wsel = blockIdx.x & 3;
    const float* src = (wsel == 0 ? wq : wsel == 1 ? wk : wsel == 2 ? wv : wo) + (size_t)l * 4096;
    u16* dst = dstall + ((size_t)l * 8 + wsel * 2) * 4608;
    int tid = threadIdx.x;
    for (int i = tid; i < 4096; i += 256) {
        int k = i >> 6, n = i & 63;
        int pos = (k >> 4) * 16 + permpos(k & 15);
        float val = src[k * 64 + n];
        u16 h = bf1(val);
        dst[n * 72 + pos]        = h;
        dst[4608 + n * 72 + pos] = bf1(val - bf16f(h));
    }
}

// ------------------------- tensor-core QKV (one weight per block) -------------
__global__ void __launch_bounds__(128) qkv_mma_kernel(
    const u16* __restrict__ xh, const u16* __restrict__ xl,
    const u16* __restrict__ wsplit,   // [3][2][4608] region for this layer
    const float* __restrict__ bq, const float* __restrict__ bk, const float* __restrict__ bv_,
    float* __restrict__ q, float* __restrict__ k, float* __restrict__ v) {
    extern __shared__ u16 sw[];   // 2*4608 u16 = 18432 B
    int tid = threadIdx.x, w = tid >> 5, lane = tid & 31;
    int gid = lane >> 2, tig = lane & 3;
    int m0 = blockIdx.x * 64;
    int wsel = blockIdx.y;
    int r0 = m0 + w * 16 + gid;

    {   // copy this weight's hi/lo (18432 B)
        const float4* src = (const float4*)(wsplit + (size_t)wsel * 2 * 4608);
        float4* dst = (float4*)sw;
        #pragma unroll
        for (int i = 0; i < 9; ++i) dst[tid + i * 128] = src[tid + i * 128];
    }

    u32 Ah[4][4], Al[4][4];
    {
        const u16* ph0 = xh + (size_t)r0 * 72;
        const u16* ph8 = xh + (size_t)(r0 + 8) * 72;
        const u16* pl0 = xl + (size_t)r0 * 72;
        const u16* pl8 = xl + (size_t)(r0 + 8) * 72;
        #pragma unroll
        for (int gk = 0; gk < 4; ++gk) {
            uint2 t0 = *(const uint2*)(ph0 + gk * 16 + tig * 4);
            uint2 t1 = *(const uint2*)(ph8 + gk * 16 + tig * 4);
            Ah[gk][0] = t0.x; Ah[gk][2] = t0.y;
            Ah[gk][1] = t1.x; Ah[gk][3] = t1.y;
            uint2 s0 = *(const uint2*)(pl0 + gk * 16 + tig * 4);
            uint2 s1 = *(const uint2*)(pl8 + gk * 16 + tig * 4);
            Al[gk][0] = s0.x; Al[gk][2] = s0.y;
            Al[gk][1] = s1.x; Al[gk][3] = s1.y;
        }
    }
    __syncthreads();
    const u16* Wh = sw;
    const u16* Wl = sw + 4608;

    float C2[8][4];
    #pragma unroll
    for (int j = 0; j < 8; ++j)
        #pragma unroll
        for (int i = 0; i < 4; ++i) C2[j][i] = 0.f;

    #pragma unroll
    for (int j = 0; j < 8; ++j) {
        #pragma unroll
        for (int t = 0; t < 4; ++t) {
            uint2 bh = *(const uint2*)(Wh + (8 * j + gid) * 72 + t * 16 + tig * 4);
            uint2 bl = *(const uint2*)(Wl + (8 * j + gid) * 72 + t * 16 + tig * 4);
            mma_bf16(C2[j][0], C2[j][1], C2[j][2], C2[j][3], Ah[t][0], Ah[t][1], Ah[t][2], Ah[t][3], bh.x, bh.y);
            mma_bf16(C2[j][0], C2[j][1], C2[j][2], C2[j][3], Ah[t][0], Ah[t][1], Ah[t][2], Ah[t][3], bl.x, bl.y);
            mma_bf16(C2[j][0], C2[j][1], C2[j][2], C2[j][3], Al[t][0], Al[t][1], Al[t][2], Al[t][3], bh.x, bh.y);
        }
    }

    const float* bias = wsel == 0 ? bq : wsel == 1 ? bk : bv_;
    float* out = wsel == 0 ? q : wsel == 1 ? k : v;
    #pragma unroll
    for (int j = 0; j < 8; ++j) {
        int c = 8 * j + 2 * tig;
        float2 bb = *(const float2*)(bias + c);
        *(float2*)(out + (size_t)r0 * 64 + c)       = make_float2(C2[j][0] + bb.x, C2[j][1] + bb.y);
        *(float2*)(out + (size_t)(r0 + 8) * 64 + c) = make_float2(C2[j][2] + bb.x, C2[j][3] + bb.y);
    }
}

// ------------------------- tensor-core flash attention -------------------------
// 256 threads = 8 warps, each warp owns 32 queries. Block: 256 q. Emits split ctx frags.
#define KCHUNK 64
__global__ void __launch_bounds__(256) attn_mma_kernel(
    const float* __restrict__ q, const float* __restrict__ k,
    const float* __restrict__ v, const float* __restrict__ nanf,
    u16* __restrict__ cxh, u16* __restrict__ cxl) {
    __shared__ __align__(16) u16 Qs[256 * 16];
    __shared__ __align__(16) u16 Ks[KCHUNK * 18];
    __shared__ __align__(16) u16 Vt[16 * 66];
    __shared__ float bias[KCHUNK];
    __shared__ float rkeep[256];

    int tid = threadIdx.x;
    int w   = tid >> 5;
    int lane = tid & 31;
    int gid = lane >> 2;
    int tig = lane & 3;
    int bh = blockIdx.y;
    int b = bh >> 2, h = bh & 3;
    int qbase = blockIdx.x * 256;
    size_t bS = (size_t)b * S_;

    const float SC = 0.25f * 1.4426950408889634f;

    #pragma unroll
    for (int it = 0; it < 4; ++it) {
        int idx = tid + it * 256;
        int qq = idx >> 2, d4 = idx & 3;
        float4 f = *(const float4*)(q + (bS + qbase + qq) * 64 + h * 16 + d4 * 4);
        *(u32*)((char*)Qs + qq * 32 + d4 * 8)     = bf2(f.x * SC, f.y * SC);
        *(u32*)((char*)Qs + qq * 32 + d4 * 8 + 4) = bf2(f.z * SC, f.w * SC);
    }
    rkeep[tid] = (nanf[bS + qbase + tid] == 0.f) ? 1.f : 0.f;
    __syncthreads();

    u32 qa[2][4];
    #pragma unroll
    for (int s = 0; s < 2; ++s) {
        int row = w * 32 + s * 16 + gid;
        qa[s][0] = *(const u32*)((char*)Qs + row * 32 + tig * 4);
        qa[s][1] = *(const u32*)((char*)Qs + (row + 8) * 32 + tig * 4);
        qa[s][2] = *(const u32*)((char*)Qs + row * 32 + tig * 4 + 16);
        qa[s][3] = *(const u32*)((char*)Qs + (row + 8) * 32 + tig * 4 + 16);
    }

    float z[2][2] = {{0.f, 0.f}, {0.f, 0.f}};
    float cd[2][2][4];
    #pragma unroll
    for (int s = 0; s < 2; ++s)
        #pragma unroll
        for (int dt = 0; dt < 2; ++dt)
            #pragma unroll
            for (int i = 0; i < 4; ++i) cd[s][dt][i] = 0.f;

    for (int ch = 0; ch < S_ / KCHUNK; ++ch) {
        __syncthreads();
        int kg = ch * KCHUNK;
        {
            int key = tid >> 2, d4 = tid & 3;
            float4 kf = *(const float4*)(k + (bS + kg + key) * 64 + h * 16 + d4 * 4);
            *(u32*)((char*)Ks + key * 36 + d4 * 8)     = bf2(kf.x, kf.y);
            *(u32*)((char*)Ks + key * 36 + d4 * 8 + 4) = bf2(kf.z, kf.w);
            float4 vf = *(const float4*)(v + (bS + kg + key) * 64 + h * 16 + d4 * 4);
            Vt[(d4 * 4 + 0) * 66 + key] = bf1(vf.x);
            Vt[(d4 * 4 + 1) * 66 + key] = bf1(vf.y);
            Vt[(d4 * 4 + 2) * 66 + key] = bf1(vf.z);
            Vt[(d4 * 4 + 3) * 66 + key] = bf1(vf.w);
            if (tid < KCHUNK) bias[tid] = (nanf[bS + kg + tid] != 0.f) ? -1e30f : 0.f;
        }
        __syncthreads();

        #pragma unroll
        for (int kb = 0; kb < KCHUNK; kb += 16) {
            u32 kb0a = *(const u32*)((char*)Ks + (kb + gid) * 36 + tig * 4);
            u32 kb1a = *(const u32*)((char*)Ks + (kb + gid) * 36 + tig * 4 + 16);
            u32 kb0b = *(const u32*)((char*)Ks + (kb + 8 + gid) * 36 + tig * 4);
            u32 kb1b = *(const u32*)((char*)Ks + (kb + 8 + gid) * 36 + tig * 4 + 16);
            u32 vb00 = *(const u32*)((char*)Vt + (gid * 66 + kb + 2 * tig) * 2);
            u32 vb01 = *(const u32*)((char*)Vt + (gid * 66 + kb + 8 + 2 * tig) * 2);
            u32 vb10 = *(const u32*)((char*)Vt + ((gid + 8) * 66 + kb + 2 * tig) * 2);
            u32 vb11 = *(const u32*)((char*)Vt + ((gid + 8) * 66 + kb + 8 + 2 * tig) * 2);
            float2 bv0 = *(const float2*)(bias + kb + 2 * tig);
            float2 bv1 = *(const float2*)(bias + kb + 8 + 2 * tig);

            #pragma unroll
            for (int s = 0; s < 2; ++s) {
                float c0 = 0.f, c1 = 0.f, c2 = 0.f, c3 = 0.f;
                mma_bf16(c0, c1, c2, c3, qa[s][0], qa[s][1], qa[s][2], qa[s][3], kb0a, kb1a);
                float d0 = 0.f, d1 = 0.f, d2 = 0.f, d3 = 0.f;
                mma_bf16(d0, d1, d2, d3, qa[s][0], qa[s][1], qa[s][2], qa[s][3], kb0b, kb1b);

                float p0 = ex2f(c0 + bv0.x), p1 = ex2f(c1 + bv0.y);
                float p2 = ex2f(c2 + bv0.x), p3 = ex2f(c3 + bv0.y);
                float p4 = ex2f(d0 + bv1.x), p5 = ex2f(d1 + bv1.y);
                float p6 = ex2f(d2 + bv1.x), p7 = ex2f(d3 + bv1.y);
                z[s][0] += (p0 + p1) + (p4 + p5);
                z[s][1] += (p2 + p3) + (p6 + p7);

                u32 pa0 = bf2(p0, p1), pa1 = bf2(p2, p3);
                u32 pa2 = bf2(p4, p5), pa3 = bf2(p6, p7);
                mma_bf16(cd[s][0][0], cd[s][0][1], cd[s][0][2], cd[s][0][3],
                         pa0, pa1, pa2, pa3, vb00, vb01);
                mma_bf16(cd[s][1][0], cd[s][1][1], cd[s][1][2], cd[s][1][3],
                         pa0, pa1, pa2, pa3, vb10, vb11);
            }
        }
    }

    int posA = h * 16 + tig * 4;       // dt=0 pair
    int posB = posA + 2;               // dt=1 pair
    #pragma unroll
    for (int s = 0; s < 2; ++s) {
        float z0 = z[s][0], z1 = z[s][1];
        z0 += __shfl_xor_sync(0xffffffffu, z0, 1);
        z0 += __shfl_xor_sync(0xffffffffu, z0, 2);
        z1 += __shfl_xor_sync(0xffffffffu, z1, 1);
        z1 += __shfl_xor_sync(0xffffffffu, z1, 2);

        int q0 = w * 32 + s * 16 + gid;
        int q1 = q0 + 8;
        float rk0 = rkeep[q0], rk1 = rkeep[q1];
        float rz0 = (rk0 != 0.f && z0 > 0.f) ? (1.f / z0) : 0.f;
        float rz1 = (rk1 != 0.f && z1 > 0.f) ? (1.f / z1) : 0.f;

        size_t row0 = (bS + qbase + q0) * 72;
        size_t row1 = (bS + qbase + q1) * 72;
        u32 hh, ll;
        split2(cd[s][0][0] * rz0, cd[s][0][1] * rz0, hh, ll);
        *(u32*)&cxh[row0 + posA] = hh; *(u32*)&cxl[row0 + posA] = ll;
        split2(cd[s][1][0] * rz0, cd[s][1][1] * rz0, hh, ll);
        *(u32*)&cxh[row0 + posB] = hh; *(u32*)&cxl[row0 + posB] = ll;
        split2(cd[s][0][2] * rz1, cd[s][0][3] * rz1, hh, ll);
        *(u32*)&cxh[row1 + posA] = hh; *(u32*)&cxl[row1 + posA] = ll;
        split2(cd[s][1][2] * rz1, cd[s][1][3] * rz1, hh, ll);
        *(u32*)&cxh[row1 + posB] = hh; *(u32*)&cxl[row1 + posB] = ll;
    }
}

// ------------------------- tensor-core WO GEMM + resid + LN + keep -------------
__global__ void __launch_bounds__(128) wo_mma_kernel(
    const u16* __restrict__ cxh, const u16* __restrict__ cxl,
    const float* __restrict__ resid, const u16* __restrict__ wsplit,
    const float* __restrict__ g, const float* __restrict__ be,
    const float* __restrict__ keep, float* __restrict__ out1,
    u16* __restrict__ o1h, u16* __restrict__ o1l) {
    extern __shared__ u16 sw[];   // 2*4608 u16
    int tid = threadIdx.x, w = tid >> 5, lane = tid & 31;
    int gid = lane >> 2, tig = lane & 3;
    int m0 = blockIdx.x * 64;
    int r0 = m0 + w * 16 + gid;

    {
        const float4* src = (const float4*)wsplit;
        float4* dst = (float4*)sw;
        #pragma unroll
        for (int i = 0; i < 9; ++i) dst[tid + i * 128] = src[tid + i * 128];
    }

    u32 Ah[4][4], Al[4][4];
    {
        const u16* ph0 = cxh + (size_t)r0 * 72;
        const u16* ph8 = cxh + (size_t)(r0 + 8) * 72;
        const u16* pl0 = cxl + (size_t)r0 * 72;
        const u16* pl8 = cxl + (size_t)(r0 + 8) * 72;
        #pragma unroll
        for (int gk = 0; gk < 4; ++gk) {
            uint2 t0 = *(const uint2*)(ph0 + gk * 16 + tig * 4);
            uint2 t1 = *(const uint2*)(ph8 + gk * 16 + tig * 4);
            Ah[gk][0] = t0.x; Ah[gk][2] = t0.y;
            Ah[gk][1] = t1.x; Ah[gk][3] = t1.y;
            uint2 s0 = *(const uint2*)(pl0 + gk * 16 + tig * 4);
            uint2 s1 = *(const uint2*)(pl8 + gk * 16 + tig * 4);
            Al[gk][0] = s0.x; Al[gk][2] = s0.y;
            Al[gk][1] = s1.x; Al[gk][3] = s1.y;
        }
    }
    __syncthreads();
    const u16* Wh = sw;
    const u16* Wl = sw + 4608;

    float C2[8][4];
    #pragma unroll
    for (int j = 0; j < 8; ++j)
        #pragma unroll
        for (int i = 0; i < 4; ++i) C2[j][i] = 0.f;

    #pragma unroll
    for (int j = 0; j < 8; ++j) {
        #pragma unroll
        for (int t = 0; t < 4; ++t) {
            uint2 bh = *(const uint2*)(Wh + (8 * j + gid) * 72 + t * 16 + tig * 4);
            uint2 bl = *(const uint2*)(Wl + (8 * j + gid) * 72 + t * 16 + tig * 4);
            mma_bf16(C2[j][0], C2[j][1], C2[j][2], C2[j][3], Ah[t][0], Ah[t][1], Ah[t][2], Ah[t][3], bh.x, bh.y);
            mma_bf16(C2[j][0], C2[j][1], C2[j][2], C2[j][3], Ah[t][0], Ah[t][1], Ah[t][2], Ah[t][3], bl.x, bl.y);
            mma_bf16(C2[j][0], C2[j][1], C2[j][2], C2[j][3], Al[t][0], Al[t][1], Al[t][2], Al[t][3], bh.x, bh.y);
        }
    }

    // epilogue: + resid, LN, keep, write fp32 + split frags
    float v0[16], v1[16];
    float s0 = 0.f, q0 = 0.f, s1 = 0.f, q1 = 0.f;
    #pragma unroll
    for (int j = 0; j < 8; ++j) {
        float2 ra = *(const float2*)(resid + (size_t)r0 * 64 + 8 * j + 2 * tig);
        float2 rb = *(const float2*)(resid + (size_t)(r0 + 8) * 64 + 8 * j + 2 * tig);
        float a0v = C2[j][0] + ra.x, a1v = C2[j][1] + ra.y;
        float b0v = C2[j][2] + rb.x, b1v = C2[j][3] + rb.y;
        v0[2 * j] = a0v; v0[2 * j + 1] = a1v;
        v1[2 * j] = b0v; v1[2 * j + 1] = b1v;
        s0 += a0v + a1v; q0 += a0v * a0v + a1v * a1v;
        s1 += b0v + b1v; q1 += b0v * b0v + b1v * b1v;
    }
    s0 += __shfl_xor_sync(0xffffffffu, s0, 1); s0 += __shfl_xor_sync(0xffffffffu, s0, 2);
    q0 += __shfl_xor_sync(0xffffffffu, q0, 1); q0 += __shfl_xor_sync(0xffffffffu, q0, 2);
    s1 += __shfl_xor_sync(0xffffffffu, s1, 1); s1 += __shfl_xor_sync(0xffffffffu, s1, 2);
    q1 += __shfl_xor_sync(0xffffffffu, q1, 1); q1 += __shfl_xor_sync(0xffffffffu, q1, 2);
    float m0v = s0 * (1.f / 64.f), m1v = s1 * (1.f / 64.f);
    float i0 = rsqrtf(q0 * (1.f / 64.f) - m0v * m0v + 1e-6f);
    float i1 = rsqrtf(q1 * (1.f / 64.f) - m1v * m1v + 1e-6f);
    float kp0 = keep[r0], kp1 = keep[r0 + 8];
    #pragma unroll
    for (int j = 0; j < 8; ++j) {
        int c = 8 * j + 2 * tig;
        float2 gg = *(const float2*)(g + c);
        float2 bb = *(const float2*)(be + c);
        float2 oa = make_float2(((v0[2 * j] - m0v) * i0 * gg.x + bb.x) * kp0,
                                ((v0[2 * j + 1] - m0v) * i0 * gg.y + bb.y) * kp0);
        float2 ob = make_float2(((v1[2 * j] - m1v) * i1 * gg.x + bb.x) * kp1,
                                ((v1[2 * j + 1] - m1v) * i1 * gg.y + bb.y) * kp1);
        *(float2*)(out1 + (size_t)r0 * 64 + c) = oa;
        *(float2*)(out1 + (size_t)(r0 + 8) * 64 + c) = ob;
        int pos = pairpos(c);
        u32 hh, ll;
        split2(oa.x, oa.y, hh, ll);
        *(u32*)&o1h[(size_t)r0 * 72 + pos] = hh; *(u32*)&o1l[(size_t)r0 * 72 + pos] = ll;
        split2(ob.x, ob.y, hh, ll);
        *(u32*)&o1h[(size_t)(r0 + 8) * 72 + pos] = hh; *(u32*)&o1l[(size_t)(r0 + 8) * 72 + pos] = ll;
    }
}

// ------------------------- tensor-core FFN (bf16-split, 3-mma) ----------------
__global__ void __launch_bounds__(128) ffn_mma_kernel(
    const u16* __restrict__ a_h, const u16* __restrict__ a_l,
    const float* __restrict__ resid, const u16* __restrict__ ws,
    const float* __restrict__ g, const float* __restrict__ be,
    const float* __restrict__ keep, float* __restrict__ C,
    u16* __restrict__ xh, u16* __restrict__ xl) {
    extern __shared__ u16 sw[];   // 4 * 64 * 72 u16 = 36864 B
    int tid = threadIdx.x, w = tid >> 5, lane = tid & 31;
    int gid = lane >> 2, tig = lane & 3;
    int m0 = blockIdx.x * 64;
    int r0 = m0 + w * 16 + gid;

    u32 Ah[4][4], Al[4][4];
    {
        const u16* ph0 = a_h + (size_t)r0 * 72;
        const u16* ph8 = a_h + (size_t)(r0 + 8) * 72;
        const u16* pl0 = a_l + (size_t)r0 * 72;
        const u16* pl8 = a_l + (size_t)(r0 + 8) * 72;
        #pragma unroll
        for (int gk = 0; gk < 4; ++gk) {
            uint2 t0 = *(const uint2*)(ph0 + gk * 16 + tig * 4);
            uint2 t1 = *(const uint2*)(ph8 + gk * 16 + tig * 4);
            Ah[gk][0] = t0.x; Ah[gk][2] = t0.y;
            Ah[gk][1] = t1.x; Ah[gk][3] = t1.y;
            uint2 s0 = *(const uint2*)(pl0 + gk * 16 + tig * 4);
            uint2 s1 = *(const uint2*)(pl8 + gk * 16 + tig * 4);
            Al[gk][0] = s0.x; Al[gk][2] = s0.y;
            Al[gk][1] = s1.x; Al[gk][3] = s1.y;
        }
    }

    float C2[8][4];
    #pragma unroll
    for (int j = 0; j < 8; ++j)
        #pragma unroll
        for (int i = 0; i < 4; ++i) C2[j][i] = 0.f;

    for (int nt = 0; nt < 4; ++nt) {
        __syncthreads();
        {
            const float4* src = (const float4*)(ws + (size_t)nt * 4 * 64 * 72);
            float4* dst = (float4*)sw;
            #pragma unroll
            for (int i = 0; i < 18; ++i) dst[tid + i * 128] = src[tid + i * 128];
        }
        __syncthreads();
        const u16* W1h = sw;
        const u16* W1l = sw + 64 * 72;
        const u16* W2h = sw + 2 * 64 * 72;
        const u16* W2l = sw + 3 * 64 * 72;

        u32 A2h[4][4], A2l[4][4];
        #pragma unroll
        for (int t = 0; t < 4; ++t) {
            float Ca[4] = {0.f, 0.f, 0.f, 0.f};
            float Cb[4] = {0.f, 0.f, 0.f, 0.f};
            #pragma unroll
            for (int gk = 0; gk < 4; ++gk) {
                uint2 bha = *(const uint2*)(W1h + (16 * t + gid) * 72 + gk * 16 + tig * 4);
                uint2 bla = *(const uint2*)(W1l + (16 * t + gid) * 72 + gk * 16 + tig * 4);
                mma_bf16(Ca[0], Ca[1], Ca[2], Ca[3], Ah[gk][0], Ah[gk][1], Ah[gk][2], Ah[gk][3], bha.x, bha.y);
                mma_bf16(Ca[0], Ca[1], Ca[2], Ca[3], Ah[gk][0], Ah[gk][1], Ah[gk][2], Ah[gk][3], bla.x, bla.y);
                mma_bf16(Ca[0], Ca[1], Ca[2], Ca[3], Al[gk][0], Al[gk][1], Al[gk][2], Al[gk][3], bha.x, bha.y);
                uint2 bhb = *(const uint2*)(W1h + (16 * t + 8 + gid) * 72 + gk * 16 + tig * 4);
                uint2 blb = *(const uint2*)(W1l + (16 * t + 8 + gid) * 72 + gk * 16 + tig * 4);
                mma_bf16(Cb[0], Cb[1], Cb[2], Cb[3], Ah[gk][0], Ah[gk][1], Ah[gk][2], Ah[gk][3], bhb.x, bhb.y);
                mma_bf16(Cb[0], Cb[1], Cb[2], Cb[3], Ah[gk][0], Ah[gk][1], Ah[gk][2], Ah[gk][3], blb.x, blb.y);
                mma_bf16(Cb[0], Cb[1], Cb[2], Cb[3], Al[gk][0], Al[gk][1], Al[gk][2], Al[gk][3], bhb.x, bhb.y);
            }
            #pragma unroll
            for (int i = 0; i < 4; ++i) { Ca[i] = fmaxf(Ca[i], 0.f); Cb[i] = fmaxf(Cb[i], 0.f); }
            u32 h0 = bf2(Ca[0], Ca[1]);
            A2h[t][0] = h0;
            A2l[t][0] = bf2(Ca[0] - __uint_as_float(h0 << 16), Ca[1] - __uint_as_float(h0 & 0xffff0000u));
            u32 h1 = bf2(Ca[2], Ca[3]);
            A2h[t][1] = h1;
            A2l[t][1] = bf2(Ca[2] - __uint_as_float(h1 << 16), Ca[3] - __uint_as_float(h1 & 0xffff0000u));
            u32 h2 = bf2(Cb[0], Cb[1]);
            A2h[t][2] = h2;
            A2l[t][2] = bf2(Cb[0] - __uint_as_float(h2 << 16), Cb[1] - __uint_as_float(h2 & 0xffff0000u));
            u32 h3 = bf2(Cb[2], Cb[3]);
            A2h[t][3] = h3;
            A2l[t][3] = bf2(Cb[2] - __uint_as_float(h3 << 16), Cb[3] - __uint_as_float(h3 & 0xffff0000u));
        }

        #pragma unroll
        for (int j = 0; j < 8; ++j) {
            #pragma unroll
            for (int t = 0; t < 4; ++t) {
                uint2 bh = *(const uint2*)(W2h + (8 * j + gid) * 72 + t * 16 + tig * 4);
                uint2 bl = *(const uint2*)(W2l + (8 * j + gid) * 72 + t * 16 + tig * 4);
                mma_bf16(C2[j][0], C2[j][1], C2[j][2], C2[j][3], A2h[t][0], A2h[t][1], A2h[t][2], A2h[t][3], bh.x, bh.y);
                mma_bf16(C2[j][0], C2[j][1], C2[j][2], C2[j][3], A2h[t][0], A2h[t][1], A2h[t][2], A2h[t][3], bl.x, bl.y);
                mma_bf16(C2[j][0], C2[j][1], C2[j][2], C2[j][3], A2l[t][0], A2l[t][1], A2l[t][2], A2l[t][3], bh.x, bh.y);
            }
        }
    }

    float v0[16], v1[16];
    float s0 = 0.f, q0 = 0.f, s1 = 0.f, q1 = 0.f;
    #pragma unroll
    for (int j = 0; j < 8; ++j) {
        float2 ra = *(const float2*)(resid + (size_t)r0 * 64 + 8 * j + 2 * tig);
        float2 rb = *(const float2*)(resid + (size_t)(r0 + 8) * 64 + 8 * j + 2 * tig);
        float a0v = C2[j][0] + ra.x, a1v = C2[j][1] + ra.y;
        float b0v = C2[j][2] + rb.x, b1v = C2[j][3] + rb.y;
        v0[2 * j] = a0v; v0[2 * j + 1] = a1v;
        v1[2 * j] = b0v; v1[2 * j + 1] = b1v;
        s0 += a0v + a1v; q0 += a0v * a0v + a1v * a1v;
        s1 += b0v + b1v; q1 += b0v * b0v + b1v * b1v;
    }
    s0 += __shfl_xor_sync(0xffffffffu, s0, 1); s0 += __shfl_xor_sync(0xffffffffu, s0, 2);
    q0 += __shfl_xor_sync(0xffffffffu, q0, 1); q0 += __shfl_xor_sync(0xffffffffu, q0, 2);
    s1 += __shfl_xor_sync(0xffffffffu, s1, 1); s1 += __shfl_xor_sync(0xffffffffu, s1, 2);
    q1 += __shfl_xor_sync(0xffffffffu, q1, 1); q1 += __shfl_xor_sync(0xffffffffu, q1, 2);
    float m0v = s0 * (1.f / 64.f), m1v = s1 * (1.f / 64.f);
    float i0 = rsqrtf(q0 * (1.f / 64.f) - m0v * m0v + 1e-6f);
    float i1 = rsqrtf(q1 * (1.f / 64.f) - m1v * m1v + 1e-6f);
    float kp0 = keep[r0], kp1 = keep[r0 + 8];
    #pragma unroll
    for (int j = 0; j < 8; ++j) {
        int c = 8 * j + 2 * tig;
        float2 gg = *(const float2*)(g + c);
        float2 bb = *(const float2*)(be + c);
        float2 oa = make_float2(((v0[2 * j] - m0v) * i0 * gg.x + bb.x) * kp0,
                                ((v0[2 * j + 1] - m0v) * i0 * gg.y + bb.y) * kp0);
        float2 ob = make_float2(((v1[2 * j] - m1v) * i1 * gg.x + bb.x) * kp1,
                                ((v1[2 * j + 1] - m1v) * i1 * gg.y + bb.y) * kp1);
        *(float2*)(C + (size_t)r0 * 64 + c) = oa;
        *(float2*)(C + (size_t)(r0 + 8) * 64 + c) = ob;
        int pos = pairpos(c);
        u32 hh, ll;
        split2(oa.x, oa.y, hh, ll);
        *(u32*)&xh[(size_t)r0 * 72 + pos] = hh; *(u32*)&xl[(size_t)r0 * 72 + pos] = ll;
        split2(ob.x, ob.y, hh, ll);
        *(u32*)&xh[(size_t)(r0 + 8) * 72 + pos] = hh; *(u32*)&xl[(size_t)(r0 + 8) * 72 + pos] = ll;
    }
}

// ------------------------- classifier fused -----------------------------------
typedef unsigned long long ull;
__global__ void __launch_bounds__(256) cls_kernel(
    const float* __restrict__ x,
    const float* __restrict__ w1, const float* __restrict__ b1,
    const float* __restrict__ w2, const float* __restrict__ b2,
    const float* __restrict__ w3, const float* __restrict__ b3,
    float* __restrict__ part) {
    __shared__ float Xs[64][65];
    __shared__ __align__(16) float Ws[64][64];
    __shared__ float w3s[64];
    __shared__ float red[256];
    int tid = threadIdx.x;
    int tx = tid & 15, ty = tid >> 4;
    int m0 = blockIdx.x * 64;

    for (int i = tid; i < 64 * 64; i += 256) {
        int r = i >> 6, c = i & 63;
        Xs[r][c] = x[(size_t)(m0 + r) * 64 + c];
        Ws[r][c] = w1[i];
    }
    if (tid < 64) w3s[tid] = w3[tid];
    __syncthreads();

    u64 acc[4][2];
    #pragma unroll
    for (int i = 0; i < 4; ++i) { acc[i][0] = 0ull; acc[i][1] = 0ull; }
    #pragma unroll 8
    for (int kk = 0; kk < 64; ++kk) {
        ulonglong2 w2v = *(const ulonglong2*)&Ws[kk][tx * 4];
        #pragma unroll
        for (int i = 0; i < 4; ++i) {
            float a = Xs[ty * 4 + i][kk];
            u64 ap = pack2(a, a);
            acc[i][0] = fma2(ap, w2v.x, acc[i][0]);
            acc[i][1] = fma2(ap, w2v.y, acc[i][1]);
        }
    }
    __syncthreads();

    float4 b1v = *(const float4*)&b1[tx * 4];
    #pragma unroll
    for (int i = 0; i < 4; ++i) {
        int row = ty * 4 + i;
        float2 p0 = unpack2(acc[i][0]);
        float2 p1 = unpack2(acc[i][1]);
        Xs[row][tx * 4 + 0] = fmaxf(p0.x + b1v.x, 0.f);
        Xs[row][tx * 4 + 1] = fmaxf(p0.y + b1v.y, 0.f);
        Xs[row][tx * 4 + 2] = fmaxf(p1.x + b1v.z, 0.f);
        Xs[row][tx * 4 + 3] = fmaxf(p1.y + b1v.w, 0.f);
    }
    for (int i = tid; i < 64 * 64; i += 256) Ws[i >> 6][i & 63] = w2[i];
    __syncthreads();

    #pragma unroll
    for (int i = 0; i < 4; ++i) { acc[i][0] = 0ull; acc[i][1] = 0ull; }
    #pragma unroll 8
    for (int kk = 0; kk < 64; ++kk) {
        ulonglong2 w2v = *(const ulonglong2*)&Ws[kk][tx * 4];
        #pragma unroll
        for (int i = 0; i < 4; ++i) {
            float a = Xs[ty * 4 + i][kk];
            u64 ap = pack2(a, a);
            acc[i][0] = fma2(ap, w2v.x, acc[i][0]);
            acc[i][1] = fma2(ap, w2v.y, acc[i][1]);
        }
    }

    float4 b2v = *(const float4*)&b2[tx * 4];
    float partial = 0.f;
    #pragma unroll
    for (int i = 0; i < 4; ++i) {
        float2 p0 = unpack2(acc[i][0]);
        float2 p1 = unpack2(acc[i][1]);
        partial += fmaxf(p0.x + b2v.x, 0.f) * w3s[tx * 4 + 0];
        partial += fmaxf(p0.y + b2v.y, 0.f) * w3s[tx * 4 + 1];
        partial += fmaxf(p1.x + b2v.z, 0.f) * w3s[tx * 4 + 2];
        partial += fmaxf(p1.y + b2v.w, 0.f) * w3s[tx * 4 + 3];
    }
    red[tid] = partial;
    __syncthreads();
    for (int st = 128; st > 0; st >>= 1) {
        if (tid < st) red[tid] += red[tid + st];
        __syncthreads();
    }
    if (tid == 0) part[blockIdx.x] = red[0] + 64.f * b3[0];
}

// ------------------------- deterministic final reduction ----------------------
__global__ void reduce_y(const float* __restrict__ part,
                         const float* __restrict__ ob, float* __restrict__ y) {
    int b = threadIdx.x;   // 16
    float s = ob[0];
    #pragma unroll
    for (int i = 0; i < 16; ++i) s += part[b * 16 + i];
    y[b] = s;
}

// ------------------------- launcher ------------------------------------------
extern "C" void kernel_launch(void* const* d_in, const int* in_sizes, int n_in,
                              void* d_out, int out_size) {
    const float* input  = (const float*)d_in[0];
    const float* emb    = (const float*)d_in[1];
    const float* wq     = (const float*)d_in[2];
    const float* wq_b   = (const float*)d_in[3];
    const float* wk     = (const float*)d_in[4];
    const float* wk_b   = (const float*)d_in[5];
    const float* wv     = (const float*)d_in[6];
    const float* wv_b   = (const float*)d_in[7];
    const float* wo     = (const float*)d_in[8];
    const float* ffn_w1 = (const float*)d_in[9];
    const float* ffn_w2 = (const float*)d_in[10];
    const float* ln1_g  = (const float*)d_in[11];
    const float* ln1_b  = (const float*)d_in[12];
    const float* ln2_g  = (const float*)d_in[13];
    const float* ln2_b  = (const float*)d_in[14];
    const float* c_w1   = (const float*)d_in[15];
    const float* c_b1   = (const float*)d_in[16];
    const float* c_w2   = (const float*)d_in[17];
    const float* c_b2   = (const float*)d_in[18];
    const float* c_w3   = (const float*)d_in[19];
    const float* c_b3   = (const float*)d_in[20];
    const float* ob     = (const float*)d_in[21];
    float* y = (float*)d_out;

    float *x, *q, *k, *v, *out1, *keep, *nanf, *part;
    u16 *ws, *wqkvo, *xh, *xl, *cxh, *cxl, *o1h, *o1l;
    cudaGetSymbolAddress((void**)&x,    g_x);
    cudaGetSymbolAddress((void**)&q,    g_q);
    cudaGetSymbolAddress((void**)&k,    g_k);
    cudaGetSymbolAddress((void**)&v,    g_v);
    cudaGetSymbolAddress((void**)&out1, g_out1);
    cudaGetSymbolAddress((void**)&keep, g_keep);
    cudaGetSymbolAddress((void**)&nanf, g_nanf);
    cudaGetSymbolAddress((void**)&part, g_part);
    cudaGetSymbolAddress((void**)&ws,   g_ws);
    cudaGetSymbolAddress((void**)&wqkvo, g_wqkvo);
    cudaGetSymbolAddress((void**)&xh,   g_xh);
    cudaGetSymbolAddress((void**)&xl,   g_xl);
    cudaGetSymbolAddress((void**)&cxh,  g_cxh);
    cudaGetSymbolAddress((void**)&cxl,  g_cxl);
    cudaGetSymbolAddress((void**)&o1h,  g_o1h);
    cudaGetSymbolAddress((void**)&o1l,  g_o1l);

    const int W2_SMEM  = 2 * 4608 * 2;            // 18432 B
    const int FFN_SMEM = 4 * 64 * 72 * 2;         // 36864 B
    cudaFuncSetAttribute(qkv_mma_kernel, cudaFuncAttributeMaxDynamicSharedMemorySize, W2_SMEM);
    cudaFuncSetAttribute(wo_mma_kernel,  cudaFuncAttributeMaxDynamicSharedMemorySize, W2_SMEM);
    cudaFuncSetAttribute(ffn_mma_kernel, cudaFuncAttributeMaxDynamicSharedMemorySize, FFN_SMEM);

    prep_kernel<<<B_, S_>>>(input, keep, nanf);
    build_x_kernel<<<(BS * 32) / 256, 256>>>(input, emb, keep, x, xh, xl);
    wprep_kernel<<<L_ * 4, 256>>>(ffn_w1, ffn_w2, ws);
    wprep_qkvo_kernel<<<L_ * 4, 256>>>(wq, wk, wv, wo, wqkvo);

    for (int l = 0; l < L_; ++l) {
        const u16* wqkv_l = wqkvo + (size_t)l * 8 * 4608;       // q,k,v regions
        const u16* wo_l   = wqkvo + ((size_t)l * 8 + 6) * 4608; // o region

        qkv_mma_kernel<<<dim3(BS / 64, 3), 128, W2_SMEM>>>(
            xh, xl, wqkv_l, wq_b + l * D_, wk_b + l * D_, wv_b + l * D_, q, k, v);
        attn_mma_kernel<<<dim3(S_ / 256, B_ * H_), 256>>>(q, k, v, nanf, cxh, cxl);
        wo_mma_kernel<<<BS / 64, 128, W2_SMEM>>>(
            cxh, cxl, x, wo_l, ln1_g + l * D_, ln1_b + l * D_, keep, out1, o1h, o1l);
        ffn_mma_kernel<<<BS / 64, 128, FFN_SMEM>>>(
            o1h, o1l, out1, ws + (size_t)l * 4 * 4 * 64 * 72,
            ln2_g + l * D_, ln2_b + l * D_, keep, x, xh, xl);
    }

    cls_kernel<<<BS / 64, 256>>>(x, c_w1, c_b1, c_w2, c_b2, c_w3, c_b3, part);
    reduce_y<<<1, 16>>>(part, ob, y);
}

// round 8
// speedup vs baseline: 3.5563x; 1.1468x over previous
#include <cuda_runtime.h>

#define B_  16
#define S_  1024
#define D_  64
#define H_  4
#define DFF 256
#define L_  2
#define BS  (B_ * S_)

typedef unsigned long long u64;
typedef unsigned int u32;
typedef unsigned short u16;

// ------------------------- device scratch ------------------------------------
__device__ float g_x   [BS * D_];
__device__ float g_q   [BS * D_];
__device__ float g_k   [BS * D_];
__device__ float g_v   [BS * D_];
__device__ float g_out1[BS * D_];
__device__ float g_keep[BS];
__device__ float g_nanf[BS];
__device__ float g_part[BS / 64];
__device__ u16   g_ws   [L_ * 4 * 4 * 64 * 72];  // split ffn weights, frag layout
__device__ u16   g_wqkvo[L_ * 8 * 64 * 72];      // split q,k,v,o weights (hi/lo each)
__device__ u16   g_xh  [BS * 72];                // x bf16-hi frag layout
__device__ u16   g_xl  [BS * 72];
__device__ u16   g_cxh [BS * 72];                // ctx split frag layout
__device__ u16   g_cxl [BS * 72];
__device__ u16   g_o1h [BS * 72];                // out1 split frag layout
__device__ u16   g_o1l [BS * 72];

// ------------------------- helpers --------------------------------------------
__device__ __forceinline__ u64 fma2(u64 a, u64 b, u64 c) {
    u64 d; asm("fma.rn.f32x2 %0, %1, %2, %3;" : "=l"(d) : "l"(a), "l"(b), "l"(c)); return d;
}
__device__ __forceinline__ u64 pack2(float x, float y) {
    u64 d; asm("mov.b64 %0, {%1, %2};" : "=l"(d) : "f"(x), "f"(y)); return d;
}
__device__ __forceinline__ float2 unpack2(u64 a) {
    float lo, hi; asm("mov.b64 {%0, %1}, %2;" : "=f"(lo), "=f"(hi) : "l"(a));
    return make_float2(lo, hi);
}
__device__ __forceinline__ float ex2f(float x) {
    float r; asm("ex2.approx.f32 %0, %1;" : "=f"(r) : "f"(x)); return r;
}
__device__ __forceinline__ u32 bf2(float lo, float hi) {
    u32 r; asm("cvt.rn.bf16x2.f32 %0, %1, %2;" : "=r"(r) : "f"(hi), "f"(lo)); return r;
}
__device__ __forceinline__ u16 bf1(float f) {
    u16 h; asm("cvt.rn.bf16.f32 %0, %1;" : "=h"(h) : "f"(f)); return h;
}
__device__ __forceinline__ float bf16f(u16 h) { return __uint_as_float((u32)h << 16); }
__device__ __forceinline__ void mma_bf16(
    float& c0, float& c1, float& c2, float& c3,
    u32 a0, u32 a1, u32 a2, u32 a3, u32 b0, u32 b1) {
    asm volatile(
        "mma.sync.aligned.m16n8k16.row.col.f32.bf16.bf16.f32 "
        "{%0,%1,%2,%3},{%4,%5,%6,%7},{%8,%9},{%0,%1,%2,%3};"
        : "+f"(c0), "+f"(c1), "+f"(c2), "+f"(c3)
        : "r"(a0), "r"(a1), "r"(a2), "r"(a3), "r"(b0), "r"(b1));
}
// permuted k-position inside a 16-group
__device__ __forceinline__ int permpos(int j) {   // j in 0..15
    int p = j >> 1, l = j & 1;
    return (p & 3) * 4 + ((p >> 2) << 1) + l;
}
// pos of an even column pair (c,c+1) in the 72-wide frag row
__device__ __forceinline__ int pairpos(int c) {
    int p = (c & 15) >> 1;
    return (c >> 4) * 16 + (p & 3) * 4 + ((p >> 2) << 1);
}
// split a float pair into hi/lo bf16x2
__device__ __forceinline__ void split2(float a, float b, u32& h, u32& l) {
    h = bf2(a, b);
    l = bf2(a - __uint_as_float(h << 16), b - __uint_as_float(h & 0xffff0000u));
}

// ------------------------- prep: nan flags + keep ----------------------------
__global__ void prep_kernel(const float* __restrict__ in,
                            float* __restrict__ keepv, float* __restrict__ nanf) {
    int b = blockIdx.x;
    int s = threadIdx.x;            // 1024 threads
    float v = in[b * S_ + s];
    bool nan = (v != v);
    unsigned bal = __ballot_sync(0xffffffffu, nan);
    __shared__ int warp_all[32];
    __shared__ int allnan_s;
    if ((s & 31) == 0) warp_all[s >> 5] = (bal == 0xffffffffu);
    __syncthreads();
    if (s == 0) {
        int a = 1;
        #pragma unroll
        for (int i = 0; i < 32; ++i) a &= warp_all[i];
        allnan_s = a;
    }
    __syncthreads();
    float kp = (nan || allnan_s) ? 0.f : 1.f;
    keepv[b * S_ + s] = kp;
    nanf [b * S_ + s] = nan ? 1.f : 0.f;
}

// ------------------------- build x (fp32 + split frag emit) -------------------
__global__ void build_x_kernel(const float* __restrict__ in,
                               const float* __restrict__ emb,
                               const float* __restrict__ keepv,
                               float* __restrict__ x,
                               u16* __restrict__ xh, u16* __restrict__ xl) {
    int idx = blockIdx.x * 256 + threadIdx.x;   // BS*32
    int cp  = idx & 31;
    int row = idx >> 5;
    int s   = row & (S_ - 1);
    int c   = cp * 2;
    float kp = keepv[row];
    const float SQF = 7.93725393319377f * 8.0f;  // sqrt(63)*sqrt(64)
    float v0 = emb[s * 63 + c] * SQF * kp;
    float v1;
    if (c + 1 == 63) {
        float t = in[row];
        v1 = ((t != t) ? 0.f : t) * kp;
    } else {
        v1 = emb[s * 63 + c + 1] * SQF * kp;
    }
    x[row * 64 + c] = v0;
    x[row * 64 + c + 1] = v1;
    int pos = pairpos(c);
    u32 h, l; split2(v0, v1, h, l);
    *(u32*)&xh[(size_t)row * 72 + pos] = h;
    *(u32*)&xl[(size_t)row * 72 + pos] = l;
}

// ------------------------- weight prep: ffn (1 elem/thread) -------------------
__global__ void wprep_kernel(const float* __restrict__ w1, const float* __restrict__ w2,
                             u16* __restrict__ ws) {
    int idx = blockIdx.x * 256 + threadIdx.x;   // [0, L*4*2*4096)
    int region = idx >> 13;                      // 0..7  (l*4+nt)
    int rem    = idx & 8191;
    int which  = rem >> 12;                      // 0=w1, 1=w2
    int i      = rem & 4095;
    int l = region >> 2, nt = region & 3;
    u16* dst = ws + (size_t)region * (4 * 64 * 72);
    int k = i >> 6, n = i & 63;
    int pos = (k >> 4) * 16 + permpos(k & 15);
    if (which == 0) {
        float wa = w1[(size_t)l * 64 * 256 + k * 256 + nt * 64 + n];
        u16 h = bf1(wa);
        dst[0 * 64 * 72 + n * 72 + pos] = h;
        dst[1 * 64 * 72 + n * 72 + pos] = bf1(wa - bf16f(h));
    } else {
        float wb = w2[(size_t)l * 256 * 64 + (nt * 64 + k) * 64 + n];
        u16 h2 = bf1(wb);
        dst[2 * 64 * 72 + n * 72 + pos] = h2;
        dst[3 * 64 * 72 + n * 72 + pos] = bf1(wb - bf16f(h2));
    }
}

// ------------------------- weight prep: q,k,v,o (1 elem/thread) ---------------
__global__ void wprep_qkvo_kernel(const float* __restrict__ wq, const float* __restrict__ wk,
                                  const float* __restrict__ wv, const float* __restrict__ wo,
                                  u16* __restrict__ dstall) {
    int idx = blockIdx.x * 256 + threadIdx.x;   // [0, L*4*4096)
    int region = idx >> 12;                      // 0..7 (l*4+wsel)
    int i      = idx & 4095;
    int l = region >> 2, wsel = region & 3;
    const float* src = (wsel == 0 ? wq : wsel == 1 ? wk : wsel == 2 ? wv : wo) + (size_t)l * 4096;
    u16* dst = dstall + ((size_t)l * 8 + wsel * 2) * 4608;
    int k = i >> 6, n = i & 63;
    int pos = (k >> 4) * 16 + permpos(k & 15);
    float val = src[k * 64 + n];
    u16 h = bf1(val);
    dst[n * 72 + pos]        = h;
    dst[4608 + n * 72 + pos] = bf1(val - bf16f(h));
}

// ------------------------- tensor-core QKV (one weight per block) -------------
__global__ void __launch_bounds__(128) qkv_mma_kernel(
    const u16* __restrict__ xh, const u16* __restrict__ xl,
    const u16* __restrict__ wsplit,   // [3][2][4608] region for this layer
    const float* __restrict__ bq, const float* __restrict__ bk, const float* __restrict__ bv_,
    float* __restrict__ q, float* __restrict__ k, float* __restrict__ v) {
    extern __shared__ u16 sw[];   // 2*4608 u16 = 18432 B
    int tid = threadIdx.x, w = tid >> 5, lane = tid & 31;
    int gid = lane >> 2, tig = lane & 3;
    int m0 = blockIdx.x * 64;
    int wsel = blockIdx.y;
    int r0 = m0 + w * 16 + gid;

    {   // copy this weight's hi/lo (18432 B)
        const float4* src = (const float4*)(wsplit + (size_t)wsel * 2 * 4608);
        float4* dst = (float4*)sw;
        #pragma unroll
        for (int i = 0; i < 9; ++i) dst[tid + i * 128] = src[tid + i * 128];
    }

    u32 Ah[4][4], Al[4][4];
    {
        const u16* ph0 = xh + (size_t)r0 * 72;
        const u16* ph8 = xh + (size_t)(r0 + 8) * 72;
        const u16* pl0 = xl + (size_t)r0 * 72;
        const u16* pl8 = xl + (size_t)(r0 + 8) * 72;
        #pragma unroll
        for (int gk = 0; gk < 4; ++gk) {
            uint2 t0 = *(const uint2*)(ph0 + gk * 16 + tig * 4);
            uint2 t1 = *(const uint2*)(ph8 + gk * 16 + tig * 4);
            Ah[gk][0] = t0.x; Ah[gk][2] = t0.y;
            Ah[gk][1] = t1.x; Ah[gk][3] = t1.y;
            uint2 s0 = *(const uint2*)(pl0 + gk * 16 + tig * 4);
            uint2 s1 = *(const uint2*)(pl8 + gk * 16 + tig * 4);
            Al[gk][0] = s0.x; Al[gk][2] = s0.y;
            Al[gk][1] = s1.x; Al[gk][3] = s1.y;
        }
    }
    __syncthreads();
    const u16* Wh = sw;
    const u16* Wl = sw + 4608;

    float C2[8][4];
    #pragma unroll
    for (int j = 0; j < 8; ++j)
        #pragma unroll
        for (int i = 0; i < 4; ++i) C2[j][i] = 0.f;

    #pragma unroll
    for (int j = 0; j < 8; ++j) {
        #pragma unroll
        for (int t = 0; t < 4; ++t) {
            uint2 bh = *(const uint2*)(Wh + (8 * j + gid) * 72 + t * 16 + tig * 4);
            uint2 bl = *(const uint2*)(Wl + (8 * j + gid) * 72 + t * 16 + tig * 4);
            mma_bf16(C2[j][0], C2[j][1], C2[j][2], C2[j][3], Ah[t][0], Ah[t][1], Ah[t][2], Ah[t][3], bh.x, bh.y);
            mma_bf16(C2[j][0], C2[j][1], C2[j][2], C2[j][3], Ah[t][0], Ah[t][1], Ah[t][2], Ah[t][3], bl.x, bl.y);
            mma_bf16(C2[j][0], C2[j][1], C2[j][2], C2[j][3], Al[t][0], Al[t][1], Al[t][2], Al[t][3], bh.x, bh.y);
        }
    }

    const float* bias = wsel == 0 ? bq : wsel == 1 ? bk : bv_;
    float* out = wsel == 0 ? q : wsel == 1 ? k : v;
    #pragma unroll
    for (int j = 0; j < 8; ++j) {
        int c = 8 * j + 2 * tig;
        float2 bb = *(const float2*)(bias + c);
        *(float2*)(out + (size_t)r0 * 64 + c)       = make_float2(C2[j][0] + bb.x, C2[j][1] + bb.y);
        *(float2*)(out + (size_t)(r0 + 8) * 64 + c) = make_float2(C2[j][2] + bb.x, C2[j][3] + bb.y);
    }
}

// ------------------------- tensor-core flash attention -------------------------
// 256 threads = 8 warps, each warp owns 32 queries. Block: 256 q. Emits split ctx frags.
#define KCHUNK 64
__global__ void __launch_bounds__(256) attn_mma_kernel(
    const float* __restrict__ q, const float* __restrict__ k,
    const float* __restrict__ v, const float* __restrict__ nanf,
    u16* __restrict__ cxh, u16* __restrict__ cxl) {
    __shared__ __align__(16) u16 Qs[256 * 16];
    __shared__ __align__(16) u16 Ks[KCHUNK * 18];
    __shared__ __align__(16) u16 Vt[16 * 66];
    __shared__ float bias[KCHUNK];
    __shared__ float rkeep[256];

    int tid = threadIdx.x;
    int w   = tid >> 5;
    int lane = tid & 31;
    int gid = lane >> 2;
    int tig = lane & 3;
    int bh = blockIdx.y;
    int b = bh >> 2, h = bh & 3;
    int qbase = blockIdx.x * 256;
    size_t bS = (size_t)b * S_;

    const float SC = 0.25f * 1.4426950408889634f;

    #pragma unroll
    for (int it = 0; it < 4; ++it) {
        int idx = tid + it * 256;
        int qq = idx >> 2, d4 = idx & 3;
        float4 f = *(const float4*)(q + (bS + qbase + qq) * 64 + h * 16 + d4 * 4);
        *(u32*)((char*)Qs + qq * 32 + d4 * 8)     = bf2(f.x * SC, f.y * SC);
        *(u32*)((char*)Qs + qq * 32 + d4 * 8 + 4) = bf2(f.z * SC, f.w * SC);
    }
    rkeep[tid] = (nanf[bS + qbase + tid] == 0.f) ? 1.f : 0.f;
    __syncthreads();

    u32 qa[2][4];
    #pragma unroll
    for (int s = 0; s < 2; ++s) {
        int row = w * 32 + s * 16 + gid;
        qa[s][0] = *(const u32*)((char*)Qs + row * 32 + tig * 4);
        qa[s][1] = *(const u32*)((char*)Qs + (row + 8) * 32 + tig * 4);
        qa[s][2] = *(const u32*)((char*)Qs + row * 32 + tig * 4 + 16);
        qa[s][3] = *(const u32*)((char*)Qs + (row + 8) * 32 + tig * 4 + 16);
    }

    float z[2][2] = {{0.f, 0.f}, {0.f, 0.f}};
    float cd[2][2][4];
    #pragma unroll
    for (int s = 0; s < 2; ++s)
        #pragma unroll
        for (int dt = 0; dt < 2; ++dt)
            #pragma unroll
            for (int i = 0; i < 4; ++i) cd[s][dt][i] = 0.f;

    for (int ch = 0; ch < S_ / KCHUNK; ++ch) {
        __syncthreads();
        int kg = ch * KCHUNK;
        {
            int key = tid >> 2, d4 = tid & 3;
            float4 kf = *(const float4*)(k + (bS + kg + key) * 64 + h * 16 + d4 * 4);
            *(u32*)((char*)Ks + key * 36 + d4 * 8)     = bf2(kf.x, kf.y);
            *(u32*)((char*)Ks + key * 36 + d4 * 8 + 4) = bf2(kf.z, kf.w);
            float4 vf = *(const float4*)(v + (bS + kg + key) * 64 + h * 16 + d4 * 4);
            Vt[(d4 * 4 + 0) * 66 + key] = bf1(vf.x);
            Vt[(d4 * 4 + 1) * 66 + key] = bf1(vf.y);
            Vt[(d4 * 4 + 2) * 66 + key] = bf1(vf.z);
            Vt[(d4 * 4 + 3) * 66 + key] = bf1(vf.w);
            if (tid < KCHUNK) bias[tid] = (nanf[bS + kg + tid] != 0.f) ? -1e30f : 0.f;
        }
        __syncthreads();

        #pragma unroll
        for (int kb = 0; kb < KCHUNK; kb += 16) {
            u32 kb0a = *(const u32*)((char*)Ks + (kb + gid) * 36 + tig * 4);
            u32 kb1a = *(const u32*)((char*)Ks + (kb + gid) * 36 + tig * 4 + 16);
            u32 kb0b = *(const u32*)((char*)Ks + (kb + 8 + gid) * 36 + tig * 4);
            u32 kb1b = *(const u32*)((char*)Ks + (kb + 8 + gid) * 36 + tig * 4 + 16);
            u32 vb00 = *(const u32*)((char*)Vt + (gid * 66 + kb + 2 * tig) * 2);
            u32 vb01 = *(const u32*)((char*)Vt + (gid * 66 + kb + 8 + 2 * tig) * 2);
            u32 vb10 = *(const u32*)((char*)Vt + ((gid + 8) * 66 + kb + 2 * tig) * 2);
            u32 vb11 = *(const u32*)((char*)Vt + ((gid + 8) * 66 + kb + 8 + 2 * tig) * 2);
            float2 bv0 = *(const float2*)(bias + kb + 2 * tig);
            float2 bv1 = *(const float2*)(bias + kb + 8 + 2 * tig);

            #pragma unroll
            for (int s = 0; s < 2; ++s) {
                float c0 = 0.f, c1 = 0.f, c2 = 0.f, c3 = 0.f;
                mma_bf16(c0, c1, c2, c3, qa[s][0], qa[s][1], qa[s][2], qa[s][3], kb0a, kb1a);
                float d0 = 0.f, d1 = 0.f, d2 = 0.f, d3 = 0.f;
                mma_bf16(d0, d1, d2, d3, qa[s][0], qa[s][1], qa[s][2], qa[s][3], kb0b, kb1b);

                float p0 = ex2f(c0 + bv0.x), p1 = ex2f(c1 + bv0.y);
                float p2 = ex2f(c2 + bv0.x), p3 = ex2f(c3 + bv0.y);
                float p4 = ex2f(d0 + bv1.x), p5 = ex2f(d1 + bv1.y);
                float p6 = ex2f(d2 + bv1.x), p7 = ex2f(d3 + bv1.y);
                z[s][0] += (p0 + p1) + (p4 + p5);
                z[s][1] += (p2 + p3) + (p6 + p7);

                u32 pa0 = bf2(p0, p1), pa1 = bf2(p2, p3);
                u32 pa2 = bf2(p4, p5), pa3 = bf2(p6, p7);
                mma_bf16(cd[s][0][0], cd[s][0][1], cd[s][0][2], cd[s][0][3],
                         pa0, pa1, pa2, pa3, vb00, vb01);
                mma_bf16(cd[s][1][0], cd[s][1][1], cd[s][1][2], cd[s][1][3],
                         pa0, pa1, pa2, pa3, vb10, vb11);
            }
        }
    }

    int posA = h * 16 + tig * 4;       // dt=0 pair
    int posB = posA + 2;               // dt=1 pair
    #pragma unroll
    for (int s = 0; s < 2; ++s) {
        float z0 = z[s][0], z1 = z[s][1];
        z0 += __shfl_xor_sync(0xffffffffu, z0, 1);
        z0 += __shfl_xor_sync(0xffffffffu, z0, 2);
        z1 += __shfl_xor_sync(0xffffffffu, z1, 1);
        z1 += __shfl_xor_sync(0xffffffffu, z1, 2);

        int q0 = w * 32 + s * 16 + gid;
        int q1 = q0 + 8;
        float rk0 = rkeep[q0], rk1 = rkeep[q1];
        float rz0 = (rk0 != 0.f && z0 > 0.f) ? (1.f / z0) : 0.f;
        float rz1 = (rk1 != 0.f && z1 > 0.f) ? (1.f / z1) : 0.f;

        size_t row0 = (bS + qbase + q0) * 72;
        size_t row1 = (bS + qbase + q1) * 72;
        u32 hh, ll;
        split2(cd[s][0][0] * rz0, cd[s][0][1] * rz0, hh, ll);
        *(u32*)&cxh[row0 + posA] = hh; *(u32*)&cxl[row0 + posA] = ll;
        split2(cd[s][1][0] * rz0, cd[s][1][1] * rz0, hh, ll);
        *(u32*)&cxh[row0 + posB] = hh; *(u32*)&cxl[row0 + posB] = ll;
        split2(cd[s][0][2] * rz1, cd[s][0][3] * rz1, hh, ll);
        *(u32*)&cxh[row1 + posA] = hh; *(u32*)&cxl[row1 + posA] = ll;
        split2(cd[s][1][2] * rz1, cd[s][1][3] * rz1, hh, ll);
        *(u32*)&cxh[row1 + posB] = hh; *(u32*)&cxl[row1 + posB] = ll;
    }
}

// ------------------------- tensor-core WO GEMM + resid + LN + keep -------------
__global__ void __launch_bounds__(128) wo_mma_kernel(
    const u16* __restrict__ cxh, const u16* __restrict__ cxl,
    const float* __restrict__ resid, const u16* __restrict__ wsplit,
    const float* __restrict__ g, const float* __restrict__ be,
    const float* __restrict__ keep, float* __restrict__ out1,
    u16* __restrict__ o1h, u16* __restrict__ o1l) {
    extern __shared__ u16 sw[];   // 2*4608 u16
    int tid = threadIdx.x, w = tid >> 5, lane = tid & 31;
    int gid = lane >> 2, tig = lane & 3;
    int m0 = blockIdx.x * 64;
    int r0 = m0 + w * 16 + gid;

    {
        const float4* src = (const float4*)wsplit;
        float4* dst = (float4*)sw;
        #pragma unroll
        for (int i = 0; i < 9; ++i) dst[tid + i * 128] = src[tid + i * 128];
    }

    u32 Ah[4][4], Al[4][4];
    {
        const u16* ph0 = cxh + (size_t)r0 * 72;
        const u16* ph8 = cxh + (size_t)(r0 + 8) * 72;
        const u16* pl0 = cxl + (size_t)r0 * 72;
        const u16* pl8 = cxl + (size_t)(r0 + 8) * 72;
        #pragma unroll
        for (int gk = 0; gk < 4; ++gk) {
            uint2 t0 = *(const uint2*)(ph0 + gk * 16 + tig * 4);
            uint2 t1 = *(const uint2*)(ph8 + gk * 16 + tig * 4);
            Ah[gk][0] = t0.x; Ah[gk][2] = t0.y;
            Ah[gk][1] = t1.x; Ah[gk][3] = t1.y;
            uint2 s0 = *(const uint2*)(pl0 + gk * 16 + tig * 4);
            uint2 s1 = *(const uint2*)(pl8 + gk * 16 + tig * 4);
            Al[gk][0] = s0.x; Al[gk][2] = s0.y;
            Al[gk][1] = s1.x; Al[gk][3] = s1.y;
        }
    }
    __syncthreads();
    const u16* Wh = sw;
    const u16* Wl = sw + 4608;

    float C2[8][4];
    #pragma unroll
    for (int j = 0; j < 8; ++j)
        #pragma unroll
        for (int i = 0; i < 4; ++i) C2[j][i] = 0.f;

    #pragma unroll
    for (int j = 0; j < 8; ++j) {
        #pragma unroll
        for (int t = 0; t < 4; ++t) {
            uint2 bh = *(const uint2*)(Wh + (8 * j + gid) * 72 + t * 16 + tig * 4);
            uint2 bl = *(const uint2*)(Wl + (8 * j + gid) * 72 + t * 16 + tig * 4);
            mma_bf16(C2[j][0], C2[j][1], C2[j][2], C2[j][3], Ah[t][0], Ah[t][1], Ah[t][2], Ah[t][3], bh.x, bh.y);
            mma_bf16(C2[j][0], C2[j][1], C2[j][2], C2[j][3], Ah[t][0], Ah[t][1], Ah[t][2], Ah[t][3], bl.x, bl.y);
            mma_bf16(C2[j][0], C2[j][1], C2[j][2], C2[j][3], Al[t][0], Al[t][1], Al[t][2], Al[t][3], bh.x, bh.y);
        }
    }

    // epilogue: + resid, LN, keep, write fp32 + split frags
    float v0[16], v1[16];
    float s0 = 0.f, q0 = 0.f, s1 = 0.f, q1 = 0.f;
    #pragma unroll
    for (int j = 0; j < 8; ++j) {
        float2 ra = *(const float2*)(resid + (size_t)r0 * 64 + 8 * j + 2 * tig);
        float2 rb = *(const float2*)(resid + (size_t)(r0 + 8) * 64 + 8 * j + 2 * tig);
        float a0v = C2[j][0] + ra.x, a1v = C2[j][1] + ra.y;
        float b0v = C2[j][2] + rb.x, b1v = C2[j][3] + rb.y;
        v0[2 * j] = a0v; v0[2 * j + 1] = a1v;
        v1[2 * j] = b0v; v1[2 * j + 1] = b1v;
        s0 += a0v + a1v; q0 += a0v * a0v + a1v * a1v;
        s1 += b0v + b1v; q1 += b0v * b0v + b1v * b1v;
    }
    s0 += __shfl_xor_sync(0xffffffffu, s0, 1); s0 += __shfl_xor_sync(0xffffffffu, s0, 2);
    q0 += __shfl_xor_sync(0xffffffffu, q0, 1); q0 += __shfl_xor_sync(0xffffffffu, q0, 2);
    s1 += __shfl_xor_sync(0xffffffffu, s1, 1); s1 += __shfl_xor_sync(0xffffffffu, s1, 2);
    q1 += __shfl_xor_sync(0xffffffffu, q1, 1); q1 += __shfl_xor_sync(0xffffffffu, q1, 2);
    float m0v = s0 * (1.f / 64.f), m1v = s1 * (1.f / 64.f);
    float i0 = rsqrtf(q0 * (1.f / 64.f) - m0v * m0v + 1e-6f);
    float i1 = rsqrtf(q1 * (1.f / 64.f) - m1v * m1v + 1e-6f);
    float kp0 = keep[r0], kp1 = keep[r0 + 8];
    #pragma unroll
    for (int j = 0; j < 8; ++j) {
        int c = 8 * j + 2 * tig;
        float2 gg = *(const float2*)(g + c);
        float2 bb = *(const float2*)(be + c);
        float2 oa = make_float2(((v0[2 * j] - m0v) * i0 * gg.x + bb.x) * kp0,
                                ((v0[2 * j + 1] - m0v) * i0 * gg.y + bb.y) * kp0);
        float2 ob = make_float2(((v1[2 * j] - m1v) * i1 * gg.x + bb.x) * kp1,
                                ((v1[2 * j + 1] - m1v) * i1 * gg.y + bb.y) * kp1);
        *(float2*)(out1 + (size_t)r0 * 64 + c) = oa;
        *(float2*)(out1 + (size_t)(r0 + 8) * 64 + c) = ob;
        int pos = pairpos(c);
        u32 hh, ll;
        split2(oa.x, oa.y, hh, ll);
        *(u32*)&o1h[(size_t)r0 * 72 + pos] = hh; *(u32*)&o1l[(size_t)r0 * 72 + pos] = ll;
        split2(ob.x, ob.y, hh, ll);
        *(u32*)&o1h[(size_t)(r0 + 8) * 72 + pos] = hh; *(u32*)&o1l[(size_t)(r0 + 8) * 72 + pos] = ll;
    }
}

// ------------------------- tensor-core FFN (bf16-split, 3-mma) ----------------
__global__ void __launch_bounds__(128) ffn_mma_kernel(
    const u16* __restrict__ a_h, const u16* __restrict__ a_l,
    const float* __restrict__ resid, const u16* __restrict__ ws,
    const float* __restrict__ g, const float* __restrict__ be,
    const float* __restrict__ keep, float* __restrict__ C,
    u16* __restrict__ xh, u16* __restrict__ xl) {
    extern __shared__ u16 sw[];   // 4 * 64 * 72 u16 = 36864 B
    int tid = threadIdx.x, w = tid >> 5, lane = tid & 31;
    int gid = lane >> 2, tig = lane & 3;
    int m0 = blockIdx.x * 64;
    int r0 = m0 + w * 16 + gid;

    u32 Ah[4][4], Al[4][4];
    {
        const u16* ph0 = a_h + (size_t)r0 * 72;
        const u16* ph8 = a_h + (size_t)(r0 + 8) * 72;
        const u16* pl0 = a_l + (size_t)r0 * 72;
        const u16* pl8 = a_l + (size_t)(r0 + 8) * 72;
        #pragma unroll
        for (int gk = 0; gk < 4; ++gk) {
            uint2 t0 = *(const uint2*)(ph0 + gk * 16 + tig * 4);
            uint2 t1 = *(const uint2*)(ph8 + gk * 16 + tig * 4);
            Ah[gk][0] = t0.x; Ah[gk][2] = t0.y;
            Ah[gk][1] = t1.x; Ah[gk][3] = t1.y;
            uint2 s0 = *(const uint2*)(pl0 + gk * 16 + tig * 4);
            uint2 s1 = *(const uint2*)(pl8 + gk * 16 + tig * 4);
            Al[gk][0] = s0.x; Al[gk][2] = s0.y;
            Al[gk][1] = s1.x; Al[gk][3] = s1.y;
        }
    }

    float C2[8][4];
    #pragma unroll
    for (int j = 0; j < 8; ++j)
        #pragma unroll
        for (int i = 0; i < 4; ++i) C2[j][i] = 0.f;

    for (int nt = 0; nt < 4; ++nt) {
        __syncthreads();
        {
            const float4* src = (const float4*)(ws + (size_t)nt * 4 * 64 * 72);
            float4* dst = (float4*)sw;
            #pragma unroll
            for (int i = 0; i < 18; ++i) dst[tid + i * 128] = src[tid + i * 128];
        }
        __syncthreads();
        const u16* W1h = sw;
        const u16* W1l = sw + 64 * 72;
        const u16* W2h = sw + 2 * 64 * 72;
        const u16* W2l = sw + 3 * 64 * 72;

        u32 A2h[4][4], A2l[4][4];
        #pragma unroll
        for (int t = 0; t < 4; ++t) {
            float Ca[4] = {0.f, 0.f, 0.f, 0.f};
            float Cb[4] = {0.f, 0.f, 0.f, 0.f};
            #pragma unroll
            for (int gk = 0; gk < 4; ++gk) {
                uint2 bha = *(const uint2*)(W1h + (16 * t + gid) * 72 + gk * 16 + tig * 4);
                uint2 bla = *(const uint2*)(W1l + (16 * t + gid) * 72 + gk * 16 + tig * 4);
                mma_bf16(Ca[0], Ca[1], Ca[2], Ca[3], Ah[gk][0], Ah[gk][1], Ah[gk][2], Ah[gk][3], bha.x, bha.y);
                mma_bf16(Ca[0], Ca[1], Ca[2], Ca[3], Ah[gk][0], Ah[gk][1], Ah[gk][2], Ah[gk][3], bla.x, bla.y);
                mma_bf16(Ca[0], Ca[1], Ca[2], Ca[3], Al[gk][0], Al[gk][1], Al[gk][2], Al[gk][3], bha.x, bha.y);
                uint2 bhb = *(const uint2*)(W1h + (16 * t + 8 + gid) * 72 + gk * 16 + tig * 4);
                uint2 blb = *(const uint2*)(W1l + (16 * t + 8 + gid) * 72 + gk * 16 + tig * 4);
                mma_bf16(Cb[0], Cb[1], Cb[2], Cb[3], Ah[gk][0], Ah[gk][1], Ah[gk][2], Ah[gk][3], bhb.x, bhb.y);
                mma_bf16(Cb[0], Cb[1], Cb[2], Cb[3], Ah[gk][0], Ah[gk][1], Ah[gk][2], Ah[gk][3], blb.x, blb.y);
                mma_bf16(Cb[0], Cb[1], Cb[2], Cb[3], Al[gk][0], Al[gk][1], Al[gk][2], Al[gk][3], bhb.x, bhb.y);
            }
            #pragma unroll
            for (int i = 0; i < 4; ++i) { Ca[i] = fmaxf(Ca[i], 0.f); Cb[i] = fmaxf(Cb[i], 0.f); }
            u32 h0 = bf2(Ca[0], Ca[1]);
            A2h[t][0] = h0;
            A2l[t][0] = bf2(Ca[0] - __uint_as_float(h0 << 16), Ca[1] - __uint_as_float(h0 & 0xffff0000u));
            u32 h1 = bf2(Ca[2], Ca[3]);
            A2h[t][1] = h1;
            A2l[t][1] = bf2(Ca[2] - __uint_as_float(h1 << 16), Ca[3] - __uint_as_float(h1 & 0xffff0000u));
            u32 h2 = bf2(Cb[0], Cb[1]);
            A2h[t][2] = h2;
            A2l[t][2] = bf2(Cb[0] - __uint_as_float(h2 << 16), Cb[1] - __uint_as_float(h2 & 0xffff0000u));
            u32 h3 = bf2(Cb[2], Cb[3]);
            A2h[t][3] = h3;
            A2l[t][3] = bf2(Cb[2] - __uint_as_float(h3 << 16), Cb[3] - __uint_as_float(h3 & 0xffff0000u));
        }

        #pragma unroll
        for (int j = 0; j < 8; ++j) {
            #pragma unroll
            for (int t = 0; t < 4; ++t) {
                uint2 bh = *(const uint2*)(W2h + (8 * j + gid) * 72 + t * 16 + tig * 4);
                uint2 bl = *(const uint2*)(W2l + (8 * j + gid) * 72 + t * 16 + tig * 4);
                mma_bf16(C2[j][0], C2[j][1], C2[j][2], C2[j][3], A2h[t][0], A2h[t][1], A2h[t][2], A2h[t][3], bh.x, bh.y);
                mma_bf16(C2[j][0], C2[j][1], C2[j][2], C2[j][3], A2h[t][0], A2h[t][1], A2h[t][2], A2h[t][3], bl.x, bl.y);
                mma_bf16(C2[j][0], C2[j][1], C2[j][2], C2[j][3], A2l[t][0], A2l[t][1], A2l[t][2], A2l[t][3], bh.x, bh.y);
            }
        }
    }

    float v0[16], v1[16];
    float s0 = 0.f, q0 = 0.f, s1 = 0.f, q1 = 0.f;
    #pragma unroll
    for (int j = 0; j < 8; ++j) {
        float2 ra = *(const float2*)(resid + (size_t)r0 * 64 + 8 * j + 2 * tig);
        float2 rb = *(const float2*)(resid + (size_t)(r0 + 8) * 64 + 8 * j + 2 * tig);
        float a0v = C2[j][0] + ra.x, a1v = C2[j][1] + ra.y;
        float b0v = C2[j][2] + rb.x, b1v = C2[j][3] + rb.y;
        v0[2 * j] = a0v; v0[2 * j + 1] = a1v;
        v1[2 * j] = b0v; v1[2 * j + 1] = b1v;
        s0 += a0v + a1v; q0 += a0v * a0v + a1v * a1v;
        s1 += b0v + b1v; q1 += b0v * b0v + b1v * b1v;
    }
    s0 += __shfl_xor_sync(0xffffffffu, s0, 1); s0 += __shfl_xor_sync(0xffffffffu, s0, 2);
    q0 += __shfl_xor_sync(0xffffffffu, q0, 1); q0 += __shfl_xor_sync(0xffffffffu, q0, 2);
    s1 += __shfl_xor_sync(0xffffffffu, s1, 1); s1 += __shfl_xor_sync(0xffffffffu, s1, 2);
    q1 += __shfl_xor_sync(0xffffffffu, q1, 1); q1 += __shfl_xor_sync(0xffffffffu, q1, 2);
    float m0v = s0 * (1.f / 64.f), m1v = s1 * (1.f / 64.f);
    float i0 = rsqrtf(q0 * (1.f / 64.f) - m0v * m0v + 1e-6f);
    float i1 = rsqrtf(q1 * (1.f / 64.f) - m1v * m1v + 1e-6f);
    float kp0 = keep[r0], kp1 = keep[r0 + 8];
    #pragma unroll
    for (int j = 0; j < 8; ++j) {
        int c = 8 * j + 2 * tig;
        float2 gg = *(const float2*)(g + c);
        float2 bb = *(const float2*)(be + c);
        float2 oa = make_float2(((v0[2 * j] - m0v) * i0 * gg.x + bb.x) * kp0,
                                ((v0[2 * j + 1] - m0v) * i0 * gg.y + bb.y) * kp0);
        float2 ob = make_float2(((v1[2 * j] - m1v) * i1 * gg.x + bb.x) * kp1,
                                ((v1[2 * j + 1] - m1v) * i1 * gg.y + bb.y) * kp1);
        *(float2*)(C + (size_t)r0 * 64 + c) = oa;
        *(float2*)(C + (size_t)(r0 + 8) * 64 + c) = ob;
        int pos = pairpos(c);
        u32 hh, ll;
        split2(oa.x, oa.y, hh, ll);
        *(u32*)&xh[(size_t)r0 * 72 + pos] = hh; *(u32*)&xl[(size_t)r0 * 72 + pos] = ll;
        split2(ob.x, ob.y, hh, ll);
        *(u32*)&xh[(size_t)(r0 + 8) * 72 + pos] = hh; *(u32*)&xl[(size_t)(r0 + 8) * 72 + pos] = ll;
    }
}

// ------------------------- classifier fused -----------------------------------
__global__ void __launch_bounds__(256) cls_kernel(
    const float* __restrict__ x,
    const float* __restrict__ w1, const float* __restrict__ b1,
    const float* __restrict__ w2, const float* __restrict__ b2,
    const float* __restrict__ w3, const float* __restrict__ b3,
    float* __restrict__ part) {
    __shared__ float Xs[64][65];
    __shared__ __align__(16) float Ws[64][64];
    __shared__ float w3s[64];
    __shared__ float red[256];
    int tid = threadIdx.x;
    int tx = tid & 15, ty = tid >> 4;
    int m0 = blockIdx.x * 64;

    for (int i = tid; i < 64 * 64; i += 256) {
        int r = i >> 6, c = i & 63;
        Xs[r][c] = x[(size_t)(m0 + r) * 64 + c];
        Ws[r][c] = w1[i];
    }
    if (tid < 64) w3s[tid] = w3[tid];
    __syncthreads();

    u64 acc[4][2];
    #pragma unroll
    for (int i = 0; i < 4; ++i) { acc[i][0] = 0ull; acc[i][1] = 0ull; }
    #pragma unroll 8
    for (int kk = 0; kk < 64; ++kk) {
        ulonglong2 w2v = *(const ulonglong2*)&Ws[kk][tx * 4];
        #pragma unroll
        for (int i = 0; i < 4; ++i) {
            float a = Xs[ty * 4 + i][kk];
            u64 ap = pack2(a, a);
            acc[i][0] = fma2(ap, w2v.x, acc[i][0]);
            acc[i][1] = fma2(ap, w2v.y, acc[i][1]);
        }
    }
    __syncthreads();

    float4 b1v = *(const float4*)&b1[tx * 4];
    #pragma unroll
    for (int i = 0; i < 4; ++i) {
        int row = ty * 4 + i;
        float2 p0 = unpack2(acc[i][0]);
        float2 p1 = unpack2(acc[i][1]);
        Xs[row][tx * 4 + 0] = fmaxf(p0.x + b1v.x, 0.f);
        Xs[row][tx * 4 + 1] = fmaxf(p0.y + b1v.y, 0.f);
        Xs[row][tx * 4 + 2] = fmaxf(p1.x + b1v.z, 0.f);
        Xs[row][tx * 4 + 3] = fmaxf(p1.y + b1v.w, 0.f);
    }
    for (int i = tid; i < 64 * 64; i += 256) Ws[i >> 6][i & 63] = w2[i];
    __syncthreads();

    #pragma unroll
    for (int i = 0; i < 4; ++i) { acc[i][0] = 0ull; acc[i][1] = 0ull; }
    #pragma unroll 8
    for (int kk = 0; kk < 64; ++kk) {
        ulonglong2 w2v = *(const ulonglong2*)&Ws[kk][tx * 4];
        #pragma unroll
        for (int i = 0; i < 4; ++i) {
            float a = Xs[ty * 4 + i][kk];
            u64 ap = pack2(a, a);
            acc[i][0] = fma2(ap, w2v.x, acc[i][0]);
            acc[i][1] = fma2(ap, w2v.y, acc[i][1]);
        }
    }

    float4 b2v = *(const float4*)&b2[tx * 4];
    float partial = 0.f;
    #pragma unroll
    for (int i = 0; i < 4; ++i) {
        float2 p0 = unpack2(acc[i][0]);
        float2 p1 = unpack2(acc[i][1]);
        partial += fmaxf(p0.x + b2v.x, 0.f) * w3s[tx * 4 + 0];
        partial += fmaxf(p0.y + b2v.y, 0.f) * w3s[tx * 4 + 1];
        partial += fmaxf(p1.x + b2v.z, 0.f) * w3s[tx * 4 + 2];
        partial += fmaxf(p1.y + b2v.w, 0.f) * w3s[tx * 4 + 3];
    }
    red[tid] = partial;
    __syncthreads();
    for (int st = 128; st > 0; st >>= 1) {
        if (tid < st) red[tid] += red[tid + st];
        __syncthreads();
    }
    if (tid == 0) part[blockIdx.x] = red[0] + 64.f * b3[0];
}

// ------------------------- deterministic final reduction ----------------------
__global__ void reduce_y(const float* __restrict__ part,
                         const float* __restrict__ ob, float* __restrict__ y) {
    int b = threadIdx.x;   // 16
    float s = ob[0];
    #pragma unroll
    for (int i = 0; i < 16; ++i) s += part[b * 16 + i];
    y[b] = s;
}

// ------------------------- launcher ------------------------------------------
extern "C" void kernel_launch(void* const* d_in, const int* in_sizes, int n_in,
                              void* d_out, int out_size) {
    const float* input  = (const float*)d_in[0];
    const float* emb    = (const float*)d_in[1];
    const float* wq     = (const float*)d_in[2];
    const float* wq_b   = (const float*)d_in[3];
    const float* wk     = (const float*)d_in[4];
    const float* wk_b   = (const float*)d_in[5];
    const float* wv     = (const float*)d_in[6];
    const float* wv_b   = (const float*)d_in[7];
    const float* wo     = (const float*)d_in[8];
    const float* ffn_w1 = (const float*)d_in[9];
    const float* ffn_w2 = (const float*)d_in[10];
    const float* ln1_g  = (const float*)d_in[11];
    const float* ln1_b  = (const float*)d_in[12];
    const float* ln2_g  = (const float*)d_in[13];
    const float* ln2_b  = (const float*)d_in[14];
    const float* c_w1   = (const float*)d_in[15];
    const float* c_b1   = (const float*)d_in[16];
    const float* c_w2   = (const float*)d_in[17];
    const float* c_b2   = (const float*)d_in[18];
    const float* c_w3   = (const float*)d_in[19];
    const float* c_b3   = (const float*)d_in[20];
    const float* ob     = (const float*)d_in[21];
    float* y = (float*)d_out;

    float *x, *q, *k, *v, *out1, *keep, *nanf, *part;
    u16 *ws, *wqkvo, *xh, *xl, *cxh, *cxl, *o1h, *o1l;
    cudaGetSymbolAddress((void**)&x,    g_x);
    cudaGetSymbolAddress((void**)&q,    g_q);
    cudaGetSymbolAddress((void**)&k,    g_k);
    cudaGetSymbolAddress((void**)&v,    g_v);
    cudaGetSymbolAddress((void**)&out1, g_out1);
    cudaGetSymbolAddress((void**)&keep, g_keep);
    cudaGetSymbolAddress((void**)&nanf, g_nanf);
    cudaGetSymbolAddress((void**)&part, g_part);
    cudaGetSymbolAddress((void**)&ws,   g_ws);
    cudaGetSymbolAddress((void**)&wqkvo, g_wqkvo);
    cudaGetSymbolAddress((void**)&xh,   g_xh);
    cudaGetSymbolAddress((void**)&xl,   g_xl);
    cudaGetSymbolAddress((void**)&cxh,  g_cxh);
    cudaGetSymbolAddress((void**)&cxl,  g_cxl);
    cudaGetSymbolAddress((void**)&o1h,  g_o1h);
    cudaGetSymbolAddress((void**)&o1l,  g_o1l);

    const int W2_SMEM  = 2 * 4608 * 2;            // 18432 B
    const int FFN_SMEM = 4 * 64 * 72 * 2;         // 36864 B
    cudaFuncSetAttribute(qkv_mma_kernel, cudaFuncAttributeMaxDynamicSharedMemorySize, W2_SMEM);
    cudaFuncSetAttribute(wo_mma_kernel,  cudaFuncAttributeMaxDynamicSharedMemorySize, W2_SMEM);
    cudaFuncSetAttribute(ffn_mma_kernel, cudaFuncAttributeMaxDynamicSharedMemorySize, FFN_SMEM);

    prep_kernel<<<B_, S_>>>(input, keep, nanf);
    build_x_kernel<<<(BS * 32) / 256, 256>>>(input, emb, keep, x, xh, xl);
    wprep_kernel<<<(L_ * 4 * 2 * 4096) / 256, 256>>>(ffn_w1, ffn_w2, ws);
    wprep_qkvo_kernel<<<(L_ * 4 * 4096) / 256, 256>>>(wq, wk, wv, wo, wqkvo);

    for (int l = 0; l < L_; ++l) {
        const u16* wqkv_l = wqkvo + (size_t)l * 8 * 4608;       // q,k,v regions
        const u16* wo_l   = wqkvo + ((size_t)l * 8 + 6) * 4608; // o region

        qkv_mma_kernel<<<dim3(BS / 64, 3), 128, W2_SMEM>>>(
            xh, xl, wqkv_l, wq_b + l * D_, wk_b + l * D_, wv_b + l * D_, q, k, v);
        attn_mma_kernel<<<dim3(S_ / 256, B_ * H_), 256>>>(q, k, v, nanf, cxh, cxl);
        wo_mma_kernel<<<BS / 64, 128, W2_SMEM>>>(
            cxh, cxl, x, wo_l, ln1_g + l * D_, ln1_b + l * D_, keep, out1, o1h, o1l);
        ffn_mma_kernel<<<BS / 64, 128, FFN_SMEM>>>(
            o1h, o1l, out1, ws + (size_t)l * 4 * 4 * 64 * 72,
            ln2_g + l * D_, ln2_b + l * D_, keep, x, xh, xl);
    }

    cls_kernel<<<BS / 64, 256>>>(x, c_w1, c_b1, c_w2, c_b2, c_w3, c_b3, part);
    reduce_y<<<1, 16>>>(part, ob, y);
}

// round 9
// speedup vs baseline: 3.7350x; 1.0503x over previous
#include <cuda_runtime.h>

#define B_  16
#define S_  1024
#define D_  64
#define H_  4
#define DFF 256
#define L_  2
#define BS  (B_ * S_)

typedef unsigned long long u64;
typedef unsigned int u32;
typedef unsigned short u16;

// ------------------------- device scratch ------------------------------------
__device__ float g_x   [BS * D_];
__device__ float g_q   [BS * D_];
__device__ float g_k   [BS * D_];
__device__ float g_v   [BS * D_];
__device__ float g_out1[BS * D_];
__device__ float g_keep[BS];
__device__ float g_nanf[BS];
__device__ float g_part[BS / 64];
__device__ u16   g_ws   [L_ * 4 * 4 * 64 * 72];  // split ffn weights, frag layout
__device__ u16   g_wqkvo[L_ * 8 * 64 * 72];      // split q,k,v,o weights (hi/lo each)
__device__ u16   g_xh  [BS * 72];                // x bf16-hi frag layout
__device__ u16   g_xl  [BS * 72];
__device__ u16   g_cxh [BS * 72];                // ctx split frag layout
__device__ u16   g_cxl [BS * 72];
__device__ u16   g_o1h [BS * 72];                // out1 split frag layout
__device__ u16   g_o1l [BS * 72];

// ------------------------- helpers --------------------------------------------
__device__ __forceinline__ u64 fma2(u64 a, u64 b, u64 c) {
    u64 d; asm("fma.rn.f32x2 %0, %1, %2, %3;" : "=l"(d) : "l"(a), "l"(b), "l"(c)); return d;
}
__device__ __forceinline__ u64 pack2(float x, float y) {
    u64 d; asm("mov.b64 %0, {%1, %2};" : "=l"(d) : "f"(x), "f"(y)); return d;
}
__device__ __forceinline__ float2 unpack2(u64 a) {
    float lo, hi; asm("mov.b64 {%0, %1}, %2;" : "=f"(lo), "=f"(hi) : "l"(a));
    return make_float2(lo, hi);
}
__device__ __forceinline__ float ex2f(float x) {
    float r; asm("ex2.approx.f32 %0, %1;" : "=f"(r) : "f"(x)); return r;
}
__device__ __forceinline__ u32 bf2(float lo, float hi) {
    u32 r; asm("cvt.rn.bf16x2.f32 %0, %1, %2;" : "=r"(r) : "f"(hi), "f"(lo)); return r;
}
__device__ __forceinline__ u16 bf1(float f) {
    u16 h; asm("cvt.rn.bf16.f32 %0, %1;" : "=h"(h) : "f"(f)); return h;
}
__device__ __forceinline__ float bf16f(u16 h) { return __uint_as_float((u32)h << 16); }
__device__ __forceinline__ void mma_bf16(
    float& c0, float& c1, float& c2, float& c3,
    u32 a0, u32 a1, u32 a2, u32 a3, u32 b0, u32 b1) {
    asm volatile(
        "mma.sync.aligned.m16n8k16.row.col.f32.bf16.bf16.f32 "
        "{%0,%1,%2,%3},{%4,%5,%6,%7},{%8,%9},{%0,%1,%2,%3};"
        : "+f"(c0), "+f"(c1), "+f"(c2), "+f"(c3)
        : "r"(a0), "r"(a1), "r"(a2), "r"(a3), "r"(b0), "r"(b1));
}
// permuted k-position inside a 16-group
__device__ __forceinline__ int permpos(int j) {   // j in 0..15
    int p = j >> 1, l = j & 1;
    return (p & 3) * 4 + ((p >> 2) << 1) + l;
}
// pos of an even column pair (c,c+1) in the 72-wide frag row
__device__ __forceinline__ int pairpos(int c) {
    int p = (c & 15) >> 1;
    return (c >> 4) * 16 + (p & 3) * 4 + ((p >> 2) << 1);
}
// split a float pair into hi/lo bf16x2
__device__ __forceinline__ void split2(float a, float b, u32& h, u32& l) {
    h = bf2(a, b);
    l = bf2(a - __uint_as_float(h << 16), b - __uint_as_float(h & 0xffff0000u));
}

// ------------------------- prep: nan flags + keep ----------------------------
__global__ void prep_kernel(const float* __restrict__ in,
                            float* __restrict__ keepv, float* __restrict__ nanf) {
    int b = blockIdx.x;
    int s = threadIdx.x;            // 1024 threads
    float v = in[b * S_ + s];
    bool nan = (v != v);
    unsigned bal = __ballot_sync(0xffffffffu, nan);
    __shared__ int warp_all[32];
    __shared__ int allnan_s;
    if ((s & 31) == 0) warp_all[s >> 5] = (bal == 0xffffffffu);
    __syncthreads();
    if (s == 0) {
        int a = 1;
        #pragma unroll
        for (int i = 0; i < 32; ++i) a &= warp_all[i];
        allnan_s = a;
    }
    __syncthreads();
    float kp = (nan || allnan_s) ? 0.f : 1.f;
    keepv[b * S_ + s] = kp;
    nanf [b * S_ + s] = nan ? 1.f : 0.f;
}

// ------------------------- build x (fp32 + split frag emit) -------------------
__global__ void build_x_kernel(const float* __restrict__ in,
                               const float* __restrict__ emb,
                               const float* __restrict__ keepv,
                               float* __restrict__ x,
                               u16* __restrict__ xh, u16* __restrict__ xl) {
    int idx = blockIdx.x * 256 + threadIdx.x;   // BS*32
    int cp  = idx & 31;
    int row = idx >> 5;
    int s   = row & (S_ - 1);
    int c   = cp * 2;
    float kp = keepv[row];
    const float SQF = 7.93725393319377f * 8.0f;  // sqrt(63)*sqrt(64)
    float v0 = emb[s * 63 + c] * SQF * kp;
    float v1;
    if (c + 1 == 63) {
        float t = in[row];
        v1 = ((t != t) ? 0.f : t) * kp;
    } else {
        v1 = emb[s * 63 + c + 1] * SQF * kp;
    }
    x[row * 64 + c] = v0;
    x[row * 64 + c + 1] = v1;
    int pos = pairpos(c);
    u32 h, l; split2(v0, v1, h, l);
    *(u32*)&xh[(size_t)row * 72 + pos] = h;
    *(u32*)&xl[(size_t)row * 72 + pos] = l;
}

// ------------------------- unified weight prep (1 elem/thread) ----------------
// blocks [0,128): qkvo weights;  blocks [128,384): ffn weights
__global__ void wprep_all_kernel(
    const float* __restrict__ wq, const float* __restrict__ wk,
    const float* __restrict__ wv, const float* __restrict__ wo,
    const float* __restrict__ w1, const float* __restrict__ w2,
    u16* __restrict__ dstqkvo, u16* __restrict__ ws) {
    if (blockIdx.x < 128) {
        int idx = blockIdx.x * 256 + threadIdx.x;   // [0, L*4*4096)
        int region = idx >> 12;
        int i      = idx & 4095;
        int l = region >> 2, wsel = region & 3;
        const float* src = (wsel == 0 ? wq : wsel == 1 ? wk : wsel == 2 ? wv : wo) + (size_t)l * 4096;
        u16* dst = dstqkvo + ((size_t)l * 8 + wsel * 2) * 4608;
        int k = i >> 6, n = i & 63;
        int pos = (k >> 4) * 16 + permpos(k & 15);
        float val = src[k * 64 + n];
        u16 h = bf1(val);
        dst[n * 72 + pos]        = h;
        dst[4608 + n * 72 + pos] = bf1(val - bf16f(h));
    } else {
        int idx = (blockIdx.x - 128) * 256 + threadIdx.x;   // [0, L*4*2*4096)
        int region = idx >> 13;
        int rem    = idx & 8191;
        int which  = rem >> 12;
        int i      = rem & 4095;
        int l = region >> 2, nt = region & 3;
        u16* dst = ws + (size_t)region * (4 * 64 * 72);
        int k = i >> 6, n = i & 63;
        int pos = (k >> 4) * 16 + permpos(k & 15);
        if (which == 0) {
            float wa = w1[(size_t)l * 64 * 256 + k * 256 + nt * 64 + n];
            u16 h = bf1(wa);
            dst[0 * 64 * 72 + n * 72 + pos] = h;
            dst[1 * 64 * 72 + n * 72 + pos] = bf1(wa - bf16f(h));
        } else {
            float wb = w2[(size_t)l * 256 * 64 + (nt * 64 + k) * 64 + n];
            u16 h2 = bf1(wb);
            dst[2 * 64 * 72 + n * 72 + pos] = h2;
            dst[3 * 64 * 72 + n * 72 + pos] = bf1(wb - bf16f(h2));
        }
    }
}

// ------------------------- tensor-core QKV (one weight per block) -------------
__global__ void __launch_bounds__(128) qkv_mma_kernel(
    const u16* __restrict__ xh, const u16* __restrict__ xl,
    const u16* __restrict__ wsplit,   // [3][2][4608] region for this layer
    const float* __restrict__ bq, const float* __restrict__ bk, const float* __restrict__ bv_,
    float* __restrict__ q, float* __restrict__ k, float* __restrict__ v) {
    extern __shared__ u16 sw[];   // 2*4608 u16 = 18432 B
    int tid = threadIdx.x, w = tid >> 5, lane = tid & 31;
    int gid = lane >> 2, tig = lane & 3;
    int m0 = blockIdx.x * 64;
    int wsel = blockIdx.y;
    int r0 = m0 + w * 16 + gid;

    {   // copy this weight's hi/lo (18432 B)
        const float4* src = (const float4*)(wsplit + (size_t)wsel * 2 * 4608);
        float4* dst = (float4*)sw;
        #pragma unroll
        for (int i = 0; i < 9; ++i) dst[tid + i * 128] = src[tid + i * 128];
    }

    u32 Ah[4][4], Al[4][4];
    {
        const u16* ph0 = xh + (size_t)r0 * 72;
        const u16* ph8 = xh + (size_t)(r0 + 8) * 72;
        const u16* pl0 = xl + (size_t)r0 * 72;
        const u16* pl8 = xl + (size_t)(r0 + 8) * 72;
        #pragma unroll
        for (int gk = 0; gk < 4; ++gk) {
            uint2 t0 = *(const uint2*)(ph0 + gk * 16 + tig * 4);
            uint2 t1 = *(const uint2*)(ph8 + gk * 16 + tig * 4);
            Ah[gk][0] = t0.x; Ah[gk][2] = t0.y;
            Ah[gk][1] = t1.x; Ah[gk][3] = t1.y;
            uint2 s0 = *(const uint2*)(pl0 + gk * 16 + tig * 4);
            uint2 s1 = *(const uint2*)(pl8 + gk * 16 + tig * 4);
            Al[gk][0] = s0.x; Al[gk][2] = s0.y;
            Al[gk][1] = s1.x; Al[gk][3] = s1.y;
        }
    }
    __syncthreads();
    const u16* Wh = sw;
    const u16* Wl = sw + 4608;

    float C2[8][4];
    #pragma unroll
    for (int j = 0; j < 8; ++j)
        #pragma unroll
        for (int i = 0; i < 4; ++i) C2[j][i] = 0.f;

    #pragma unroll
    for (int j = 0; j < 8; ++j) {
        #pragma unroll
        for (int t = 0; t < 4; ++t) {
            uint2 bh = *(const uint2*)(Wh + (8 * j + gid) * 72 + t * 16 + tig * 4);
            uint2 bl = *(const uint2*)(Wl + (8 * j + gid) * 72 + t * 16 + tig * 4);
            mma_bf16(C2[j][0], C2[j][1], C2[j][2], C2[j][3], Ah[t][0], Ah[t][1], Ah[t][2], Ah[t][3], bh.x, bh.y);
            mma_bf16(C2[j][0], C2[j][1], C2[j][2], C2[j][3], Ah[t][0], Ah[t][1], Ah[t][2], Ah[t][3], bl.x, bl.y);
            mma_bf16(C2[j][0], C2[j][1], C2[j][2], C2[j][3], Al[t][0], Al[t][1], Al[t][2], Al[t][3], bh.x, bh.y);
        }
    }

    const float* bias = wsel == 0 ? bq : wsel == 1 ? bk : bv_;
    float* out = wsel == 0 ? q : wsel == 1 ? k : v;
    #pragma unroll
    for (int j = 0; j < 8; ++j) {
        int c = 8 * j + 2 * tig;
        float2 bb = *(const float2*)(bias + c);
        *(float2*)(out + (size_t)r0 * 64 + c)       = make_float2(C2[j][0] + bb.x, C2[j][1] + bb.y);
        *(float2*)(out + (size_t)(r0 + 8) * 64 + c) = make_float2(C2[j][2] + bb.x, C2[j][3] + bb.y);
    }
}

// ------------------------- tensor-core flash attention -------------------------
// 256 threads = 8 warps, each warp owns 32 queries. Block: 256 q.
// Double-buffered K/V staging, bias folded into mma accumulator init.
#define KCHUNK 64
__global__ void __launch_bounds__(256) attn_mma_kernel(
    const float* __restrict__ q, const float* __restrict__ k,
    const float* __restrict__ v, const float* __restrict__ nanf,
    u16* __restrict__ cxh, u16* __restrict__ cxl) {
    __shared__ __align__(16) u16 Qs[256 * 16];
    __shared__ __align__(16) u16 Ks[2][KCHUNK * 18];
    __shared__ __align__(16) u16 Vt[2][16 * 66];
    __shared__ float bias[2][KCHUNK];
    __shared__ float rkeep[256];

    int tid = threadIdx.x;
    int w   = tid >> 5;
    int lane = tid & 31;
    int gid = lane >> 2;
    int tig = lane & 3;
    int bh = blockIdx.y;
    int b = bh >> 2, h = bh & 3;
    int qbase = blockIdx.x * 256;
    size_t bS = (size_t)b * S_;

    const float SC = 0.25f * 1.4426950408889634f;
    int key = tid >> 2, d4 = tid & 3;

    // stage chunk 0 (issue loads before Q work to overlap)
    float4 kf0 = *(const float4*)(k + (bS + key) * 64 + h * 16 + d4 * 4);
    float4 vf0 = *(const float4*)(v + (bS + key) * 64 + h * 16 + d4 * 4);
    float bb0 = 0.f;
    if (tid < KCHUNK) bb0 = (nanf[bS + tid] != 0.f) ? -1e30f : 0.f;

    #pragma unroll
    for (int it = 0; it < 4; ++it) {
        int idx = tid + it * 256;
        int qq = idx >> 2, dd = idx & 3;
        float4 f = *(const float4*)(q + (bS + qbase + qq) * 64 + h * 16 + dd * 4);
        *(u32*)((char*)Qs + qq * 32 + dd * 8)     = bf2(f.x * SC, f.y * SC);
        *(u32*)((char*)Qs + qq * 32 + dd * 8 + 4) = bf2(f.z * SC, f.w * SC);
    }
    rkeep[tid] = (nanf[bS + qbase + tid] == 0.f) ? 1.f : 0.f;

    {
        *(u32*)((char*)Ks[0] + key * 36 + d4 * 8)     = bf2(kf0.x, kf0.y);
        *(u32*)((char*)Ks[0] + key * 36 + d4 * 8 + 4) = bf2(kf0.z, kf0.w);
        Vt[0][(d4 * 4 + 0) * 66 + key] = bf1(vf0.x);
        Vt[0][(d4 * 4 + 1) * 66 + key] = bf1(vf0.y);
        Vt[0][(d4 * 4 + 2) * 66 + key] = bf1(vf0.z);
        Vt[0][(d4 * 4 + 3) * 66 + key] = bf1(vf0.w);
        if (tid < KCHUNK) bias[0][tid] = bb0;
    }
    __syncthreads();

    u32 qa[2][4];
    #pragma unroll
    for (int s = 0; s < 2; ++s) {
        int row = w * 32 + s * 16 + gid;
        qa[s][0] = *(const u32*)((char*)Qs + row * 32 + tig * 4);
        qa[s][1] = *(const u32*)((char*)Qs + (row + 8) * 32 + tig * 4);
        qa[s][2] = *(const u32*)((char*)Qs + row * 32 + tig * 4 + 16);
        qa[s][3] = *(const u32*)((char*)Qs + (row + 8) * 32 + tig * 4 + 16);
    }

    float z[2][2] = {{0.f, 0.f}, {0.f, 0.f}};
    float cd[2][2][4];
    #pragma unroll
    for (int s = 0; s < 2; ++s)
        #pragma unroll
        for (int dt = 0; dt < 2; ++dt)
            #pragma unroll
            for (int i = 0; i < 4; ++i) cd[s][dt][i] = 0.f;

    for (int ch = 0; ch < S_ / KCHUNK; ++ch) {
        int cur = ch & 1;
        // prefetch next chunk into registers
        float4 kfn, vfn; float bbn = 0.f;
        if (ch + 1 < S_ / KCHUNK) {
            size_t nb = bS + (ch + 1) * KCHUNK;
            kfn = *(const float4*)(k + (nb + key) * 64 + h * 16 + d4 * 4);
            vfn = *(const float4*)(v + (nb + key) * 64 + h * 16 + d4 * 4);
            if (tid < KCHUNK) bbn = (nanf[nb + tid] != 0.f) ? -1e30f : 0.f;
        }

        const u16* KsC = Ks[cur];
        const u16* VtC = Vt[cur];
        const float* biC = bias[cur];

        #pragma unroll
        for (int kb = 0; kb < KCHUNK; kb += 16) {
            u32 kb0a = *(const u32*)((char*)KsC + (kb + gid) * 36 + tig * 4);
            u32 kb1a = *(const u32*)((char*)KsC + (kb + gid) * 36 + tig * 4 + 16);
            u32 kb0b = *(const u32*)((char*)KsC + (kb + 8 + gid) * 36 + tig * 4);
            u32 kb1b = *(const u32*)((char*)KsC + (kb + 8 + gid) * 36 + tig * 4 + 16);
            u32 vb00 = *(const u32*)((char*)VtC + (gid * 66 + kb + 2 * tig) * 2);
            u32 vb01 = *(const u32*)((char*)VtC + (gid * 66 + kb + 8 + 2 * tig) * 2);
            u32 vb10 = *(const u32*)((char*)VtC + ((gid + 8) * 66 + kb + 2 * tig) * 2);
            u32 vb11 = *(const u32*)((char*)VtC + ((gid + 8) * 66 + kb + 8 + 2 * tig) * 2);
            float2 bv0 = *(const float2*)(biC + kb + 2 * tig);
            float2 bv1 = *(const float2*)(biC + kb + 8 + 2 * tig);

            #pragma unroll
            for (int s = 0; s < 2; ++s) {
                float c0 = bv0.x, c1 = bv0.y, c2 = bv0.x, c3 = bv0.y;
                mma_bf16(c0, c1, c2, c3, qa[s][0], qa[s][1], qa[s][2], qa[s][3], kb0a, kb1a);
                float d0 = bv1.x, d1 = bv1.y, d2 = bv1.x, d3 = bv1.y;
                mma_bf16(d0, d1, d2, d3, qa[s][0], qa[s][1], qa[s][2], qa[s][3], kb0b, kb1b);

                float p0 = ex2f(c0), p1 = ex2f(c1);
                float p2 = ex2f(c2), p3 = ex2f(c3);
                float p4 = ex2f(d0), p5 = ex2f(d1);
                float p6 = ex2f(d2), p7 = ex2f(d3);
                z[s][0] += (p0 + p1) + (p4 + p5);
                z[s][1] += (p2 + p3) + (p6 + p7);

                u32 pa0 = bf2(p0, p1), pa1 = bf2(p2, p3);
                u32 pa2 = bf2(p4, p5), pa3 = bf2(p6, p7);
                mma_bf16(cd[s][0][0], cd[s][0][1], cd[s][0][2], cd[s][0][3],
                         pa0, pa1, pa2, pa3, vb00, vb01);
                mma_bf16(cd[s][1][0], cd[s][1][1], cd[s][1][2], cd[s][1][3],
                         pa0, pa1, pa2, pa3, vb10, vb11);
            }
        }

        if (ch + 1 < S_ / KCHUNK) {
            int nxt = cur ^ 1;
            *(u32*)((char*)Ks[nxt] + key * 36 + d4 * 8)     = bf2(kfn.x, kfn.y);
            *(u32*)((char*)Ks[nxt] + key * 36 + d4 * 8 + 4) = bf2(kfn.z, kfn.w);
            Vt[nxt][(d4 * 4 + 0) * 66 + key] = bf1(vfn.x);
            Vt[nxt][(d4 * 4 + 1) * 66 + key] = bf1(vfn.y);
            Vt[nxt][(d4 * 4 + 2) * 66 + key] = bf1(vfn.z);
            Vt[nxt][(d4 * 4 + 3) * 66 + key] = bf1(vfn.w);
            if (tid < KCHUNK) bias[nxt][tid] = bbn;
            __syncthreads();
        }
    }

    int posA = h * 16 + tig * 4;       // dt=0 pair
    int posB = posA + 2;               // dt=1 pair
    #pragma unroll
    for (int s = 0; s < 2; ++s) {
        float z0 = z[s][0], z1 = z[s][1];
        z0 += __shfl_xor_sync(0xffffffffu, z0, 1);
        z0 += __shfl_xor_sync(0xffffffffu, z0, 2);
        z1 += __shfl_xor_sync(0xffffffffu, z1, 1);
        z1 += __shfl_xor_sync(0xffffffffu, z1, 2);

        int q0 = w * 32 + s * 16 + gid;
        int q1 = q0 + 8;
        float rk0 = rkeep[q0], rk1 = rkeep[q1];
        float rz0 = (rk0 != 0.f && z0 > 0.f) ? (1.f / z0) : 0.f;
        float rz1 = (rk1 != 0.f && z1 > 0.f) ? (1.f / z1) : 0.f;

        size_t row0 = (bS + qbase + q0) * 72;
        size_t row1 = (bS + qbase + q1) * 72;
        u32 hh, ll;
        split2(cd[s][0][0] * rz0, cd[s][0][1] * rz0, hh, ll);
        *(u32*)&cxh[row0 + posA] = hh; *(u32*)&cxl[row0 + posA] = ll;
        split2(cd[s][1][0] * rz0, cd[s][1][1] * rz0, hh, ll);
        *(u32*)&cxh[row0 + posB] = hh; *(u32*)&cxl[row0 + posB] = ll;
        split2(cd[s][0][2] * rz1, cd[s][0][3] * rz1, hh, ll);
        *(u32*)&cxh[row1 + posA] = hh; *(u32*)&cxl[row1 + posA] = ll;
        split2(cd[s][1][2] * rz1, cd[s][1][3] * rz1, hh, ll);
        *(u32*)&cxh[row1 + posB] = hh; *(u32*)&cxl[row1 + posB] = ll;
    }
}

// ------------------------- tensor-core WO GEMM + resid + LN + keep -------------
__global__ void __launch_bounds__(128) wo_mma_kernel(
    const u16* __restrict__ cxh, const u16* __restrict__ cxl,
    const float* __restrict__ resid, const u16* __restrict__ wsplit,
    const float* __restrict__ g, const float* __restrict__ be,
    const float* __restrict__ keep, float* __restrict__ out1,
    u16* __restrict__ o1h, u16* __restrict__ o1l) {
    extern __shared__ u16 sw[];   // 2*4608 u16
    int tid = threadIdx.x, w = tid >> 5, lane = tid & 31;
    int gid = lane >> 2, tig = lane & 3;
    int m0 = blockIdx.x * 64;
    int r0 = m0 + w * 16 + gid;

    {
        const float4* src = (const float4*)wsplit;
        float4* dst = (float4*)sw;
        #pragma unroll
        for (int i = 0; i < 9; ++i) dst[tid + i * 128] = src[tid + i * 128];
    }

    u32 Ah[4][4], Al[4][4];
    {
        const u16* ph0 = cxh + (size_t)r0 * 72;
        const u16* ph8 = cxh + (size_t)(r0 + 8) * 72;
        const u16* pl0 = cxl + (size_t)r0 * 72;
        const u16* pl8 = cxl + (size_t)(r0 + 8) * 72;
        #pragma unroll
        for (int gk = 0; gk < 4; ++gk) {
            uint2 t0 = *(const uint2*)(ph0 + gk * 16 + tig * 4);
            uint2 t1 = *(const uint2*)(ph8 + gk * 16 + tig * 4);
            Ah[gk][0] = t0.x; Ah[gk][2] = t0.y;
            Ah[gk][1] = t1.x; Ah[gk][3] = t1.y;
            uint2 s0 = *(const uint2*)(pl0 + gk * 16 + tig * 4);
            uint2 s1 = *(const uint2*)(pl8 + gk * 16 + tig * 4);
            Al[gk][0] = s0.x; Al[gk][2] = s0.y;
            Al[gk][1] = s1.x; Al[gk][3] = s1.y;
        }
    }
    __syncthreads();
    const u16* Wh = sw;
    const u16* Wl = sw + 4608;

    float C2[8][4];
    #pragma unroll
    for (int j = 0; j < 8; ++j)
        #pragma unroll
        for (int i = 0; i < 4; ++i) C2[j][i] = 0.f;

    #pragma unroll
    for (int j = 0; j < 8; ++j) {
        #pragma unroll
        for (int t = 0; t < 4; ++t) {
            uint2 bh = *(const uint2*)(Wh + (8 * j + gid) * 72 + t * 16 + tig * 4);
            uint2 bl = *(const uint2*)(Wl + (8 * j + gid) * 72 + t * 16 + tig * 4);
            mma_bf16(C2[j][0], C2[j][1], C2[j][2], C2[j][3], Ah[t][0], Ah[t][1], Ah[t][2], Ah[t][3], bh.x, bh.y);
            mma_bf16(C2[j][0], C2[j][1], C2[j][2], C2[j][3], Ah[t][0], Ah[t][1], Ah[t][2], Ah[t][3], bl.x, bl.y);
            mma_bf16(C2[j][0], C2[j][1], C2[j][2], C2[j][3], Al[t][0], Al[t][1], Al[t][2], Al[t][3], bh.x, bh.y);
        }
    }

    // epilogue: + resid, LN, keep, write fp32 + split frags
    float v0[16], v1[16];
    float s0 = 0.f, q0 = 0.f, s1 = 0.f, q1 = 0.f;
    #pragma unroll
    for (int j = 0; j < 8; ++j) {
        float2 ra = *(const float2*)(resid + (size_t)r0 * 64 + 8 * j + 2 * tig);
        float2 rb = *(const float2*)(resid + (size_t)(r0 + 8) * 64 + 8 * j + 2 * tig);
        float a0v = C2[j][0] + ra.x, a1v = C2[j][1] + ra.y;
        float b0v = C2[j][2] + rb.x, b1v = C2[j][3] + rb.y;
        v0[2 * j] = a0v; v0[2 * j + 1] = a1v;
        v1[2 * j] = b0v; v1[2 * j + 1] = b1v;
        s0 += a0v + a1v; q0 += a0v * a0v + a1v * a1v;
        s1 += b0v + b1v; q1 += b0v * b0v + b1v * b1v;
    }
    s0 += __shfl_xor_sync(0xffffffffu, s0, 1); s0 += __shfl_xor_sync(0xffffffffu, s0, 2);
    q0 += __shfl_xor_sync(0xffffffffu, q0, 1); q0 += __shfl_xor_sync(0xffffffffu, q0, 2);
    s1 += __shfl_xor_sync(0xffffffffu, s1, 1); s1 += __shfl_xor_sync(0xffffffffu, s1, 2);
    q1 += __shfl_xor_sync(0xffffffffu, q1, 1); q1 += __shfl_xor_sync(0xffffffffu, q1, 2);
    float m0v = s0 * (1.f / 64.f), m1v = s1 * (1.f / 64.f);
    float i0 = rsqrtf(q0 * (1.f / 64.f) - m0v * m0v + 1e-6f);
    float i1 = rsqrtf(q1 * (1.f / 64.f) - m1v * m1v + 1e-6f);
    float kp0 = keep[r0], kp1 = keep[r0 + 8];
    #pragma unroll
    for (int j = 0; j < 8; ++j) {
        int c = 8 * j + 2 * tig;
        float2 gg = *(const float2*)(g + c);
        float2 bb = *(const float2*)(be + c);
        float2 oa = make_float2(((v0[2 * j] - m0v) * i0 * gg.x + bb.x) * kp0,
                                ((v0[2 * j + 1] - m0v) * i0 * gg.y + bb.y) * kp0);
        float2 ob = make_float2(((v1[2 * j] - m1v) * i1 * gg.x + bb.x) * kp1,
                                ((v1[2 * j + 1] - m1v) * i1 * gg.y + bb.y) * kp1);
        *(float2*)(out1 + (size_t)r0 * 64 + c) = oa;
        *(float2*)(out1 + (size_t)(r0 + 8) * 64 + c) = ob;
        int pos = pairpos(c);
        u32 hh, ll;
        split2(oa.x, oa.y, hh, ll);
        *(u32*)&o1h[(size_t)r0 * 72 + pos] = hh; *(u32*)&o1l[(size_t)r0 * 72 + pos] = ll;
        split2(ob.x, ob.y, hh, ll);
        *(u32*)&o1h[(size_t)(r0 + 8) * 72 + pos] = hh; *(u32*)&o1l[(size_t)(r0 + 8) * 72 + pos] = ll;
    }
}

// ------------------------- tensor-core FFN (bf16-split, 3-mma) ----------------
__global__ void __launch_bounds__(128) ffn_mma_kernel(
    const u16* __restrict__ a_h, const u16* __restrict__ a_l,
    const float* __restrict__ resid, const u16* __restrict__ ws,
    const float* __restrict__ g, const float* __restrict__ be,
    const float* __restrict__ keep, float* __restrict__ C,
    u16* __restrict__ xh, u16* __restrict__ xl) {
    extern __shared__ u16 sw[];   // 4 * 64 * 72 u16 = 36864 B
    int tid = threadIdx.x, w = tid >> 5, lane = tid & 31;
    int gid = lane >> 2, tig = lane & 3;
    int m0 = blockIdx.x * 64;
    int r0 = m0 + w * 16 + gid;

    u32 Ah[4][4], Al[4][4];
    {
        const u16* ph0 = a_h + (size_t)r0 * 72;
        const u16* ph8 = a_h + (size_t)(r0 + 8) * 72;
        const u16* pl0 = a_l + (size_t)r0 * 72;
        const u16* pl8 = a_l + (size_t)(r0 + 8) * 72;
        #pragma unroll
        for (int gk = 0; gk < 4; ++gk) {
            uint2 t0 = *(const uint2*)(ph0 + gk * 16 + tig * 4);
            uint2 t1 = *(const uint2*)(ph8 + gk * 16 + tig * 4);
            Ah[gk][0] = t0.x; Ah[gk][2] = t0.y;
            Ah[gk][1] = t1.x; Ah[gk][3] = t1.y;
            uint2 s0 = *(const uint2*)(pl0 + gk * 16 + tig * 4);
            uint2 s1 = *(const uint2*)(pl8 + gk * 16 + tig * 4);
            Al[gk][0] = s0.x; Al[gk][2] = s0.y;
            Al[gk][1] = s1.x; Al[gk][3] = s1.y;
        }
    }

    float C2[8][4];
    #pragma unroll
    for (int j = 0; j < 8; ++j)
        #pragma unroll
        for (int i = 0; i < 4; ++i) C2[j][i] = 0.f;

    for (int nt = 0; nt < 4; ++nt) {
        __syncthreads();
        {
            const float4* src = (const float4*)(ws + (size_t)nt * 4 * 64 * 72);
            float4* dst = (float4*)sw;
            #pragma unroll
            for (int i = 0; i < 18; ++i) dst[tid + i * 128] = src[tid + i * 128];
        }
        __syncthreads();
        const u16* W1h = sw;
        const u16* W1l = sw + 64 * 72;
        const u16* W2h = sw + 2 * 64 * 72;
        const u16* W2l = sw + 3 * 64 * 72;

        u32 A2h[4][4], A2l[4][4];
        #pragma unroll
        for (int t = 0; t < 4; ++t) {
            float Ca[4] = {0.f, 0.f, 0.f, 0.f};
            float Cb[4] = {0.f, 0.f, 0.f, 0.f};
            #pragma unroll
            for (int gk = 0; gk < 4; ++gk) {
                uint2 bha = *(const uint2*)(W1h + (16 * t + gid) * 72 + gk * 16 + tig * 4);
                uint2 bla = *(const uint2*)(W1l + (16 * t + gid) * 72 + gk * 16 + tig * 4);
                mma_bf16(Ca[0], Ca[1], Ca[2], Ca[3], Ah[gk][0], Ah[gk][1], Ah[gk][2], Ah[gk][3], bha.x, bha.y);
                mma_bf16(Ca[0], Ca[1], Ca[2], Ca[3], Ah[gk][0], Ah[gk][1], Ah[gk][2], Ah[gk][3], bla.x, bla.y);
                mma_bf16(Ca[0], Ca[1], Ca[2], Ca[3], Al[gk][0], Al[gk][1], Al[gk][2], Al[gk][3], bha.x, bha.y);
                uint2 bhb = *(const uint2*)(W1h + (16 * t + 8 + gid) * 72 + gk * 16 + tig * 4);
                uint2 blb = *(const uint2*)(W1l + (16 * t + 8 + gid) * 72 + gk * 16 + tig * 4);
                mma_bf16(Cb[0], Cb[1], Cb[2], Cb[3], Ah[gk][0], Ah[gk][1], Ah[gk][2], Ah[gk][3], bhb.x, bhb.y);
                mma_bf16(Cb[0], Cb[1], Cb[2], Cb[3], Ah[gk][0], Ah[gk][1], Ah[gk][2], Ah[gk][3], blb.x, blb.y);
                mma_bf16(Cb[0], Cb[1], Cb[2], Cb[3], Al[gk][0], Al[gk][1], Al[gk][2], Al[gk][3], bhb.x, bhb.y);
            }
            #pragma unroll
            for (int i = 0; i < 4; ++i) { Ca[i] = fmaxf(Ca[i], 0.f); Cb[i] = fmaxf(Cb[i], 0.f); }
            u32 h0 = bf2(Ca[0], Ca[1]);
            A2h[t][0] = h0;
            A2l[t][0] = bf2(Ca[0] - __uint_as_float(h0 << 16), Ca[1] - __uint_as_float(h0 & 0xffff0000u));
            u32 h1 = bf2(Ca[2], Ca[3]);
            A2h[t][1] = h1;
            A2l[t][1] = bf2(Ca[2] - __uint_as_float(h1 << 16), Ca[3] - __uint_as_float(h1 & 0xffff0000u));
            u32 h2 = bf2(Cb[0], Cb[1]);
            A2h[t][2] = h2;
            A2l[t][2] = bf2(Cb[0] - __uint_as_float(h2 << 16), Cb[1] - __uint_as_float(h2 & 0xffff0000u));
            u32 h3 = bf2(Cb[2], Cb[3]);
            A2h[t][3] = h3;
            A2l[t][3] = bf2(Cb[2] - __uint_as_float(h3 << 16), Cb[3] - __uint_as_float(h3 & 0xffff0000u));
        }

        #pragma unroll
        for (int j = 0; j < 8; ++j) {
            #pragma unroll
            for (int t = 0; t < 4; ++t) {
                uint2 bh = *(const uint2*)(W2h + (8 * j + gid) * 72 + t * 16 + tig * 4);
                uint2 bl = *(const uint2*)(W2l + (8 * j + gid) * 72 + t * 16 + tig * 4);
                mma_bf16(C2[j][0], C2[j][1], C2[j][2], C2[j][3], A2h[t][0], A2h[t][1], A2h[t][2], A2h[t][3], bh.x, bh.y);
                mma_bf16(C2[j][0], C2[j][1], C2[j][2], C2[j][3], A2h[t][0], A2h[t][1], A2h[t][2], A2h[t][3], bl.x, bl.y);
                mma_bf16(C2[j][0], C2[j][1], C2[j][2], C2[j][3], A2l[t][0], A2l[t][1], A2l[t][2], A2l[t][3], bh.x, bh.y);
            }
        }
    }

    float v0[16], v1[16];
    float s0 = 0.f, q0 = 0.f, s1 = 0.f, q1 = 0.f;
    #pragma unroll
    for (int j = 0; j < 8; ++j) {
        float2 ra = *(const float2*)(resid + (size_t)r0 * 64 + 8 * j + 2 * tig);
        float2 rb = *(const float2*)(resid + (size_t)(r0 + 8) * 64 + 8 * j + 2 * tig);
        float a0v = C2[j][0] + ra.x, a1v = C2[j][1] + ra.y;
        float b0v = C2[j][2] + rb.x, b1v = C2[j][3] + rb.y;
        v0[2 * j] = a0v; v0[2 * j + 1] = a1v;
        v1[2 * j] = b0v; v1[2 * j + 1] = b1v;
        s0 += a0v + a1v; q0 += a0v * a0v + a1v * a1v;
        s1 += b0v + b1v; q1 += b0v * b0v + b1v * b1v;
    }
    s0 += __shfl_xor_sync(0xffffffffu, s0, 1); s0 += __shfl_xor_sync(0xffffffffu, s0, 2);
    q0 += __shfl_xor_sync(0xffffffffu, q0, 1); q0 += __shfl_xor_sync(0xffffffffu, q0, 2);
    s1 += __shfl_xor_sync(0xffffffffu, s1, 1); s1 += __shfl_xor_sync(0xffffffffu, s1, 2);
    q1 += __shfl_xor_sync(0xffffffffu, q1, 1); q1 += __shfl_xor_sync(0xffffffffu, q1, 2);
    float m0v = s0 * (1.f / 64.f), m1v = s1 * (1.f / 64.f);
    float i0 = rsqrtf(q0 * (1.f / 64.f) - m0v * m0v + 1e-6f);
    float i1 = rsqrtf(q1 * (1.f / 64.f) - m1v * m1v + 1e-6f);
    float kp0 = keep[r0], kp1 = keep[r0 + 8];
    #pragma unroll
    for (int j = 0; j < 8; ++j) {
        int c = 8 * j + 2 * tig;
        float2 gg = *(const float2*)(g + c);
        float2 bb = *(const float2*)(be + c);
        float2 oa = make_float2(((v0[2 * j] - m0v) * i0 * gg.x + bb.x) * kp0,
                                ((v0[2 * j + 1] - m0v) * i0 * gg.y + bb.y) * kp0);
        float2 ob = make_float2(((v1[2 * j] - m1v) * i1 * gg.x + bb.x) * kp1,
                                ((v1[2 * j + 1] - m1v) * i1 * gg.y + bb.y) * kp1);
        *(float2*)(C + (size_t)r0 * 64 + c) = oa;
        *(float2*)(C + (size_t)(r0 + 8) * 64 + c) = ob;
        int pos = pairpos(c);
        u32 hh, ll;
        split2(oa.x, oa.y, hh, ll);
        *(u32*)&xh[(size_t)r0 * 72 + pos] = hh; *(u32*)&xl[(size_t)r0 * 72 + pos] = ll;
        split2(ob.x, ob.y, hh, ll);
        *(u32*)&xh[(size_t)(r0 + 8) * 72 + pos] = hh; *(u32*)&xl[(size_t)(r0 + 8) * 72 + pos] = ll;
    }
}

// ------------------------- classifier fused -----------------------------------
__global__ void __launch_bounds__(256) cls_kernel(
    const float* __restrict__ x,
    const float* __restrict__ w1, const float* __restrict__ b1,
    const float* __restrict__ w2, const float* __restrict__ b2,
    const float* __restrict__ w3, const float* __restrict__ b3,
    float* __restrict__ part) {
    __shared__ float Xs[64][65];
    __shared__ __align__(16) float Ws[64][64];
    __shared__ float w3s[64];
    __shared__ float red[256];
    int tid = threadIdx.x;
    int tx = tid & 15, ty = tid >> 4;
    int m0 = blockIdx.x * 64;

    for (int i = tid; i < 64 * 64; i += 256) {
        int r = i >> 6, c = i & 63;
        Xs[r][c] = x[(size_t)(m0 + r) * 64 + c];
        Ws[r][c] = w1[i];
    }
    if (tid < 64) w3s[tid] = w3[tid];
    __syncthreads();

    u64 acc[4][2];
    #pragma unroll
    for (int i = 0; i < 4; ++i) { acc[i][0] = 0ull; acc[i][1] = 0ull; }
    #pragma unroll 8
    for (int kk = 0; kk < 64; ++kk) {
        ulonglong2 w2v = *(const ulonglong2*)&Ws[kk][tx * 4];
        #pragma unroll
        for (int i = 0; i < 4; ++i) {
            float a = Xs[ty * 4 + i][kk];
            u64 ap = pack2(a, a);
            acc[i][0] = fma2(ap, w2v.x, acc[i][0]);
            acc[i][1] = fma2(ap, w2v.y, acc[i][1]);
        }
    }
    __syncthreads();

    float4 b1v = *(const float4*)&b1[tx * 4];
    #pragma unroll
    for (int i = 0; i < 4; ++i) {
        int row = ty * 4 + i;
        float2 p0 = unpack2(acc[i][0]);
        float2 p1 = unpack2(acc[i][1]);
        Xs[row][tx * 4 + 0] = fmaxf(p0.x + b1v.x, 0.f);
        Xs[row][tx * 4 + 1] = fmaxf(p0.y + b1v.y, 0.f);
        Xs[row][tx * 4 + 2] = fmaxf(p1.x + b1v.z, 0.f);
        Xs[row][tx * 4 + 3] = fmaxf(p1.y + b1v.w, 0.f);
    }
    for (int i = tid; i < 64 * 64; i += 256) Ws[i >> 6][i & 63] = w2[i];
    __syncthreads();

    #pragma unroll
    for (int i = 0; i < 4; ++i) { acc[i][0] = 0ull; acc[i][1] = 0ull; }
    #pragma unroll 8
    for (int kk = 0; kk < 64; ++kk) {
        ulonglong2 w2v = *(const ulonglong2*)&Ws[kk][tx * 4];
        #pragma unroll
        for (int i = 0; i < 4; ++i) {
            float a = Xs[ty * 4 + i][kk];
            u64 ap = pack2(a, a);
            acc[i][0] = fma2(ap, w2v.x, acc[i][0]);
            acc[i][1] = fma2(ap, w2v.y, acc[i][1]);
        }
    }

    float4 b2v = *(const float4*)&b2[tx * 4];
    float partial = 0.f;
    #pragma unroll
    for (int i = 0; i < 4; ++i) {
        float2 p0 = unpack2(acc[i][0]);
        float2 p1 = unpack2(acc[i][1]);
        partial += fmaxf(p0.x + b2v.x, 0.f) * w3s[tx * 4 + 0];
        partial += fmaxf(p0.y + b2v.y, 0.f) * w3s[tx * 4 + 1];
        partial += fmaxf(p1.x + b2v.z, 0.f) * w3s[tx * 4 + 2];
        partial += fmaxf(p1.y + b2v.w, 0.f) * w3s[tx * 4 + 3];
    }
    red[tid] = partial;
    __syncthreads();
    for (int st = 128; st > 0; st >>= 1) {
        if (tid < st) red[tid] += red[tid + st];
        __syncthreads();
    }
    if (tid == 0) part[blockIdx.x] = red[0] + 64.f * b3[0];
}

// ------------------------- deterministic final reduction ----------------------
__global__ void reduce_y(const float* __restrict__ part,
                         const float* __restrict__ ob, float* __restrict__ y) {
    int b = threadIdx.x;   // 16
    float s = ob[0];
    #pragma unroll
    for (int i = 0; i < 16; ++i) s += part[b * 16 + i];
    y[b] = s;
}

// ------------------------- launcher ------------------------------------------
extern "C" void kernel_launch(void* const* d_in, const int* in_sizes, int n_in,
                              void* d_out, int out_size) {
    const float* input  = (const float*)d_in[0];
    const float* emb    = (const float*)d_in[1];
    const float* wq     = (const float*)d_in[2];
    const float* wq_b   = (const float*)d_in[3];
    const float* wk     = (const float*)d_in[4];
    const float* wk_b   = (const float*)d_in[5];
    const float* wv     = (const float*)d_in[6];
    const float* wv_b   = (const float*)d_in[7];
    const float* wo     = (const float*)d_in[8];
    const float* ffn_w1 = (const float*)d_in[9];
    const float* ffn_w2 = (const float*)d_in[10];
    const float* ln1_g  = (const float*)d_in[11];
    const float* ln1_b  = (const float*)d_in[12];
    const float* ln2_g  = (const float*)d_in[13];
    const float* ln2_b  = (const float*)d_in[14];
    const float* c_w1   = (const float*)d_in[15];
    const float* c_b1   = (const float*)d_in[16];
    const float* c_w2   = (const float*)d_in[17];
    const float* c_b2   = (const float*)d_in[18];
    const float* c_w3   = (const float*)d_in[19];
    const float* c_b3   = (const float*)d_in[20];
    const float* ob     = (const float*)d_in[21];
    float* y = (float*)d_out;

    float *x, *q, *k, *v, *out1, *keep, *nanf, *part;
    u16 *ws, *wqkvo, *xh, *xl, *cxh, *cxl, *o1h, *o1l;
    cudaGetSymbolAddress((void**)&x,    g_x);
    cudaGetSymbolAddress((void**)&q,    g_q);
    cudaGetSymbolAddress((void**)&k,    g_k);
    cudaGetSymbolAddress((void**)&v,    g_v);
    cudaGetSymbolAddress((void**)&out1, g_out1);
    cudaGetSymbolAddress((void**)&keep, g_keep);
    cudaGetSymbolAddress((void**)&nanf, g_nanf);
    cudaGetSymbolAddress((void**)&part, g_part);
    cudaGetSymbolAddress((void**)&ws,   g_ws);
    cudaGetSymbolAddress((void**)&wqkvo, g_wqkvo);
    cudaGetSymbolAddress((void**)&xh,   g_xh);
    cudaGetSymbolAddress((void**)&xl,   g_xl);
    cudaGetSymbolAddress((void**)&cxh,  g_cxh);
    cudaGetSymbolAddress((void**)&cxl,  g_cxl);
    cudaGetSymbolAddress((void**)&o1h,  g_o1h);
    cudaGetSymbolAddress((void**)&o1l,  g_o1l);

    const int W2_SMEM  = 2 * 4608 * 2;            // 18432 B
    const int FFN_SMEM = 4 * 64 * 72 * 2;         // 36864 B
    cudaFuncSetAttribute(qkv_mma_kernel, cudaFuncAttributeMaxDynamicSharedMemorySize, W2_SMEM);
    cudaFuncSetAttribute(wo_mma_kernel,  cudaFuncAttributeMaxDynamicSharedMemorySize, W2_SMEM);
    cudaFuncSetAttribute(ffn_mma_kernel, cudaFuncAttributeMaxDynamicSharedMemorySize, FFN_SMEM);

    prep_kernel<<<B_, S_>>>(input, keep, nanf);
    build_x_kernel<<<(BS * 32) / 256, 256>>>(input, emb, keep, x, xh, xl);
    wprep_all_kernel<<<384, 256>>>(wq, wk, wv, wo, ffn_w1, ffn_w2, wqkvo, ws);

    for (int l = 0; l < L_; ++l) {
        const u16* wqkv_l = wqkvo + (size_t)l * 8 * 4608;       // q,k,v regions
        const u16* wo_l   = wqkvo + ((size_t)l * 8 + 6) * 4608; // o region

        qkv_mma_kernel<<<dim3(BS / 64, 3), 128, W2_SMEM>>>(
            xh, xl, wqkv_l, wq_b + l * D_, wk_b + l * D_, wv_b + l * D_, q, k, v);
        attn_mma_kernel<<<dim3(S_ / 256, B_ * H_), 256>>>(q, k, v, nanf, cxh, cxl);
        wo_mma_kernel<<<BS / 64, 128, W2_SMEM>>>(
            cxh, cxl, x, wo_l, ln1_g + l * D_, ln1_b + l * D_, keep, out1, o1h, o1l);
        ffn_mma_kernel<<<BS / 64, 128, FFN_SMEM>>>(
            o1h, o1l, out1, ws + (size_t)l * 4 * 4 * 64 * 72,
            ln2_g + l * D_, ln2_b + l * D_, keep, x, xh, xl);
    }

    cls_kernel<<<BS / 64, 256>>>(x, c_w1, c_b1, c_w2, c_b2, c_w3, c_b3, part);
    reduce_y<<<1, 16>>>(part, ob, y);
}

// round 10
// speedup vs baseline: 3.8960x; 1.0431x over previous
#include <cuda_runtime.h>

#define B_  16
#define S_  1024
#define D_  64
#define H_  4
#define DFF 256
#define L_  2
#define BS  (B_ * S_)

typedef unsigned long long u64;
typedef unsigned int u32;
typedef unsigned short u16;

// ------------------------- device scratch ------------------------------------
__device__ float g_x   [BS * D_];
__device__ float g_q   [BS * D_];
__device__ float g_k   [BS * D_];
__device__ float g_v   [BS * D_];
__device__ float g_keep[BS];
__device__ float g_nanf[BS];
__device__ float g_part[BS / 64];
__device__ u16   g_ws   [L_ * 4 * 4 * 64 * 72];  // split ffn weights, frag layout
__device__ u16   g_wqkvo[L_ * 8 * 64 * 72];      // split q,k,v,o weights (hi/lo each)
__device__ u16   g_xh  [BS * 72];                // x bf16-hi frag layout
__device__ u16   g_xl  [BS * 72];
__device__ u16   g_cxh [BS * 72];                // ctx split frag layout
__device__ u16   g_cxl [BS * 72];

// ------------------------- helpers --------------------------------------------
__device__ __forceinline__ u64 fma2(u64 a, u64 b, u64 c) {
    u64 d; asm("fma.rn.f32x2 %0, %1, %2, %3;" : "=l"(d) : "l"(a), "l"(b), "l"(c)); return d;
}
__device__ __forceinline__ u64 pack2(float x, float y) {
    u64 d; asm("mov.b64 %0, {%1, %2};" : "=l"(d) : "f"(x), "f"(y)); return d;
}
__device__ __forceinline__ float2 unpack2(u64 a) {
    float lo, hi; asm("mov.b64 {%0, %1}, %2;" : "=f"(lo), "=f"(hi) : "l"(a));
    return make_float2(lo, hi);
}
__device__ __forceinline__ float ex2f(float x) {
    float r; asm("ex2.approx.f32 %0, %1;" : "=f"(r) : "f"(x)); return r;
}
__device__ __forceinline__ u32 bf2(float lo, float hi) {
    u32 r; asm("cvt.rn.bf16x2.f32 %0, %1, %2;" : "=r"(r) : "f"(hi), "f"(lo)); return r;
}
__device__ __forceinline__ u16 bf1(float f) {
    u16 h; asm("cvt.rn.bf16.f32 %0, %1;" : "=h"(h) : "f"(f)); return h;
}
__device__ __forceinline__ float bf16f(u16 h) { return __uint_as_float((u32)h << 16); }
__device__ __forceinline__ float lopart(u32 h) { return __uint_as_float(h << 16); }
__device__ __forceinline__ float hipart(u32 h) { return __uint_as_float(h & 0xffff0000u); }
__device__ __forceinline__ void mma_bf16(
    float& c0, float& c1, float& c2, float& c3,
    u32 a0, u32 a1, u32 a2, u32 a3, u32 b0, u32 b1) {
    asm volatile(
        "mma.sync.aligned.m16n8k16.row.col.f32.bf16.bf16.f32 "
        "{%0,%1,%2,%3},{%4,%5,%6,%7},{%8,%9},{%0,%1,%2,%3};"
        : "+f"(c0), "+f"(c1), "+f"(c2), "+f"(c3)
        : "r"(a0), "r"(a1), "r"(a2), "r"(a3), "r"(b0), "r"(b1));
}
// permuted k-position inside a 16-group
__device__ __forceinline__ int permpos(int j) {   // j in 0..15
    int p = j >> 1, l = j & 1;
    return (p & 3) * 4 + ((p >> 2) << 1) + l;
}
// pos of an even column pair (c,c+1) in the 72-wide frag row
__device__ __forceinline__ int pairpos(int c) {
    int p = (c & 15) >> 1;
    return (c >> 4) * 16 + (p & 3) * 4 + ((p >> 2) << 1);
}
// split a float pair into hi/lo bf16x2
__device__ __forceinline__ void split2(float a, float b, u32& h, u32& l) {
    h = bf2(a, b);
    l = bf2(a - lopart(h), b - hipart(h));
}

// ------------------------- prep: nan flags + keep ----------------------------
__global__ void prep_kernel(const float* __restrict__ in,
                            float* __restrict__ keepv, float* __restrict__ nanf) {
    int b = blockIdx.x;
    int s = threadIdx.x;            // 1024 threads
    float v = in[b * S_ + s];
    bool nan = (v != v);
    unsigned bal = __ballot_sync(0xffffffffu, nan);
    __shared__ int warp_all[32];
    __shared__ int allnan_s;
    if ((s & 31) == 0) warp_all[s >> 5] = (bal == 0xffffffffu);
    __syncthreads();
    if (s == 0) {
        int a = 1;
        #pragma unroll
        for (int i = 0; i < 32; ++i) a &= warp_all[i];
        allnan_s = a;
    }
    __syncthreads();
    float kp = (nan || allnan_s) ? 0.f : 1.f;
    keepv[b * S_ + s] = kp;
    nanf [b * S_ + s] = nan ? 1.f : 0.f;
}

// ------------------------- build x (fp32 + split frag emit) -------------------
__global__ void build_x_kernel(const float* __restrict__ in,
                               const float* __restrict__ emb,
                               const float* __restrict__ keepv,
                               float* __restrict__ x,
                               u16* __restrict__ xh, u16* __restrict__ xl) {
    int idx = blockIdx.x * 256 + threadIdx.x;   // BS*32
    int cp  = idx & 31;
    int row = idx >> 5;
    int s   = row & (S_ - 1);
    int c   = cp * 2;
    float kp = keepv[row];
    const float SQF = 7.93725393319377f * 8.0f;  // sqrt(63)*sqrt(64)
    float v0 = emb[s * 63 + c] * SQF * kp;
    float v1;
    if (c + 1 == 63) {
        float t = in[row];
        v1 = ((t != t) ? 0.f : t) * kp;
    } else {
        v1 = emb[s * 63 + c + 1] * SQF * kp;
    }
    x[row * 64 + c] = v0;
    x[row * 64 + c + 1] = v1;
    int pos = pairpos(c);
    u32 h, l; split2(v0, v1, h, l);
    *(u32*)&xh[(size_t)row * 72 + pos] = h;
    *(u32*)&xl[(size_t)row * 72 + pos] = l;
}

// ------------------------- unified weight prep (1 elem/thread) ----------------
__global__ void wprep_all_kernel(
    const float* __restrict__ wq, const float* __restrict__ wk,
    const float* __restrict__ wv, const float* __restrict__ wo,
    const float* __restrict__ w1, const float* __restrict__ w2,
    u16* __restrict__ dstqkvo, u16* __restrict__ ws) {
    if (blockIdx.x < 128) {
        int idx = blockIdx.x * 256 + threadIdx.x;   // [0, L*4*4096)
        int region = idx >> 12;
        int i      = idx & 4095;
        int l = region >> 2, wsel = region & 3;
        const float* src = (wsel == 0 ? wq : wsel == 1 ? wk : wsel == 2 ? wv : wo) + (size_t)l * 4096;
        u16* dst = dstqkvo + ((size_t)l * 8 + wsel * 2) * 4608;
        int k = i >> 6, n = i & 63;
        int pos = (k >> 4) * 16 + permpos(k & 15);
        float val = src[k * 64 + n];
        u16 h = bf1(val);
        dst[n * 72 + pos]        = h;
        dst[4608 + n * 72 + pos] = bf1(val - bf16f(h));
    } else {
        int idx = (blockIdx.x - 128) * 256 + threadIdx.x;   // [0, L*4*2*4096)
        int region = idx >> 13;
        int rem    = idx & 8191;
        int which  = rem >> 12;
        int i      = rem & 4095;
        int l = region >> 2, nt = region & 3;
        u16* dst = ws + (size_t)region * (4 * 64 * 72);
        int k = i >> 6, n = i & 63;
        int pos = (k >> 4) * 16 + permpos(k & 15);
        if (which == 0) {
            float wa = w1[(size_t)l * 64 * 256 + k * 256 + nt * 64 + n];
            u16 h = bf1(wa);
            dst[0 * 64 * 72 + n * 72 + pos] = h;
            dst[1 * 64 * 72 + n * 72 + pos] = bf1(wa - bf16f(h));
        } else {
            float wb = w2[(size_t)l * 256 * 64 + (nt * 64 + k) * 64 + n];
            u16 h2 = bf1(wb);
            dst[2 * 64 * 72 + n * 72 + pos] = h2;
            dst[3 * 64 * 72 + n * 72 + pos] = bf1(wb - bf16f(h2));
        }
    }
}

// ------------------------- tensor-core QKV (direct-LDG weights) ---------------
__global__ void __launch_bounds__(128) qkv_mma_kernel(
    const u16* __restrict__ xh, const u16* __restrict__ xl,
    const u16* __restrict__ wsplit,   // [3][2][4608] region for this layer
    const float* __restrict__ bq, const float* __restrict__ bk, const float* __restrict__ bv_,
    float* __restrict__ q, float* __restrict__ k, float* __restrict__ v) {
    int tid = threadIdx.x, w = tid >> 5, lane = tid & 31;
    int gid = lane >> 2, tig = lane & 3;
    int m0 = blockIdx.x * 64;
    int wsel = blockIdx.y;
    int r0 = m0 + w * 16 + gid;

    const u16* Wh = wsplit + (size_t)wsel * 2 * 4608;
    const u16* Wl = Wh + 4608;

    u32 Ah[4][4], Al[4][4];
    {
        const u16* ph0 = xh + (size_t)r0 * 72;
        const u16* ph8 = xh + (size_t)(r0 + 8) * 72;
        const u16* pl0 = xl + (size_t)r0 * 72;
        const u16* pl8 = xl + (size_t)(r0 + 8) * 72;
        #pragma unroll
        for (int gk = 0; gk < 4; ++gk) {
            uint2 t0 = *(const uint2*)(ph0 + gk * 16 + tig * 4);
            uint2 t1 = *(const uint2*)(ph8 + gk * 16 + tig * 4);
            Ah[gk][0] = t0.x; Ah[gk][2] = t0.y;
            Ah[gk][1] = t1.x; Ah[gk][3] = t1.y;
            uint2 s0 = *(const uint2*)(pl0 + gk * 16 + tig * 4);
            uint2 s1 = *(const uint2*)(pl8 + gk * 16 + tig * 4);
            Al[gk][0] = s0.x; Al[gk][2] = s0.y;
            Al[gk][1] = s1.x; Al[gk][3] = s1.y;
        }
    }

    float C2[8][4];
    #pragma unroll
    for (int j = 0; j < 8; ++j)
        #pragma unroll
        for (int i = 0; i < 4; ++i) C2[j][i] = 0.f;

    #pragma unroll
    for (int j = 0; j < 8; ++j) {
        #pragma unroll
        for (int t = 0; t < 4; ++t) {
            uint2 bh = *(const uint2*)(Wh + (8 * j + gid) * 72 + t * 16 + tig * 4);
            uint2 bl = *(const uint2*)(Wl + (8 * j + gid) * 72 + t * 16 + tig * 4);
            mma_bf16(C2[j][0], C2[j][1], C2[j][2], C2[j][3], Ah[t][0], Ah[t][1], Ah[t][2], Ah[t][3], bh.x, bh.y);
            mma_bf16(C2[j][0], C2[j][1], C2[j][2], C2[j][3], Ah[t][0], Ah[t][1], Ah[t][2], Ah[t][3], bl.x, bl.y);
            mma_bf16(C2[j][0], C2[j][1], C2[j][2], C2[j][3], Al[t][0], Al[t][1], Al[t][2], Al[t][3], bh.x, bh.y);
        }
    }

    const float* bias = wsel == 0 ? bq : wsel == 1 ? bk : bv_;
    float* out = wsel == 0 ? q : wsel == 1 ? k : v;
    #pragma unroll
    for (int j = 0; j < 8; ++j) {
        int c = 8 * j + 2 * tig;
        float2 bb = *(const float2*)(bias + c);
        *(float2*)(out + (size_t)r0 * 64 + c)       = make_float2(C2[j][0] + bb.x, C2[j][1] + bb.y);
        *(float2*)(out + (size_t)(r0 + 8) * 64 + c) = make_float2(C2[j][2] + bb.x, C2[j][3] + bb.y);
    }
}

// ------------------------- tensor-core flash attention -------------------------
#define KCHUNK 64
__global__ void __launch_bounds__(256) attn_mma_kernel(
    const float* __restrict__ q, const float* __restrict__ k,
    const float* __restrict__ v, const float* __restrict__ nanf,
    u16* __restrict__ cxh, u16* __restrict__ cxl) {
    __shared__ __align__(16) u16 Qs[256 * 16];
    __shared__ __align__(16) u16 Ks[2][KCHUNK * 18];
    __shared__ __align__(16) u16 Vt[2][16 * 66];
    __shared__ float bias[2][KCHUNK];
    __shared__ float rkeep[256];

    int tid = threadIdx.x;
    int w   = tid >> 5;
    int lane = tid & 31;
    int gid = lane >> 2;
    int tig = lane & 3;
    int bh = blockIdx.y;
    int b = bh >> 2, h = bh & 3;
    int qbase = blockIdx.x * 256;
    size_t bS = (size_t)b * S_;

    const float SC = 0.25f * 1.4426950408889634f;
    int key = tid >> 2, d4 = tid & 3;

    float4 kf0 = *(const float4*)(k + (bS + key) * 64 + h * 16 + d4 * 4);
    float4 vf0 = *(const float4*)(v + (bS + key) * 64 + h * 16 + d4 * 4);
    float bb0 = 0.f;
    if (tid < KCHUNK) bb0 = (nanf[bS + tid] != 0.f) ? -1e30f : 0.f;

    #pragma unroll
    for (int it = 0; it < 4; ++it) {
        int idx = tid + it * 256;
        int qq = idx >> 2, dd = idx & 3;
        float4 f = *(const float4*)(q + (bS + qbase + qq) * 64 + h * 16 + dd * 4);
        *(u32*)((char*)Qs + qq * 32 + dd * 8)     = bf2(f.x * SC, f.y * SC);
        *(u32*)((char*)Qs + qq * 32 + dd * 8 + 4) = bf2(f.z * SC, f.w * SC);
    }
    rkeep[tid] = (nanf[bS + qbase + tid] == 0.f) ? 1.f : 0.f;

    {
        *(u32*)((char*)Ks[0] + key * 36 + d4 * 8)     = bf2(kf0.x, kf0.y);
        *(u32*)((char*)Ks[0] + key * 36 + d4 * 8 + 4) = bf2(kf0.z, kf0.w);
        Vt[0][(d4 * 4 + 0) * 66 + key] = bf1(vf0.x);
        Vt[0][(d4 * 4 + 1) * 66 + key] = bf1(vf0.y);
        Vt[0][(d4 * 4 + 2) * 66 + key] = bf1(vf0.z);
        Vt[0][(d4 * 4 + 3) * 66 + key] = bf1(vf0.w);
        if (tid < KCHUNK) bias[0][tid] = bb0;
    }
    __syncthreads();

    u32 qa[2][4];
    #pragma unroll
    for (int s = 0; s < 2; ++s) {
        int row = w * 32 + s * 16 + gid;
        qa[s][0] = *(const u32*)((char*)Qs + row * 32 + tig * 4);
        qa[s][1] = *(const u32*)((char*)Qs + (row + 8) * 32 + tig * 4);
        qa[s][2] = *(const u32*)((char*)Qs + row * 32 + tig * 4 + 16);
        qa[s][3] = *(const u32*)((char*)Qs + (row + 8) * 32 + tig * 4 + 16);
    }

    float z[2][2] = {{0.f, 0.f}, {0.f, 0.f}};
    float cd[2][2][4];
    #pragma unroll
    for (int s = 0; s < 2; ++s)
        #pragma unroll
        for (int dt = 0; dt < 2; ++dt)
            #pragma unroll
            for (int i = 0; i < 4; ++i) cd[s][dt][i] = 0.f;

    for (int ch = 0; ch < S_ / KCHUNK; ++ch) {
        int cur = ch & 1;
        float4 kfn, vfn; float bbn = 0.f;
        if (ch + 1 < S_ / KCHUNK) {
            size_t nb = bS + (ch + 1) * KCHUNK;
            kfn = *(const float4*)(k + (nb + key) * 64 + h * 16 + d4 * 4);
            vfn = *(const float4*)(v + (nb + key) * 64 + h * 16 + d4 * 4);
            if (tid < KCHUNK) bbn = (nanf[nb + tid] != 0.f) ? -1e30f : 0.f;
        }

        const u16* KsC = Ks[cur];
        const u16* VtC = Vt[cur];
        const float* biC = bias[cur];

        #pragma unroll
        for (int kb = 0; kb < KCHUNK; kb += 16) {
            u32 kb0a = *(const u32*)((char*)KsC + (kb + gid) * 36 + tig * 4);
            u32 kb1a = *(const u32*)((char*)KsC + (kb + gid) * 36 + tig * 4 + 16);
            u32 kb0b = *(const u32*)((char*)KsC + (kb + 8 + gid) * 36 + tig * 4);
            u32 kb1b = *(const u32*)((char*)KsC + (kb + 8 + gid) * 36 + tig * 4 + 16);
            u32 vb00 = *(const u32*)((char*)VtC + (gid * 66 + kb + 2 * tig) * 2);
            u32 vb01 = *(const u32*)((char*)VtC + (gid * 66 + kb + 8 + 2 * tig) * 2);
            u32 vb10 = *(const u32*)((char*)VtC + ((gid + 8) * 66 + kb + 2 * tig) * 2);
            u32 vb11 = *(const u32*)((char*)VtC + ((gid + 8) * 66 + kb + 8 + 2 * tig) * 2);
            float2 bv0 = *(const float2*)(biC + kb + 2 * tig);
            float2 bv1 = *(const float2*)(biC + kb + 8 + 2 * tig);

            #pragma unroll
            for (int s = 0; s < 2; ++s) {
                float c0 = bv0.x, c1 = bv0.y, c2 = bv0.x, c3 = bv0.y;
                mma_bf16(c0, c1, c2, c3, qa[s][0], qa[s][1], qa[s][2], qa[s][3], kb0a, kb1a);
                float d0 = bv1.x, d1 = bv1.y, d2 = bv1.x, d3 = bv1.y;
                mma_bf16(d0, d1, d2, d3, qa[s][0], qa[s][1], qa[s][2], qa[s][3], kb0b, kb1b);

                float p0 = ex2f(c0), p1 = ex2f(c1);
                float p2 = ex2f(c2), p3 = ex2f(c3);
                float p4 = ex2f(d0), p5 = ex2f(d1);
                float p6 = ex2f(d2), p7 = ex2f(d3);
                z[s][0] += (p0 + p1) + (p4 + p5);
                z[s][1] += (p2 + p3) + (p6 + p7);

                u32 pa0 = bf2(p0, p1), pa1 = bf2(p2, p3);
                u32 pa2 = bf2(p4, p5), pa3 = bf2(p6, p7);
                mma_bf16(cd[s][0][0], cd[s][0][1], cd[s][0][2], cd[s][0][3],
                         pa0, pa1, pa2, pa3, vb00, vb01);
                mma_bf16(cd[s][1][0], cd[s][1][1], cd[s][1][2], cd[s][1][3],
                         pa0, pa1, pa2, pa3, vb10, vb11);
            }
        }

        if (ch + 1 < S_ / KCHUNK) {
            int nxt = cur ^ 1;
            *(u32*)((char*)Ks[nxt] + key * 36 + d4 * 8)     = bf2(kfn.x, kfn.y);
            *(u32*)((char*)Ks[nxt] + key * 36 + d4 * 8 + 4) = bf2(kfn.z, kfn.w);
            Vt[nxt][(d4 * 4 + 0) * 66 + key] = bf1(vfn.x);
            Vt[nxt][(d4 * 4 + 1) * 66 + key] = bf1(vfn.y);
            Vt[nxt][(d4 * 4 + 2) * 66 + key] = bf1(vfn.z);
            Vt[nxt][(d4 * 4 + 3) * 66 + key] = bf1(vfn.w);
            if (tid < KCHUNK) bias[nxt][tid] = bbn;
            __syncthreads();
        }
    }

    int posA = h * 16 + tig * 4;
    int posB = posA + 2;
    #pragma unroll
    for (int s = 0; s < 2; ++s) {
        float z0 = z[s][0], z1 = z[s][1];
        z0 += __shfl_xor_sync(0xffffffffu, z0, 1);
        z0 += __shfl_xor_sync(0xffffffffu, z0, 2);
        z1 += __shfl_xor_sync(0xffffffffu, z1, 1);
        z1 += __shfl_xor_sync(0xffffffffu, z1, 2);

        int q0 = w * 32 + s * 16 + gid;
        int q1 = q0 + 8;
        float rk0 = rkeep[q0], rk1 = rkeep[q1];
        float rz0 = (rk0 != 0.f && z0 > 0.f) ? (1.f / z0) : 0.f;
        float rz1 = (rk1 != 0.f && z1 > 0.f) ? (1.f / z1) : 0.f;

        size_t row0 = (bS + qbase + q0) * 72;
        size_t row1 = (bS + qbase + q1) * 72;
        u32 hh, ll;
        split2(cd[s][0][0] * rz0, cd[s][0][1] * rz0, hh, ll);
        *(u32*)&cxh[row0 + posA] = hh; *(u32*)&cxl[row0 + posA] = ll;
        split2(cd[s][1][0] * rz0, cd[s][1][1] * rz0, hh, ll);
        *(u32*)&cxh[row0 + posB] = hh; *(u32*)&cxl[row0 + posB] = ll;
        split2(cd[s][0][2] * rz1, cd[s][0][3] * rz1, hh, ll);
        *(u32*)&cxh[row1 + posA] = hh; *(u32*)&cxl[row1 + posA] = ll;
        split2(cd[s][1][2] * rz1, cd[s][1][3] * rz1, hh, ll);
        *(u32*)&cxh[row1 + posB] = hh; *(u32*)&cxl[row1 + posB] = ll;
    }
}

// ------------------------- fused WO + LN1 + FFN + LN2 kernel -------------------
// wo GEMM (direct-LDG weights) -> LN1 in regs -> A1 frags in regs ->
// ffn gemm1/relu/gemm2 (streamed smem weights) -> LN2 epilogue -> x + frags.
__global__ void __launch_bounds__(128) wo_ffn_kernel(
    const u16* __restrict__ cxh, const u16* __restrict__ cxl,
    const float* __restrict__ residx, const u16* __restrict__ wo_w,
    const u16* __restrict__ ws,
    const float* __restrict__ g1, const float* __restrict__ be1,
    const float* __restrict__ g2, const float* __restrict__ be2,
    const float* __restrict__ keep, float* __restrict__ xout,
    u16* __restrict__ xh, u16* __restrict__ xl) {
    extern __shared__ u16 sw[];   // 4 * 64 * 72 u16 = 36864 B (ffn stream buffer)
    int tid = threadIdx.x, w = tid >> 5, lane = tid & 31;
    int gid = lane >> 2, tig = lane & 3;
    int m0 = blockIdx.x * 64;
    int r0 = m0 + w * 16 + gid;

    // ---- phase 1: wo GEMM on ctx frags ----
    float C2[8][4];
    #pragma unroll
    for (int j = 0; j < 8; ++j)
        #pragma unroll
        for (int i = 0; i < 4; ++i) C2[j][i] = 0.f;
    {
        u32 Ah[4][4], Al[4][4];
        const u16* ph0 = cxh + (size_t)r0 * 72;
        const u16* ph8 = cxh + (size_t)(r0 + 8) * 72;
        const u16* pl0 = cxl + (size_t)r0 * 72;
        const u16* pl8 = cxl + (size_t)(r0 + 8) * 72;
        #pragma unroll
        for (int gk = 0; gk < 4; ++gk) {
            uint2 t0 = *(const uint2*)(ph0 + gk * 16 + tig * 4);
            uint2 t1 = *(const uint2*)(ph8 + gk * 16 + tig * 4);
            Ah[gk][0] = t0.x; Ah[gk][2] = t0.y;
            Ah[gk][1] = t1.x; Ah[gk][3] = t1.y;
            uint2 s0 = *(const uint2*)(pl0 + gk * 16 + tig * 4);
            uint2 s1 = *(const uint2*)(pl8 + gk * 16 + tig * 4);
            Al[gk][0] = s0.x; Al[gk][2] = s0.y;
            Al[gk][1] = s1.x; Al[gk][3] = s1.y;
        }
        const u16* Wh = wo_w;
        const u16* Wl = wo_w + 4608;
        #pragma unroll
        for (int j = 0; j < 8; ++j) {
            #pragma unroll
            for (int t = 0; t < 4; ++t) {
                uint2 bh = *(const uint2*)(Wh + (8 * j + gid) * 72 + t * 16 + tig * 4);
                uint2 bl = *(const uint2*)(Wl + (8 * j + gid) * 72 + t * 16 + tig * 4);
                mma_bf16(C2[j][0], C2[j][1], C2[j][2], C2[j][3], Ah[t][0], Ah[t][1], Ah[t][2], Ah[t][3], bh.x, bh.y);
                mma_bf16(C2[j][0], C2[j][1], C2[j][2], C2[j][3], Ah[t][0], Ah[t][1], Ah[t][2], Ah[t][3], bl.x, bl.y);
                mma_bf16(C2[j][0], C2[j][1], C2[j][2], C2[j][3], Al[t][0], Al[t][1], Al[t][2], Al[t][3], bh.x, bh.y);
            }
        }
    }

    float kp0 = keep[r0], kp1 = keep[r0 + 8];

    // ---- phase 2: LN1 in registers -> A1 frags (out1 split) ----
    u32 A1h[4][4], A1l[4][4];
    {
        float v0[16], v1[16];
        float s0 = 0.f, q0 = 0.f, s1 = 0.f, q1 = 0.f;
        #pragma unroll
        for (int j = 0; j < 8; ++j) {
            float2 ra = *(const float2*)(residx + (size_t)r0 * 64 + 8 * j + 2 * tig);
            float2 rb = *(const float2*)(residx + (size_t)(r0 + 8) * 64 + 8 * j + 2 * tig);
            float a0v = C2[j][0] + ra.x, a1v = C2[j][1] + ra.y;
            float b0v = C2[j][2] + rb.x, b1v = C2[j][3] + rb.y;
            v0[2 * j] = a0v; v0[2 * j + 1] = a1v;
            v1[2 * j] = b0v; v1[2 * j + 1] = b1v;
            s0 += a0v + a1v; q0 += a0v * a0v + a1v * a1v;
            s1 += b0v + b1v; q1 += b0v * b0v + b1v * b1v;
        }
        s0 += __shfl_xor_sync(0xffffffffu, s0, 1); s0 += __shfl_xor_sync(0xffffffffu, s0, 2);
        q0 += __shfl_xor_sync(0xffffffffu, q0, 1); q0 += __shfl_xor_sync(0xffffffffu, q0, 2);
        s1 += __shfl_xor_sync(0xffffffffu, s1, 1); s1 += __shfl_xor_sync(0xffffffffu, s1, 2);
        q1 += __shfl_xor_sync(0xffffffffu, q1, 1); q1 += __shfl_xor_sync(0xffffffffu, q1, 2);
        float m0v = s0 * (1.f / 64.f), m1v = s1 * (1.f / 64.f);
        float i0 = rsqrtf(q0 * (1.f / 64.f) - m0v * m0v + 1e-6f);
        float i1 = rsqrtf(q1 * (1.f / 64.f) - m1v * m1v + 1e-6f);
        #pragma unroll
        for (int j = 0; j < 8; ++j) {
            int c = 8 * j + 2 * tig;
            float2 gg = *(const float2*)(g1 + c);
            float2 bb = *(const float2*)(be1 + c);
            float oax = ((v0[2 * j] - m0v) * i0 * gg.x + bb.x) * kp0;
            float oay = ((v0[2 * j + 1] - m0v) * i0 * gg.y + bb.y) * kp0;
            float obx = ((v1[2 * j] - m1v) * i1 * gg.x + bb.x) * kp1;
            float oby = ((v1[2 * j + 1] - m1v) * i1 * gg.y + bb.y) * kp1;
            int gk = j >> 1, half = (j & 1) << 1;   // reg index 0 or 2
            split2(oax, oay, A1h[gk][half], A1l[gk][half]);
            split2(obx, oby, A1h[gk][half + 1], A1l[gk][half + 1]);
        }
    }

    // ---- phase 3: FFN gemm1/relu/gemm2 streamed ----
    #pragma unroll
    for (int j = 0; j < 8; ++j)
        #pragma unroll
        for (int i = 0; i < 4; ++i) C2[j][i] = 0.f;

    for (int nt = 0; nt < 4; ++nt) {
        __syncthreads();
        {
            const float4* src = (const float4*)(ws + (size_t)nt * 4 * 64 * 72);
            float4* dst = (float4*)sw;
            #pragma unroll
            for (int i = 0; i < 18; ++i) dst[tid + i * 128] = src[tid + i * 128];
        }
        __syncthreads();
        const u16* W1h = sw;
        const u16* W1l = sw + 64 * 72;
        const u16* W2h = sw + 2 * 64 * 72;
        const u16* W2l = sw + 3 * 64 * 72;

        u32 A2h[4][4], A2l[4][4];
        #pragma unroll
        for (int t = 0; t < 4; ++t) {
            float Ca[4] = {0.f, 0.f, 0.f, 0.f};
            float Cb[4] = {0.f, 0.f, 0.f, 0.f};
            #pragma unroll
            for (int gk = 0; gk < 4; ++gk) {
                uint2 bha = *(const uint2*)(W1h + (16 * t + gid) * 72 + gk * 16 + tig * 4);
                uint2 bla = *(const uint2*)(W1l + (16 * t + gid) * 72 + gk * 16 + tig * 4);
                mma_bf16(Ca[0], Ca[1], Ca[2], Ca[3], A1h[gk][0], A1h[gk][1], A1h[gk][2], A1h[gk][3], bha.x, bha.y);
                mma_bf16(Ca[0], Ca[1], Ca[2], Ca[3], A1h[gk][0], A1h[gk][1], A1h[gk][2], A1h[gk][3], bla.x, bla.y);
                mma_bf16(Ca[0], Ca[1], Ca[2], Ca[3], A1l[gk][0], A1l[gk][1], A1l[gk][2], A1l[gk][3], bha.x, bha.y);
                uint2 bhb = *(const uint2*)(W1h + (16 * t + 8 + gid) * 72 + gk * 16 + tig * 4);
                uint2 blb = *(const uint2*)(W1l + (16 * t + 8 + gid) * 72 + gk * 16 + tig * 4);
                mma_bf16(Cb[0], Cb[1], Cb[2], Cb[3], A1h[gk][0], A1h[gk][1], A1h[gk][2], A1h[gk][3], bhb.x, bhb.y);
                mma_bf16(Cb[0], Cb[1], Cb[2], Cb[3], A1h[gk][0], A1h[gk][1], A1h[gk][2], A1h[gk][3], blb.x, blb.y);
                mma_bf16(Cb[0], Cb[1], Cb[2], Cb[3], A1l[gk][0], A1l[gk][1], A1l[gk][2], A1l[gk][3], bhb.x, bhb.y);
            }
            #pragma unroll
            for (int i = 0; i < 4; ++i) { Ca[i] = fmaxf(Ca[i], 0.f); Cb[i] = fmaxf(Cb[i], 0.f); }
            split2(Ca[0], Ca[1], A2h[t][0], A2l[t][0]);
            split2(Ca[2], Ca[3], A2h[t][1], A2l[t][1]);
            split2(Cb[0], Cb[1], A2h[t][2], A2l[t][2]);
            split2(Cb[2], Cb[3], A2h[t][3], A2l[t][3]);
        }

        #pragma unroll
        for (int j = 0; j < 8; ++j) {
            #pragma unroll
            for (int t = 0; t < 4; ++t) {
                uint2 bh = *(const uint2*)(W2h + (8 * j + gid) * 72 + t * 16 + tig * 4);
                uint2 bl = *(const uint2*)(W2l + (8 * j + gid) * 72 + t * 16 + tig * 4);
                mma_bf16(C2[j][0], C2[j][1], C2[j][2], C2[j][3], A2h[t][0], A2h[t][1], A2h[t][2], A2h[t][3], bh.x, bh.y);
                mma_bf16(C2[j][0], C2[j][1], C2[j][2], C2[j][3], A2h[t][0], A2h[t][1], A2h[t][2], A2h[t][3], bl.x, bl.y);
                mma_bf16(C2[j][0], C2[j][1], C2[j][2], C2[j][3], A2l[t][0], A2l[t][1], A2l[t][2], A2l[t][3], bh.x, bh.y);
            }
        }
    }

    // ---- phase 4: LN2 epilogue (resid = out1 reconstructed from A1 frags) ----
    float v0[16], v1[16];
    float s0 = 0.f, q0 = 0.f, s1 = 0.f, q1 = 0.f;
    #pragma unroll
    for (int j = 0; j < 8; ++j) {
        int gk = j >> 1, half = (j & 1) << 1;
        float rax = lopart(A1h[gk][half])     + lopart(A1l[gk][half]);
        float ray = hipart(A1h[gk][half])     + hipart(A1l[gk][half]);
        float rbx = lopart(A1h[gk][half + 1]) + lopart(A1l[gk][half + 1]);
        float rby = hipart(A1h[gk][half + 1]) + hipart(A1l[gk][half + 1]);
        float a0v = C2[j][0] + rax, a1v = C2[j][1] + ray;
        float b0v = C2[j][2] + rbx, b1v = C2[j][3] + rby;
        v0[2 * j] = a0v; v0[2 * j + 1] = a1v;
        v1[2 * j] = b0v; v1[2 * j + 1] = b1v;
        s0 += a0v + a1v; q0 += a0v * a0v + a1v * a1v;
        s1 += b0v + b1v; q1 += b0v * b0v + b1v * b1v;
    }
    s0 += __shfl_xor_sync(0xffffffffu, s0, 1); s0 += __shfl_xor_sync(0xffffffffu, s0, 2);
    q0 += __shfl_xor_sync(0xffffffffu, q0, 1); q0 += __shfl_xor_sync(0xffffffffu, q0, 2);
    s1 += __shfl_xor_sync(0xffffffffu, s1, 1); s1 += __shfl_xor_sync(0xffffffffu, s1, 2);
    q1 += __shfl_xor_sync(0xffffffffu, q1, 1); q1 += __shfl_xor_sync(0xffffffffu, q1, 2);
    float m0v = s0 * (1.f / 64.f), m1v = s1 * (1.f / 64.f);
    float i0 = rsqrtf(q0 * (1.f / 64.f) - m0v * m0v + 1e-6f);
    float i1 = rsqrtf(q1 * (1.f / 64.f) - m1v * m1v + 1e-6f);
    #pragma unroll
    for (int j = 0; j < 8; ++j) {
        int c = 8 * j + 2 * tig;
        float2 gg = *(const float2*)(g2 + c);
        float2 bb = *(const float2*)(be2 + c);
        float2 oa = make_float2(((v0[2 * j] - m0v) * i0 * gg.x + bb.x) * kp0,
                                ((v0[2 * j + 1] - m0v) * i0 * gg.y + bb.y) * kp0);
        float2 ob = make_float2(((v1[2 * j] - m1v) * i1 * gg.x + bb.x) * kp1,
                                ((v1[2 * j + 1] - m1v) * i1 * gg.y + bb.y) * kp1);
        *(float2*)(xout + (size_t)r0 * 64 + c) = oa;
        *(float2*)(xout + (size_t)(r0 + 8) * 64 + c) = ob;
        int pos = pairpos(c);
        u32 hh, ll;
        split2(oa.x, oa.y, hh, ll);
        *(u32*)&xh[(size_t)r0 * 72 + pos] = hh; *(u32*)&xl[(size_t)r0 * 72 + pos] = ll;
        split2(ob.x, ob.y, hh, ll);
        *(u32*)&xh[(size_t)(r0 + 8) * 72 + pos] = hh; *(u32*)&xl[(size_t)(r0 + 8) * 72 + pos] = ll;
    }
}

// ------------------------- classifier fused -----------------------------------
__global__ void __launch_bounds__(256) cls_kernel(
    const float* __restrict__ x,
    const float* __restrict__ w1, const float* __restrict__ b1,
    const float* __restrict__ w2, const float* __restrict__ b2,
    const float* __restrict__ w3, const float* __restrict__ b3,
    float* __restrict__ part) {
    __shared__ float Xs[64][65];
    __shared__ __align__(16) float Ws[64][64];
    __shared__ float w3s[64];
    __shared__ float red[256];
    int tid = threadIdx.x;
    int tx = tid & 15, ty = tid >> 4;
    int m0 = blockIdx.x * 64;

    for (int i = tid; i < 64 * 64; i += 256) {
        int r = i >> 6, c = i & 63;
        Xs[r][c] = x[(size_t)(m0 + r) * 64 + c];
        Ws[r][c] = w1[i];
    }
    if (tid < 64) w3s[tid] = w3[tid];
    __syncthreads();

    u64 acc[4][2];
    #pragma unroll
    for (int i = 0; i < 4; ++i) { acc[i][0] = 0ull; acc[i][1] = 0ull; }
    #pragma unroll 8
    for (int kk = 0; kk < 64; ++kk) {
        ulonglong2 w2v = *(const ulonglong2*)&Ws[kk][tx * 4];
        #pragma unroll
        for (int i = 0; i < 4; ++i) {
            float a = Xs[ty * 4 + i][kk];
            u64 ap = pack2(a, a);
            acc[i][0] = fma2(ap, w2v.x, acc[i][0]);
            acc[i][1] = fma2(ap, w2v.y, acc[i][1]);
        }
    }
    __syncthreads();

    float4 b1v = *(const float4*)&b1[tx * 4];
    #pragma unroll
    for (int i = 0; i < 4; ++i) {
        int row = ty * 4 + i;
        float2 p0 = unpack2(acc[i][0]);
        float2 p1 = unpack2(acc[i][1]);
        Xs[row][tx * 4 + 0] = fmaxf(p0.x + b1v.x, 0.f);
        Xs[row][tx * 4 + 1] = fmaxf(p0.y + b1v.y, 0.f);
        Xs[row][tx * 4 + 2] = fmaxf(p1.x + b1v.z, 0.f);
        Xs[row][tx * 4 + 3] = fmaxf(p1.y + b1v.w, 0.f);
    }
    for (int i = tid; i < 64 * 64; i += 256) Ws[i >> 6][i & 63] = w2[i];
    __syncthreads();

    #pragma unroll
    for (int i = 0; i < 4; ++i) { acc[i][0] = 0ull; acc[i][1] = 0ull; }
    #pragma unroll 8
    for (int kk = 0; kk < 64; ++kk) {
        ulonglong2 w2v = *(const ulonglong2*)&Ws[kk][tx * 4];
        #pragma unroll
        for (int i = 0; i < 4; ++i) {
            float a = Xs[ty * 4 + i][kk];
            u64 ap = pack2(a, a);
            acc[i][0] = fma2(ap, w2v.x, acc[i][0]);
            acc[i][1] = fma2(ap, w2v.y, acc[i][1]);
        }
    }

    float4 b2v = *(const float4*)&b2[tx * 4];
    float partial = 0.f;
    #pragma unroll
    for (int i = 0; i < 4; ++i) {
        float2 p0 = unpack2(acc[i][0]);
        float2 p1 = unpack2(acc[i][1]);
        partial += fmaxf(p0.x + b2v.x, 0.f) * w3s[tx * 4 + 0];
        partial += fmaxf(p0.y + b2v.y, 0.f) * w3s[tx * 4 + 1];
        partial += fmaxf(p1.x + b2v.z, 0.f) * w3s[tx * 4 + 2];
        partial += fmaxf(p1.y + b2v.w, 0.f) * w3s[tx * 4 + 3];
    }
    red[tid] = partial;
    __syncthreads();
    for (int st = 128; st > 0; st >>= 1) {
        if (tid < st) red[tid] += red[tid + st];
        __syncthreads();
    }
    if (tid == 0) part[blockIdx.x] = red[0] + 64.f * b3[0];
}

// ------------------------- deterministic final reduction ----------------------
__global__ void reduce_y(const float* __restrict__ part,
                         const float* __restrict__ ob, float* __restrict__ y) {
    int b = threadIdx.x;   // 16
    float s = ob[0];
    #pragma unroll
    for (int i = 0; i < 16; ++i) s += part[b * 16 + i];
    y[b] = s;
}

// ------------------------- launcher ------------------------------------------
extern "C" void kernel_launch(void* const* d_in, const int* in_sizes, int n_in,
                              void* d_out, int out_size) {
    const float* input  = (const float*)d_in[0];
    const float* emb    = (const float*)d_in[1];
    const float* wq     = (const float*)d_in[2];
    const float* wq_b   = (const float*)d_in[3];
    const float* wk     = (const float*)d_in[4];
    const float* wk_b   = (const float*)d_in[5];
    const float* wv     = (const float*)d_in[6];
    const float* wv_b   = (const float*)d_in[7];
    const float* wo     = (const float*)d_in[8];
    const float* ffn_w1 = (const float*)d_in[9];
    const float* ffn_w2 = (const float*)d_in[10];
    const float* ln1_g  = (const float*)d_in[11];
    const float* ln1_b  = (const float*)d_in[12];
    const float* ln2_g  = (const float*)d_in[13];
    const float* ln2_b  = (const float*)d_in[14];
    const float* c_w1   = (const float*)d_in[15];
    const float* c_b1   = (const float*)d_in[16];
    const float* c_w2   = (const float*)d_in[17];
    const float* c_b2   = (const float*)d_in[18];
    const float* c_w3   = (const float*)d_in[19];
    const float* c_b3   = (const float*)d_in[20];
    const float* ob     = (const float*)d_in[21];
    float* y = (float*)d_out;

    float *x, *q, *k, *v, *keep, *nanf, *part;
    u16 *ws, *wqkvo, *xh, *xl, *cxh, *cxl;
    cudaGetSymbolAddress((void**)&x,    g_x);
    cudaGetSymbolAddress((void**)&q,    g_q);
    cudaGetSymbolAddress((void**)&k,    g_k);
    cudaGetSymbolAddress((void**)&v,    g_v);
    cudaGetSymbolAddress((void**)&keep, g_keep);
    cudaGetSymbolAddress((void**)&nanf, g_nanf);
    cudaGetSymbolAddress((void**)&part, g_part);
    cudaGetSymbolAddress((void**)&ws,   g_ws);
    cudaGetSymbolAddress((void**)&wqkvo, g_wqkvo);
    cudaGetSymbolAddress((void**)&xh,   g_xh);
    cudaGetSymbolAddress((void**)&xl,   g_xl);
    cudaGetSymbolAddress((void**)&cxh,  g_cxh);
    cudaGetSymbolAddress((void**)&cxl,  g_cxl);

    const int FFN_SMEM = 4 * 64 * 72 * 2;         // 36864 B
    cudaFuncSetAttribute(wo_ffn_kernel, cudaFuncAttributeMaxDynamicSharedMemorySize, FFN_SMEM);

    prep_kernel<<<B_, S_>>>(input, keep, nanf);
    build_x_kernel<<<(BS * 32) / 256, 256>>>(input, emb, keep, x, xh, xl);
    wprep_all_kernel<<<384, 256>>>(wq, wk, wv, wo, ffn_w1, ffn_w2, wqkvo, ws);

    for (int l = 0; l < L_; ++l) {
        const u16* wqkv_l = wqkvo + (size_t)l * 8 * 4608;       // q,k,v regions
        const u16* wo_l   = wqkvo + ((size_t)l * 8 + 6) * 4608; // o region

        qkv_mma_kernel<<<dim3(BS / 64, 3), 128>>>(
            xh, xl, wqkv_l, wq_b + l * D_, wk_b + l * D_, wv_b + l * D_, q, k, v);
        attn_mma_kernel<<<dim3(S_ / 256, B_ * H_), 256>>>(q, k, v, nanf, cxh, cxl);
        wo_ffn_kernel<<<BS / 64, 128, FFN_SMEM>>>(
            cxh, cxl, x, wo_l, ws + (size_t)l * 4 * 4 * 64 * 72,
            ln1_g + l * D_, ln1_b + l * D_, ln2_g + l * D_, ln2_b + l * D_,
            keep, x, xh, xl);
    }

    cls_kernel<<<BS / 64, 256>>>(x, c_w1, c_b1, c_w2, c_b2, c_w3, c_b3, part);
    reduce_y<<<1, 16>>>(part, ob, y);
}

// round 11
// speedup vs baseline: 4.0156x; 1.0307x over previous
#include <cuda_runtime.h>

#define B_  16
#define S_  1024
#define D_  64
#define H_  4
#define DFF 256
#define L_  2
#define BS  (B_ * S_)

typedef unsigned long long u64;
typedef unsigned int u32;
typedef unsigned short u16;

// ------------------------- device scratch ------------------------------------
__device__ float g_x   [BS * D_];
__device__ u16   g_qb  [BS * D_];   // q bf16, pre-scaled
__device__ u16   g_kb  [BS * D_];   // k bf16
__device__ u16   g_vb  [BS * D_];   // v bf16
__device__ float g_keep[BS];
__device__ float g_nanf[BS];
__device__ float g_bias[BS];        // 0 or -1e30 per key
__device__ float g_part[BS / 64];
__device__ u16   g_ws   [L_ * 4 * 4 * 64 * 72];  // split ffn weights, frag layout
__device__ u16   g_wqkvo[L_ * 8 * 64 * 72];      // split q,k,v,o weights (hi/lo each)
__device__ u16   g_xh  [BS * 72];                // x bf16-hi frag layout
__device__ u16   g_xl  [BS * 72];
__device__ u16   g_cxh [BS * 72];                // ctx split frag layout
__device__ u16   g_cxl [BS * 72];

// ------------------------- helpers --------------------------------------------
__device__ __forceinline__ u64 fma2(u64 a, u64 b, u64 c) {
    u64 d; asm("fma.rn.f32x2 %0, %1, %2, %3;" : "=l"(d) : "l"(a), "l"(b), "l"(c)); return d;
}
__device__ __forceinline__ u64 pack2(float x, float y) {
    u64 d; asm("mov.b64 %0, {%1, %2};" : "=l"(d) : "f"(x), "f"(y)); return d;
}
__device__ __forceinline__ float2 unpack2(u64 a) {
    float lo, hi; asm("mov.b64 {%0, %1}, %2;" : "=f"(lo), "=f"(hi) : "l"(a));
    return make_float2(lo, hi);
}
__device__ __forceinline__ float ex2f(float x) {
    float r; asm("ex2.approx.f32 %0, %1;" : "=f"(r) : "f"(x)); return r;
}
__device__ __forceinline__ u32 bf2(float lo, float hi) {
    u32 r; asm("cvt.rn.bf16x2.f32 %0, %1, %2;" : "=r"(r) : "f"(hi), "f"(lo)); return r;
}
__device__ __forceinline__ u16 bf1(float f) {
    u16 h; asm("cvt.rn.bf16.f32 %0, %1;" : "=h"(h) : "f"(f)); return h;
}
__device__ __forceinline__ float bf16f(u16 h) { return __uint_as_float((u32)h << 16); }
__device__ __forceinline__ float lopart(u32 h) { return __uint_as_float(h << 16); }
__device__ __forceinline__ float hipart(u32 h) { return __uint_as_float(h & 0xffff0000u); }
__device__ __forceinline__ void mma_bf16(
    float& c0, float& c1, float& c2, float& c3,
    u32 a0, u32 a1, u32 a2, u32 a3, u32 b0, u32 b1) {
    asm volatile(
        "mma.sync.aligned.m16n8k16.row.col.f32.bf16.bf16.f32 "
        "{%0,%1,%2,%3},{%4,%5,%6,%7},{%8,%9},{%0,%1,%2,%3};"
        : "+f"(c0), "+f"(c1), "+f"(c2), "+f"(c3)
        : "r"(a0), "r"(a1), "r"(a2), "r"(a3), "r"(b0), "r"(b1));
}
// permuted k-position inside a 16-group
__device__ __forceinline__ int permpos(int j) {   // j in 0..15
    int p = j >> 1, l = j & 1;
    return (p & 3) * 4 + ((p >> 2) << 1) + l;
}
// pos of an even column pair (c,c+1) in the 72-wide frag row
__device__ __forceinline__ int pairpos(int c) {
    int p = (c & 15) >> 1;
    return (c >> 4) * 16 + (p & 3) * 4 + ((p >> 2) << 1);
}
// split a float pair into hi/lo bf16x2
__device__ __forceinline__ void split2(float a, float b, u32& h, u32& l) {
    h = bf2(a, b);
    l = bf2(a - lopart(h), b - hipart(h));
}

// ------------------------- prep: nan flags + keep + bias ----------------------
__global__ void prep_kernel(const float* __restrict__ in,
                            float* __restrict__ keepv, float* __restrict__ nanf,
                            float* __restrict__ gbias) {
    int b = blockIdx.x;
    int s = threadIdx.x;            // 1024 threads
    float v = in[b * S_ + s];
    bool nan = (v != v);
    unsigned bal = __ballot_sync(0xffffffffu, nan);
    __shared__ int warp_all[32];
    __shared__ int allnan_s;
    if ((s & 31) == 0) warp_all[s >> 5] = (bal == 0xffffffffu);
    __syncthreads();
    if (s == 0) {
        int a = 1;
        #pragma unroll
        for (int i = 0; i < 32; ++i) a &= warp_all[i];
        allnan_s = a;
    }
    __syncthreads();
    float kp = (nan || allnan_s) ? 0.f : 1.f;
    keepv[b * S_ + s] = kp;
    nanf [b * S_ + s] = nan ? 1.f : 0.f;
    gbias[b * S_ + s] = nan ? -1e30f : 0.f;
}

// ------------------------- build x (fp32 + split frag emit) -------------------
__global__ void build_x_kernel(const float* __restrict__ in,
                               const float* __restrict__ emb,
                               const float* __restrict__ keepv,
                               float* __restrict__ x,
                               u16* __restrict__ xh, u16* __restrict__ xl) {
    int idx = blockIdx.x * 256 + threadIdx.x;   // BS*32
    int cp  = idx & 31;
    int row = idx >> 5;
    int s   = row & (S_ - 1);
    int c   = cp * 2;
    float kp = keepv[row];
    const float SQF = 7.93725393319377f * 8.0f;  // sqrt(63)*sqrt(64)
    float v0 = emb[s * 63 + c] * SQF * kp;
    float v1;
    if (c + 1 == 63) {
        float t = in[row];
        v1 = ((t != t) ? 0.f : t) * kp;
    } else {
        v1 = emb[s * 63 + c + 1] * SQF * kp;
    }
    x[row * 64 + c] = v0;
    x[row * 64 + c + 1] = v1;
    int pos = pairpos(c);
    u32 h, l; split2(v0, v1, h, l);
    *(u32*)&xh[(size_t)row * 72 + pos] = h;
    *(u32*)&xl[(size_t)row * 72 + pos] = l;
}

// ------------------------- unified weight prep (1 elem/thread) ----------------
__global__ void wprep_all_kernel(
    const float* __restrict__ wq, const float* __restrict__ wk,
    const float* __restrict__ wv, const float* __restrict__ wo,
    const float* __restrict__ w1, const float* __restrict__ w2,
    u16* __restrict__ dstqkvo, u16* __restrict__ ws) {
    if (blockIdx.x < 128) {
        int idx = blockIdx.x * 256 + threadIdx.x;   // [0, L*4*4096)
        int region = idx >> 12;
        int i      = idx & 4095;
        int l = region >> 2, wsel = region & 3;
        const float* src = (wsel == 0 ? wq : wsel == 1 ? wk : wsel == 2 ? wv : wo) + (size_t)l * 4096;
        u16* dst = dstqkvo + ((size_t)l * 8 + wsel * 2) * 4608;
        int k = i >> 6, n = i & 63;
        int pos = (k >> 4) * 16 + permpos(k & 15);
        float val = src[k * 64 + n];
        u16 h = bf1(val);
        dst[n * 72 + pos]        = h;
        dst[4608 + n * 72 + pos] = bf1(val - bf16f(h));
    } else {
        int idx = (blockIdx.x - 128) * 256 + threadIdx.x;   // [0, L*4*2*4096)
        int region = idx >> 13;
        int rem    = idx & 8191;
        int which  = rem >> 12;
        int i      = rem & 4095;
        int l = region >> 2, nt = region & 3;
        u16* dst = ws + (size_t)region * (4 * 64 * 72);
        int k = i >> 6, n = i & 63;
        int pos = (k >> 4) * 16 + permpos(k & 15);
        if (which == 0) {
            float wa = w1[(size_t)l * 64 * 256 + k * 256 + nt * 64 + n];
            u16 h = bf1(wa);
            dst[0 * 64 * 72 + n * 72 + pos] = h;
            dst[1 * 64 * 72 + n * 72 + pos] = bf1(wa - bf16f(h));
        } else {
            float wb = w2[(size_t)l * 256 * 64 + (nt * 64 + k) * 64 + n];
            u16 h2 = bf1(wb);
            dst[2 * 64 * 72 + n * 72 + pos] = h2;
            dst[3 * 64 * 72 + n * 72 + pos] = bf1(wb - bf16f(h2));
        }
    }
}

// ------------------------- tensor-core QKV (hi-only, bf16 out) ----------------
__global__ void __launch_bounds__(128) qkv_mma_kernel(
    const u16* __restrict__ xh,
    const u16* __restrict__ wsplit,   // [3][2][4608] region for this layer
    const float* __restrict__ bq, const float* __restrict__ bk, const float* __restrict__ bv_,
    u16* __restrict__ qb, u16* __restrict__ kb, u16* __restrict__ vb) {
    __shared__ __align__(16) u16 swq[4608];
    int tid = threadIdx.x, w = tid >> 5, lane = tid & 31;
    int gid = lane >> 2, tig = lane & 3;
    int m0 = blockIdx.x * 64;
    int wsel = blockIdx.y;
    int r0 = m0 + w * 16 + gid;

    {   // copy hi weights only (9216 B)
        const float4* src = (const float4*)(wsplit + (size_t)wsel * 2 * 4608);
        float4* dst = (float4*)swq;
        for (int i = tid; i < 576; i += 128) dst[i] = src[i];
    }

    u32 Ah[4][4];
    {
        const u16* ph0 = xh + (size_t)r0 * 72;
        const u16* ph8 = xh + (size_t)(r0 + 8) * 72;
        #pragma unroll
        for (int gk = 0; gk < 4; ++gk) {
            uint2 t0 = *(const uint2*)(ph0 + gk * 16 + tig * 4);
            uint2 t1 = *(const uint2*)(ph8 + gk * 16 + tig * 4);
            Ah[gk][0] = t0.x; Ah[gk][2] = t0.y;
            Ah[gk][1] = t1.x; Ah[gk][3] = t1.y;
        }
    }
    __syncthreads();

    float C2[8][4];
    #pragma unroll
    for (int j = 0; j < 8; ++j)
        #pragma unroll
        for (int i = 0; i < 4; ++i) C2[j][i] = 0.f;

    #pragma unroll
    for (int j = 0; j < 8; ++j) {
        #pragma unroll
        for (int t = 0; t < 4; ++t) {
            uint2 bh = *(const uint2*)(swq + (8 * j + gid) * 72 + t * 16 + tig * 4);
            mma_bf16(C2[j][0], C2[j][1], C2[j][2], C2[j][3],
                     Ah[t][0], Ah[t][1], Ah[t][2], Ah[t][3], bh.x, bh.y);
        }
    }

    const float SC = 0.25f * 1.4426950408889634f;  // applied only to q
    float sc = (wsel == 0) ? SC : 1.f;
    const float* bias = wsel == 0 ? bq : wsel == 1 ? bk : bv_;
    u16* out = wsel == 0 ? qb : wsel == 1 ? kb : vb;
    #pragma unroll
    for (int j = 0; j < 8; ++j) {
        int c = 8 * j + 2 * tig;
        float2 bb = *(const float2*)(bias + c);
        *(u32*)(out + (size_t)r0 * 64 + c)       = bf2((C2[j][0] + bb.x) * sc, (C2[j][1] + bb.y) * sc);
        *(u32*)(out + (size_t)(r0 + 8) * 64 + c) = bf2((C2[j][2] + bb.x) * sc, (C2[j][3] + bb.y) * sc);
    }
}

// ------------------------- tensor-core flash attention (bf16 inputs) ----------
#define KCHUNK 64
__global__ void __launch_bounds__(256) attn_mma_kernel(
    const u16* __restrict__ qb, const u16* __restrict__ kb,
    const u16* __restrict__ vb, const float* __restrict__ gbias,
    const float* __restrict__ nanf,
    u16* __restrict__ cxh, u16* __restrict__ cxl) {
    __shared__ __align__(16) u16 Ks[2][KCHUNK * 18];
    __shared__ __align__(16) u16 Vt[2][16 * 66];
    __shared__ float bias[2][KCHUNK];

    int tid = threadIdx.x;
    int w   = tid >> 5;
    int lane = tid & 31;
    int gid = lane >> 2;
    int tig = lane & 3;
    int bh = blockIdx.y;
    int b = bh >> 2, h = bh & 3;
    int qbase = blockIdx.x * 256;
    size_t bS = (size_t)b * S_;

    int key = tid >> 2, d4 = tid & 3;

    // stage chunk 0 loads first
    u64 kv0 = *(const u64*)(kb + (bS + key) * 64 + h * 16 + d4 * 4);
    u64 vv0 = *(const u64*)(vb + (bS + key) * 64 + h * 16 + d4 * 4);
    float bb0 = (tid < KCHUNK) ? gbias[bS + tid] : 0.f;

    // Q fragments direct from global (pre-scaled bf16)
    u32 qa[2][4];
    #pragma unroll
    for (int s = 0; s < 2; ++s) {
        size_t row = bS + qbase + w * 32 + s * 16 + gid;
        qa[s][0] = *(const u32*)(qb + row * 64 + h * 16 + 2 * tig);
        qa[s][1] = *(const u32*)(qb + (row + 8) * 64 + h * 16 + 2 * tig);
        qa[s][2] = *(const u32*)(qb + row * 64 + h * 16 + 8 + 2 * tig);
        qa[s][3] = *(const u32*)(qb + (row + 8) * 64 + h * 16 + 8 + 2 * tig);
    }

    {
        *(u32*)((char*)Ks[0] + key * 36 + d4 * 8)     = (u32)kv0;
        *(u32*)((char*)Ks[0] + key * 36 + d4 * 8 + 4) = (u32)(kv0 >> 32);
        Vt[0][(d4 * 4 + 0) * 66 + key] = (u16)vv0;
        Vt[0][(d4 * 4 + 1) * 66 + key] = (u16)(vv0 >> 16);
        Vt[0][(d4 * 4 + 2) * 66 + key] = (u16)(vv0 >> 32);
        Vt[0][(d4 * 4 + 3) * 66 + key] = (u16)(vv0 >> 48);
        if (tid < KCHUNK) bias[0][tid] = bb0;
    }
    __syncthreads();

    float z[2][2] = {{0.f, 0.f}, {0.f, 0.f}};
    float cd[2][2][4];
    #pragma unroll
    for (int s = 0; s < 2; ++s)
        #pragma unroll
        for (int dt = 0; dt < 2; ++dt)
            #pragma unroll
            for (int i = 0; i < 4; ++i) cd[s][dt][i] = 0.f;

    for (int ch = 0; ch < S_ / KCHUNK; ++ch) {
        int cur = ch & 1;
        u64 kvn = 0, vvn = 0; float bbn = 0.f;
        if (ch + 1 < S_ / KCHUNK) {
            size_t nb = bS + (ch + 1) * KCHUNK;
            kvn = *(const u64*)(kb + (nb + key) * 64 + h * 16 + d4 * 4);
            vvn = *(const u64*)(vb + (nb + key) * 64 + h * 16 + d4 * 4);
            if (tid < KCHUNK) bbn = gbias[nb + tid];
        }

        const u16* KsC = Ks[cur];
        const u16* VtC = Vt[cur];
        const float* biC = bias[cur];

        #pragma unroll
        for (int kbk = 0; kbk < KCHUNK; kbk += 16) {
            u32 kb0a = *(const u32*)((char*)KsC + (kbk + gid) * 36 + tig * 4);
            u32 kb1a = *(const u32*)((char*)KsC + (kbk + gid) * 36 + tig * 4 + 16);
            u32 kb0b = *(const u32*)((char*)KsC + (kbk + 8 + gid) * 36 + tig * 4);
            u32 kb1b = *(const u32*)((char*)KsC + (kbk + 8 + gid) * 36 + tig * 4 + 16);
            u32 vb00 = *(const u32*)((char*)VtC + (gid * 66 + kbk + 2 * tig) * 2);
            u32 vb01 = *(const u32*)((char*)VtC + (gid * 66 + kbk + 8 + 2 * tig) * 2);
            u32 vb10 = *(const u32*)((char*)VtC + ((gid + 8) * 66 + kbk + 2 * tig) * 2);
            u32 vb11 = *(const u32*)((char*)VtC + ((gid + 8) * 66 + kbk + 8 + 2 * tig) * 2);
            float2 bv0 = *(const float2*)(biC + kbk + 2 * tig);
            float2 bv1 = *(const float2*)(biC + kbk + 8 + 2 * tig);

            #pragma unroll
            for (int s = 0; s < 2; ++s) {
                float c0 = bv0.x, c1 = bv0.y, c2 = bv0.x, c3 = bv0.y;
                mma_bf16(c0, c1, c2, c3, qa[s][0], qa[s][1], qa[s][2], qa[s][3], kb0a, kb1a);
                float d0 = bv1.x, d1 = bv1.y, d2 = bv1.x, d3 = bv1.y;
                mma_bf16(d0, d1, d2, d3, qa[s][0], qa[s][1], qa[s][2], qa[s][3], kb0b, kb1b);

                float p0 = ex2f(c0), p1 = ex2f(c1);
                float p2 = ex2f(c2), p3 = ex2f(c3);
                float p4 = ex2f(d0), p5 = ex2f(d1);
                float p6 = ex2f(d2), p7 = ex2f(d3);
                z[s][0] += (p0 + p1) + (p4 + p5);
                z[s][1] += (p2 + p3) + (p6 + p7);

                u32 pa0 = bf2(p0, p1), pa1 = bf2(p2, p3);
                u32 pa2 = bf2(p4, p5), pa3 = bf2(p6, p7);
                mma_bf16(cd[s][0][0], cd[s][0][1], cd[s][0][2], cd[s][0][3],
                         pa0, pa1, pa2, pa3, vb00, vb01);
                mma_bf16(cd[s][1][0], cd[s][1][1], cd[s][1][2], cd[s][1][3],
                         pa0, pa1, pa2, pa3, vb10, vb11);
            }
        }

        if (ch + 1 < S_ / KCHUNK) {
            int nxt = cur ^ 1;
            *(u32*)((char*)Ks[nxt] + key * 36 + d4 * 8)     = (u32)kvn;
            *(u32*)((char*)Ks[nxt] + key * 36 + d4 * 8 + 4) = (u32)(kvn >> 32);
            Vt[nxt][(d4 * 4 + 0) * 66 + key] = (u16)vvn;
            Vt[nxt][(d4 * 4 + 1) * 66 + key] = (u16)(vvn >> 16);
            Vt[nxt][(d4 * 4 + 2) * 66 + key] = (u16)(vvn >> 32);
            Vt[nxt][(d4 * 4 + 3) * 66 + key] = (u16)(vvn >> 48);
            if (tid < KCHUNK) bias[nxt][tid] = bbn;
            __syncthreads();
        }
    }

    int posA = h * 16 + tig * 4;
    int posB = posA + 2;
    #pragma unroll
    for (int s = 0; s < 2; ++s) {
        float z0 = z[s][0], z1 = z[s][1];
        z0 += __shfl_xor_sync(0xffffffffu, z0, 1);
        z0 += __shfl_xor_sync(0xffffffffu, z0, 2);
        z1 += __shfl_xor_sync(0xffffffffu, z1, 1);
        z1 += __shfl_xor_sync(0xffffffffu, z1, 2);

        size_t g0 = bS + qbase + w * 32 + s * 16 + gid;
        size_t g1 = g0 + 8;
        float rk0 = (nanf[g0] == 0.f) ? 1.f : 0.f;
        float rk1 = (nanf[g1] == 0.f) ? 1.f : 0.f;
        float rz0 = (rk0 != 0.f && z0 > 0.f) ? (1.f / z0) : 0.f;
        float rz1 = (rk1 != 0.f && z1 > 0.f) ? (1.f / z1) : 0.f;

        size_t row0 = g0 * 72;
        size_t row1 = g1 * 72;
        u32 hh, ll;
        split2(cd[s][0][0] * rz0, cd[s][0][1] * rz0, hh, ll);
        *(u32*)&cxh[row0 + posA] = hh; *(u32*)&cxl[row0 + posA] = ll;
        split2(cd[s][1][0] * rz0, cd[s][1][1] * rz0, hh, ll);
        *(u32*)&cxh[row0 + posB] = hh; *(u32*)&cxl[row0 + posB] = ll;
        split2(cd[s][0][2] * rz1, cd[s][0][3] * rz1, hh, ll);
        *(u32*)&cxh[row1 + posA] = hh; *(u32*)&cxl[row1 + posA] = ll;
        split2(cd[s][1][2] * rz1, cd[s][1][3] * rz1, hh, ll);
        *(u32*)&cxh[row1 + posB] = hh; *(u32*)&cxl[row1 + posB] = ll;
    }
}

// ------------------------- fused WO + LN1 + FFN + LN2 kernel -------------------
__global__ void __launch_bounds__(128) wo_ffn_kernel(
    const u16* __restrict__ cxh, const u16* __restrict__ cxl,
    const float* __restrict__ residx, const u16* __restrict__ wo_w,
    const u16* __restrict__ ws,
    const float* __restrict__ g1, const float* __restrict__ be1,
    const float* __restrict__ g2, const float* __restrict__ be2,
    const float* __restrict__ keep, float* __restrict__ xout,
    u16* __restrict__ xh, u16* __restrict__ xl) {
    extern __shared__ u16 sw[];   // 4 * 64 * 72 u16 = 36864 B (ffn stream buffer)
    int tid = threadIdx.x, w = tid >> 5, lane = tid & 31;
    int gid = lane >> 2, tig = lane & 3;
    int m0 = blockIdx.x * 64;
    int r0 = m0 + w * 16 + gid;

    // ---- phase 1: wo GEMM on ctx frags ----
    float C2[8][4];
    #pragma unroll
    for (int j = 0; j < 8; ++j)
        #pragma unroll
        for (int i = 0; i < 4; ++i) C2[j][i] = 0.f;
    {
        u32 Ah[4][4], Al[4][4];
        const u16* ph0 = cxh + (size_t)r0 * 72;
        const u16* ph8 = cxh + (size_t)(r0 + 8) * 72;
        const u16* pl0 = cxl + (size_t)r0 * 72;
        const u16* pl8 = cxl + (size_t)(r0 + 8) * 72;
        #pragma unroll
        for (int gk = 0; gk < 4; ++gk) {
            uint2 t0 = *(const uint2*)(ph0 + gk * 16 + tig * 4);
            uint2 t1 = *(const uint2*)(ph8 + gk * 16 + tig * 4);
            Ah[gk][0] = t0.x; Ah[gk][2] = t0.y;
            Ah[gk][1] = t1.x; Ah[gk][3] = t1.y;
            uint2 s0 = *(const uint2*)(pl0 + gk * 16 + tig * 4);
            uint2 s1 = *(const uint2*)(pl8 + gk * 16 + tig * 4);
            Al[gk][0] = s0.x; Al[gk][2] = s0.y;
            Al[gk][1] = s1.x; Al[gk][3] = s1.y;
        }
        const u16* Wh = wo_w;
        const u16* Wl = wo_w + 4608;
        #pragma unroll
        for (int j = 0; j < 8; ++j) {
            #pragma unroll
            for (int t = 0; t < 4; ++t) {
                uint2 bh = *(const uint2*)(Wh + (8 * j + gid) * 72 + t * 16 + tig * 4);
                uint2 bl = *(const uint2*)(Wl + (8 * j + gid) * 72 + t * 16 + tig * 4);
                mma_bf16(C2[j][0], C2[j][1], C2[j][2], C2[j][3], Ah[t][0], Ah[t][1], Ah[t][2], Ah[t][3], bh.x, bh.y);
                mma_bf16(C2[j][0], C2[j][1], C2[j][2], C2[j][3], Ah[t][0], Ah[t][1], Ah[t][2], Ah[t][3], bl.x, bl.y);
                mma_bf16(C2[j][0], C2[j][1], C2[j][2], C2[j][3], Al[t][0], Al[t][1], Al[t][2], Al[t][3], bh.x, bh.y);
            }
        }
    }

    float kp0 = keep[r0], kp1 = keep[r0 + 8];

    // ---- phase 2: LN1 in registers -> A1 frags (out1 split) ----
    u32 A1h[4][4], A1l[4][4];
    {
        float v0[16], v1[16];
        float s0 = 0.f, q0 = 0.f, s1 = 0.f, q1 = 0.f;
        #pragma unroll
        for (int j = 0; j < 8; ++j) {
            float2 ra = *(const float2*)(residx + (size_t)r0 * 64 + 8 * j + 2 * tig);
            float2 rb = *(const float2*)(residx + (size_t)(r0 + 8) * 64 + 8 * j + 2 * tig);
            float a0v = C2[j][0] + ra.x, a1v = C2[j][1] + ra.y;
            float b0v = C2[j][2] + rb.x, b1v = C2[j][3] + rb.y;
            v0[2 * j] = a0v; v0[2 * j + 1] = a1v;
            v1[2 * j] = b0v; v1[2 * j + 1] = b1v;
            s0 += a0v + a1v; q0 += a0v * a0v + a1v * a1v;
            s1 += b0v + b1v; q1 += b0v * b0v + b1v * b1v;
        }
        s0 += __shfl_xor_sync(0xffffffffu, s0, 1); s0 += __shfl_xor_sync(0xffffffffu, s0, 2);
        q0 += __shfl_xor_sync(0xffffffffu, q0, 1); q0 += __shfl_xor_sync(0xffffffffu, q0, 2);
        s1 += __shfl_xor_sync(0xffffffffu, s1, 1); s1 += __shfl_xor_sync(0xffffffffu, s1, 2);
        q1 += __shfl_xor_sync(0xffffffffu, q1, 1); q1 += __shfl_xor_sync(0xffffffffu, q1, 2);
        float m0v = s0 * (1.f / 64.f), m1v = s1 * (1.f / 64.f);
        float i0 = rsqrtf(q0 * (1.f / 64.f) - m0v * m0v + 1e-6f);
        float i1 = rsqrtf(q1 * (1.f / 64.f) - m1v * m1v + 1e-6f);
        #pragma unroll
        for (int j = 0; j < 8; ++j) {
            int c = 8 * j + 2 * tig;
            float2 gg = *(const float2*)(g1 + c);
            float2 bb = *(const float2*)(be1 + c);
            float oax = ((v0[2 * j] - m0v) * i0 * gg.x + bb.x) * kp0;
            float oay = ((v0[2 * j + 1] - m0v) * i0 * gg.y + bb.y) * kp0;
            float obx = ((v1[2 * j] - m1v) * i1 * gg.x + bb.x) * kp1;
            float oby = ((v1[2 * j + 1] - m1v) * i1 * gg.y + bb.y) * kp1;
            int gk = j >> 1, half = (j & 1) << 1;   // reg index 0 or 2
            split2(oax, oay, A1h[gk][half], A1l[gk][half]);
            split2(obx, oby, A1h[gk][half + 1], A1l[gk][half + 1]);
        }
    }

    // ---- phase 3: FFN gemm1/relu/gemm2 streamed ----
    #pragma unroll
    for (int j = 0; j < 8; ++j)
        #pragma unroll
        for (int i = 0; i < 4; ++i) C2[j][i] = 0.f;

    for (int nt = 0; nt < 4; ++nt) {
        __syncthreads();
        {
            const float4* src = (const float4*)(ws + (size_t)nt * 4 * 64 * 72);
            float4* dst = (float4*)sw;
            #pragma unroll
            for (int i = 0; i < 18; ++i) dst[tid + i * 128] = src[tid + i * 128];
        }
        __syncthreads();
        const u16* W1h = sw;
        const u16* W1l = sw + 64 * 72;
        const u16* W2h = sw + 2 * 64 * 72;
        const u16* W2l = sw + 3 * 64 * 72;

        u32 A2h[4][4], A2l[4][4];
        #pragma unroll
        for (int t = 0; t < 4; ++t) {
            float Ca[4] = {0.f, 0.f, 0.f, 0.f};
            float Cb[4] = {0.f, 0.f, 0.f, 0.f};
            #pragma unroll
            for (int gk = 0; gk < 4; ++gk) {
                uint2 bha = *(const uint2*)(W1h + (16 * t + gid) * 72 + gk * 16 + tig * 4);
                uint2 bla = *(const uint2*)(W1l + (16 * t + gid) * 72 + gk * 16 + tig * 4);
                mma_bf16(Ca[0], Ca[1], Ca[2], Ca[3], A1h[gk][0], A1h[gk][1], A1h[gk][2], A1h[gk][3], bha.x, bha.y);
                mma_bf16(Ca[0], Ca[1], Ca[2], Ca[3], A1h[gk][0], A1h[gk][1], A1h[gk][2], A1h[gk][3], bla.x, bla.y);
                mma_bf16(Ca[0], Ca[1], Ca[2], Ca[3], A1l[gk][0], A1l[gk][1], A1l[gk][2], A1l[gk][3], bha.x, bha.y);
                uint2 bhb = *(const uint2*)(W1h + (16 * t + 8 + gid) * 72 + gk * 16 + tig * 4);
                uint2 blb = *(const uint2*)(W1l + (16 * t + 8 + gid) * 72 + gk * 16 + tig * 4);
                mma_bf16(Cb[0], Cb[1], Cb[2], Cb[3], A1h[gk][0], A1h[gk][1], A1h[gk][2], A1h[gk][3], bhb.x, bhb.y);
                mma_bf16(Cb[0], Cb[1], Cb[2], Cb[3], A1h[gk][0], A1h[gk][1], A1h[gk][2], A1h[gk][3], blb.x, blb.y);
                mma_bf16(Cb[0], Cb[1], Cb[2], Cb[3], A1l[gk][0], A1l[gk][1], A1l[gk][2], A1l[gk][3], bhb.x, bhb.y);
            }
            #pragma unroll
            for (int i = 0; i < 4; ++i) { Ca[i] = fmaxf(Ca[i], 0.f); Cb[i] = fmaxf(Cb[i], 0.f); }
            split2(Ca[0], Ca[1], A2h[t][0], A2l[t][0]);
            split2(Ca[2], Ca[3], A2h[t][1], A2l[t][1]);
            split2(Cb[0], Cb[1], A2h[t][2], A2l[t][2]);
            split2(Cb[2], Cb[3], A2h[t][3], A2l[t][3]);
        }

        #pragma unroll
        for (int j = 0; j < 8; ++j) {
            #pragma unroll
            for (int t = 0; t < 4; ++t) {
                uint2 bh = *(const uint2*)(W2h + (8 * j + gid) * 72 + t * 16 + tig * 4);
                uint2 bl = *(const uint2*)(W2l + (8 * j + gid) * 72 + t * 16 + tig * 4);
                mma_bf16(C2[j][0], C2[j][1], C2[j][2], C2[j][3], A2h[t][0], A2h[t][1], A2h[t][2], A2h[t][3], bh.x, bh.y);
                mma_bf16(C2[j][0], C2[j][1], C2[j][2], C2[j][3], A2h[t][0], A2h[t][1], A2h[t][2], A2h[t][3], bl.x, bl.y);
                mma_bf16(C2[j][0], C2[j][1], C2[j][2], C2[j][3], A2l[t][0], A2l[t][1], A2l[t][2], A2l[t][3], bh.x, bh.y);
            }
        }
    }

    // ---- phase 4: LN2 epilogue (resid = out1 reconstructed from A1 frags) ----
    float v0[16], v1[16];
    float s0 = 0.f, q0 = 0.f, s1 = 0.f, q1 = 0.f;
    #pragma unroll
    for (int j = 0; j < 8; ++j) {
        int gk = j >> 1, half = (j & 1) << 1;
        float rax = lopart(A1h[gk][half])     + lopart(A1l[gk][half]);
        float ray = hipart(A1h[gk][half])     + hipart(A1l[gk][half]);
        float rbx = lopart(A1h[gk][half + 1]) + lopart(A1l[gk][half + 1]);
        float rby = hipart(A1h[gk][half + 1]) + hipart(A1l[gk][half + 1]);
        float a0v = C2[j][0] + rax, a1v = C2[j][1] + ray;
        float b0v = C2[j][2] + rbx, b1v = C2[j][3] + rby;
        v0[2 * j] = a0v; v0[2 * j + 1] = a1v;
        v1[2 * j] = b0v; v1[2 * j + 1] = b1v;
        s0 += a0v + a1v; q0 += a0v * a0v + a1v * a1v;
        s1 += b0v + b1v; q1 += b0v * b0v + b1v * b1v;
    }
    s0 += __shfl_xor_sync(0xffffffffu, s0, 1); s0 += __shfl_xor_sync(0xffffffffu, s0, 2);
    q0 += __shfl_xor_sync(0xffffffffu, q0, 1); q0 += __shfl_xor_sync(0xffffffffu, q0, 2);
    s1 += __shfl_xor_sync(0xffffffffu, s1, 1); s1 += __shfl_xor_sync(0xffffffffu, s1, 2);
    q1 += __shfl_xor_sync(0xffffffffu, q1, 1); q1 += __shfl_xor_sync(0xffffffffu, q1, 2);
    float m0v = s0 * (1.f / 64.f), m1v = s1 * (1.f / 64.f);
    float i0 = rsqrtf(q0 * (1.f / 64.f) - m0v * m0v + 1e-6f);
    float i1 = rsqrtf(q1 * (1.f / 64.f) - m1v * m1v + 1e-6f);
    #pragma unroll
    for (int j = 0; j < 8; ++j) {
        int c = 8 * j + 2 * tig;
        float2 gg = *(const float2*)(g2 + c);
        float2 bb = *(const float2*)(be2 + c);
        float2 oa = make_float2(((v0[2 * j] - m0v) * i0 * gg.x + bb.x) * kp0,
                                ((v0[2 * j + 1] - m0v) * i0 * gg.y + bb.y) * kp0);
        float2 ob = make_float2(((v1[2 * j] - m1v) * i1 * gg.x + bb.x) * kp1,
                                ((v1[2 * j + 1] - m1v) * i1 * gg.y + bb.y) * kp1);
        *(float2*)(xout + (size_t)r0 * 64 + c) = oa;
        *(float2*)(xout + (size_t)(r0 + 8) * 64 + c) = ob;
        int pos = pairpos(c);
        u32 hh, ll;
        split2(oa.x, oa.y, hh, ll);
        *(u32*)&xh[(size_t)r0 * 72 + pos] = hh; *(u32*)&xl[(size_t)r0 * 72 + pos] = ll;
        split2(ob.x, ob.y, hh, ll);
        *(u32*)&xh[(size_t)(r0 + 8) * 72 + pos] = hh; *(u32*)&xl[(size_t)(r0 + 8) * 72 + pos] = ll;
    }
}

// ------------------------- classifier fused -----------------------------------
__global__ void __launch_bounds__(256) cls_kernel(
    const float* __restrict__ x,
    const float* __restrict__ w1, const float* __restrict__ b1,
    const float* __restrict__ w2, const float* __restrict__ b2,
    const float* __restrict__ w3, const float* __restrict__ b3,
    float* __restrict__ part) {
    __shared__ float Xs[64][65];
    __shared__ __align__(16) float Ws[64][64];
    __shared__ float w3s[64];
    __shared__ float red[256];
    int tid = threadIdx.x;
    int tx = tid & 15, ty = tid >> 4;
    int m0 = blockIdx.x * 64;

    for (int i = tid; i < 64 * 64; i += 256) {
        int r = i >> 6, c = i & 63;
        Xs[r][c] = x[(size_t)(m0 + r) * 64 + c];
        Ws[r][c] = w1[i];
    }
    if (tid < 64) w3s[tid] = w3[tid];
    __syncthreads();

    u64 acc[4][2];
    #pragma unroll
    for (int i = 0; i < 4; ++i) { acc[i][0] = 0ull; acc[i][1] = 0ull; }
    #pragma unroll 8
    for (int kk = 0; kk < 64; ++kk) {
        ulonglong2 w2v = *(const ulonglong2*)&Ws[kk][tx * 4];
        #pragma unroll
        for (int i = 0; i < 4; ++i) {
            float a = Xs[ty * 4 + i][kk];
            u64 ap = pack2(a, a);
            acc[i][0] = fma2(ap, w2v.x, acc[i][0]);
            acc[i][1] = fma2(ap, w2v.y, acc[i][1]);
        }
    }
    __syncthreads();

    float4 b1v = *(const float4*)&b1[tx * 4];
    #pragma unroll
    for (int i = 0; i < 4; ++i) {
        int row = ty * 4 + i;
        float2 p0 = unpack2(acc[i][0]);
        float2 p1 = unpack2(acc[i][1]);
        Xs[row][tx * 4 + 0] = fmaxf(p0.x + b1v.x, 0.f);
        Xs[row][tx * 4 + 1] = fmaxf(p0.y + b1v.y, 0.f);
        Xs[row][tx * 4 + 2] = fmaxf(p1.x + b1v.z, 0.f);
        Xs[row][tx * 4 + 3] = fmaxf(p1.y + b1v.w, 0.f);
    }
    for (int i = tid; i < 64 * 64; i += 256) Ws[i >> 6][i & 63] = w2[i];
    __syncthreads();

    #pragma unroll
    for (int i = 0; i < 4; ++i) { acc[i][0] = 0ull; acc[i][1] = 0ull; }
    #pragma unroll 8
    for (int kk = 0; kk < 64; ++kk) {
        ulonglong2 w2v = *(const ulonglong2*)&Ws[kk][tx * 4];
        #pragma unroll
        for (int i = 0; i < 4; ++i) {
            float a = Xs[ty * 4 + i][kk];
            u64 ap = pack2(a, a);
            acc[i][0] = fma2(ap, w2v.x, acc[i][0]);
            acc[i][1] = fma2(ap, w2v.y, acc[i][1]);
        }
    }

    float4 b2v = *(const float4*)&b2[tx * 4];
    float partial = 0.f;
    #pragma unroll
    for (int i = 0; i < 4; ++i) {
        float2 p0 = unpack2(acc[i][0]);
        float2 p1 = unpack2(acc[i][1]);
        partial += fmaxf(p0.x + b2v.x, 0.f) * w3s[tx * 4 + 0];
        partial += fmaxf(p0.y + b2v.y, 0.f) * w3s[tx * 4 + 1];
        partial += fmaxf(p1.x + b2v.z, 0.f) * w3s[tx * 4 + 2];
        partial += fmaxf(p1.y + b2v.w, 0.f) * w3s[tx * 4 + 3];
    }
    red[tid] = partial;
    __syncthreads();
    for (int st = 128; st > 0; st >>= 1) {
        if (tid < st) red[tid] += red[tid + st];
        __syncthreads();
    }
    if (tid == 0) part[blockIdx.x] = red[0] + 64.f * b3[0];
}

// ------------------------- deterministic final reduction ----------------------
__global__ void reduce_y(const float* __restrict__ part,
                         const float* __restrict__ ob, float* __restrict__ y) {
    int b = threadIdx.x;   // 16
    float s = ob[0];
    #pragma unroll
    for (int i = 0; i < 16; ++i) s += part[b * 16 + i];
    y[b] = s;
}

// ------------------------- launcher ------------------------------------------
extern "C" void kernel_launch(void* const* d_in, const int* in_sizes, int n_in,
                              void* d_out, int out_size) {
    const float* input  = (const float*)d_in[0];
    const float* emb    = (const float*)d_in[1];
    const float* wq     = (const float*)d_in[2];
    const float* wq_b   = (const float*)d_in[3];
    const float* wk     = (const float*)d_in[4];
    const float* wk_b   = (const float*)d_in[5];
    const float* wv     = (const float*)d_in[6];
    const float* wv_b   = (const float*)d_in[7];
    const float* wo     = (const float*)d_in[8];
    const float* ffn_w1 = (const float*)d_in[9];
    const float* ffn_w2 = (const float*)d_in[10];
    const float* ln1_g  = (const float*)d_in[11];
    const float* ln1_b  = (const float*)d_in[12];
    const float* ln2_g  = (const float*)d_in[13];
    const float* ln2_b  = (const float*)d_in[14];
    const float* c_w1   = (const float*)d_in[15];
    const float* c_b1   = (const float*)d_in[16];
    const float* c_w2   = (const float*)d_in[17];
    const float* c_b2   = (const float*)d_in[18];
    const float* c_w3   = (const float*)d_in[19];
    const float* c_b3   = (const float*)d_in[20];
    const float* ob     = (const float*)d_in[21];
    float* y = (float*)d_out;

    float *x, *keep, *nanf, *gbias, *part;
    u16 *ws, *wqkvo, *xh, *xl, *cxh, *cxl, *qb, *kbp, *vbp;
    cudaGetSymbolAddress((void**)&x,    g_x);
    cudaGetSymbolAddress((void**)&keep, g_keep);
    cudaGetSymbolAddress((void**)&nanf, g_nanf);
    cudaGetSymbolAddress((void**)&gbias, g_bias);
    cudaGetSymbolAddress((void**)&part, g_part);
    cudaGetSymbolAddress((void**)&ws,   g_ws);
    cudaGetSymbolAddress((void**)&wqkvo, g_wqkvo);
    cudaGetSymbolAddress((void**)&xh,   g_xh);
    cudaGetSymbolAddress((void**)&xl,   g_xl);
    cudaGetSymbolAddress((void**)&cxh,  g_cxh);
    cudaGetSymbolAddress((void**)&cxl,  g_cxl);
    cudaGetSymbolAddress((void**)&qb,   g_qb);
    cudaGetSymbolAddress((void**)&kbp,  g_kb);
    cudaGetSymbolAddress((void**)&vbp,  g_vb);

    const int FFN_SMEM = 4 * 64 * 72 * 2;         // 36864 B
    cudaFuncSetAttribute(wo_ffn_kernel, cudaFuncAttributeMaxDynamicSharedMemorySize, FFN_SMEM);

    prep_kernel<<<B_, S_>>>(input, keep, nanf, gbias);
    build_x_kernel<<<(BS * 32) / 256, 256>>>(input, emb, keep, x, xh, xl);
    wprep_all_kernel<<<384, 256>>>(wq, wk, wv, wo, ffn_w1, ffn_w2, wqkvo, ws);

    for (int l = 0; l < L_; ++l) {
        const u16* wqkv_l = wqkvo + (size_t)l * 8 * 4608;       // q,k,v regions
        const u16* wo_l   = wqkvo + ((size_t)l * 8 + 6) * 4608; // o region

        qkv_mma_kernel<<<dim3(BS / 64, 3), 128>>>(
            xh, wqkv_l, wq_b + l * D_, wk_b + l * D_, wv_b + l * D_, qb, kbp, vbp);
        attn_mma_kernel<<<dim3(S_ / 256, B_ * H_), 256>>>(qb, kbp, vbp, gbias, nanf, cxh, cxl);
        wo_ffn_kernel<<<BS / 64, 128, FFN_SMEM>>>(
            cxh, cxl, x, wo_l, ws + (size_t)l * 4 * 4 * 64 * 72,
            ln1_g + l * D_, ln1_b + l * D_, ln2_g + l * D_, ln2_b + l * D_,
            keep, x, xh, xl);
    }

    cls_kernel<<<BS / 64, 256>>>(x, c_w1, c_b1, c_w2, c_b2, c_w3, c_b3, part);
    reduce_y<<<1, 16>>>(part, ob, y);
}